// round 1
// baseline (speedup 1.0000x reference)
#include <cuda_runtime.h>
#include <cstdint>

// ---------------------------------------------------------------------------
// Problem constants: x [B=2, S=2048, d=1024], H=16, Dh=64, causal MHA, fp32.
// ---------------------------------------------------------------------------
#define D_MODEL 1024
#define NUM_HEADS 16
#define D_HEAD 64
#define SEQ_LEN 2048
#define BATCH 2
#define M_ROWS (BATCH * SEQ_LEN)   // 4096

// Scratch (alloc-free rule: __device__ globals). 4 x 16 MB.
__device__ float g_Q[M_ROWS * D_MODEL];
__device__ float g_K[M_ROWS * D_MODEL];
__device__ float g_V[M_ROWS * D_MODEL];
__device__ float g_O[M_ROWS * D_MODEL];

// ---------------------------------------------------------------------------
// SGEMM: C[M,N] = A[M,K] @ B[K,N] + bias[N]
// BM=128, BN=128, BK=16, 256 threads, 8x8 per thread.
// ---------------------------------------------------------------------------
__global__ __launch_bounds__(256) void sgemm_bias_kernel(
    const float* __restrict__ A, const float* __restrict__ B,
    const float* __restrict__ bias, float* __restrict__ C,
    int M, int N, int K)
{
    __shared__ float As[16][128];
    __shared__ float Bs[16][128];

    const int tid = threadIdx.x;
    const int block_row = blockIdx.y * 128;
    const int block_col = blockIdx.x * 128;
    const int trow = (tid / 16) * 8;   // 0..120
    const int tcol = (tid % 16) * 8;   // 0..120

    float acc[8][8];
    #pragma unroll
    for (int i = 0; i < 8; i++)
        #pragma unroll
        for (int j = 0; j < 8; j++) acc[i][j] = 0.0f;

    for (int k0 = 0; k0 < K; k0 += 16) {
        // Load A tile (128x16) -> As transposed [k][m]
        #pragma unroll
        for (int l = 0; l < 2; l++) {
            int fid = tid + l * 256;           // 0..511
            int r   = fid >> 2;                // 0..127
            int kq  = (fid & 3) * 4;           // 0,4,8,12
            float4 v = *reinterpret_cast<const float4*>(
                A + (size_t)(block_row + r) * K + k0 + kq);
            As[kq + 0][r] = v.x;
            As[kq + 1][r] = v.y;
            As[kq + 2][r] = v.z;
            As[kq + 3][r] = v.w;
        }
        // Load B tile (16x128) -> Bs [k][n]
        #pragma unroll
        for (int l = 0; l < 2; l++) {
            int fid = tid + l * 256;           // 0..511
            int kr  = fid >> 5;                // 0..15
            int nq  = (fid & 31) * 4;          // float offset 0..124
            *reinterpret_cast<float4*>(&Bs[kr][nq]) =
                *reinterpret_cast<const float4*>(
                    B + (size_t)(k0 + kr) * N + block_col + nq);
        }
        __syncthreads();

        #pragma unroll
        for (int kk = 0; kk < 16; kk++) {
            float ra[8], rb[8];
            *reinterpret_cast<float4*>(&ra[0]) = *reinterpret_cast<const float4*>(&As[kk][trow]);
            *reinterpret_cast<float4*>(&ra[4]) = *reinterpret_cast<const float4*>(&As[kk][trow + 4]);
            *reinterpret_cast<float4*>(&rb[0]) = *reinterpret_cast<const float4*>(&Bs[kk][tcol]);
            *reinterpret_cast<float4*>(&rb[4]) = *reinterpret_cast<const float4*>(&Bs[kk][tcol + 4]);
            #pragma unroll
            for (int i = 0; i < 8; i++)
                #pragma unroll
                for (int j = 0; j < 8; j++)
                    acc[i][j] += ra[i] * rb[j];
        }
        __syncthreads();
    }

    // Epilogue: add bias, store.
    #pragma unroll
    for (int i = 0; i < 8; i++) {
        size_t row = (size_t)(block_row + trow + i);
        #pragma unroll
        for (int j = 0; j < 8; j += 4) {
            float4 bv = *reinterpret_cast<const float4*>(bias + block_col + tcol + j);
            float4 o;
            o.x = acc[i][j + 0] + bv.x;
            o.y = acc[i][j + 1] + bv.y;
            o.z = acc[i][j + 2] + bv.z;
            o.w = acc[i][j + 3] + bv.w;
            *reinterpret_cast<float4*>(C + row * N + block_col + tcol + j) = o;
        }
    }
}

// ---------------------------------------------------------------------------
// Flash-attention (fp32, causal). One CTA = 128 query rows of one (b,h).
// K/V tiles 64x64 in SMEM; Q row + O accumulator in registers.
// All SMEM reads in the mainloop are warp-broadcast (same key row per lane).
// ---------------------------------------------------------------------------
#define BR 128
#define BC 64

__global__ __launch_bounds__(128) void attn_kernel(
    const float* __restrict__ Q, const float* __restrict__ K,
    const float* __restrict__ V, float* __restrict__ O)
{
    __shared__ float Ks[BC][D_HEAD];
    __shared__ float Vs[BC][D_HEAD];

    // Heavy tiles first (largest qt -> most key tiles) to reduce tail.
    const int qt = (int)gridDim.x - 1 - (int)blockIdx.x;
    const int bh = blockIdx.y;
    const int b  = bh >> 4;
    const int h  = bh & 15;
    const int tid = threadIdx.x;
    const int row = qt * BR + tid;                 // global query index in [0,S)

    const size_t qoff = ((size_t)(b * SEQ_LEN + row)) * D_MODEL + h * D_HEAD;

    float4 q[16];
    #pragma unroll
    for (int i = 0; i < 16; i++)
        q[i] = *reinterpret_cast<const float4*>(Q + qoff + i * 4);

    float4 acc[16];
    #pragma unroll
    for (int i = 0; i < 16; i++) acc[i] = make_float4(0.f, 0.f, 0.f, 0.f);

    float m = -3.0e38f;
    float l = 0.0f;
    const float scale = 0.125f;   // 1/sqrt(64)

    const int nkt = 2 * qt + 2;   // key tiles covering [0, qt*128+128)

    for (int kt = 0; kt < nkt; kt++) {
        const int k0 = kt * BC;
        // Load K/V tile: thread -> half of one key row (32 floats each).
        {
            int r = tid >> 1;
            int c = (tid & 1) * 32;
            size_t off = ((size_t)(b * SEQ_LEN + k0 + r)) * D_MODEL + h * D_HEAD + c;
            #pragma unroll
            for (int i = 0; i < 8; i++) {
                *reinterpret_cast<float4*>(&Ks[r][c + i * 4]) =
                    *reinterpret_cast<const float4*>(K + off + i * 4);
                *reinterpret_cast<float4*>(&Vs[r][c + i * 4]) =
                    *reinterpret_cast<const float4*>(V + off + i * 4);
            }
        }
        __syncthreads();

        const bool need_mask = (kt >= nkt - 2);

        // Process the 64-key tile in chunks of 16 (scores live in registers).
        #pragma unroll 1
        for (int jc = 0; jc < BC; jc += 16) {
            float s[16];
            #pragma unroll
            for (int j = 0; j < 16; j++) {
                float4 d0 = make_float4(0.f, 0.f, 0.f, 0.f);
                #pragma unroll
                for (int i = 0; i < 16; i++) {
                    float4 kv = *reinterpret_cast<const float4*>(&Ks[jc + j][i * 4]);
                    d0.x += q[i].x * kv.x;
                    d0.y += q[i].y * kv.y;
                    d0.z += q[i].z * kv.z;
                    d0.w += q[i].w * kv.w;
                }
                float sv = ((d0.x + d0.y) + (d0.z + d0.w)) * scale;
                if (need_mask && (k0 + jc + j > row)) sv = -3.0e38f;
                s[j] = sv;
            }

            float cmax = s[0];
            #pragma unroll
            for (int j = 1; j < 16; j++) cmax = fmaxf(cmax, s[j]);
            float mnew = fmaxf(m, cmax);
            float corr = __expf(m - mnew);
            m = mnew;
            l *= corr;
            #pragma unroll
            for (int i = 0; i < 16; i++) {
                acc[i].x *= corr; acc[i].y *= corr;
                acc[i].z *= corr; acc[i].w *= corr;
            }

            #pragma unroll
            for (int j = 0; j < 16; j++) {
                float p = __expf(s[j] - mnew);
                if (need_mask && (k0 + jc + j > row)) p = 0.0f;  // fully-masked-chunk safety
                l += p;
                #pragma unroll
                for (int i = 0; i < 16; i++) {
                    float4 vv = *reinterpret_cast<const float4*>(&Vs[jc + j][i * 4]);
                    acc[i].x += p * vv.x;
                    acc[i].y += p * vv.y;
                    acc[i].z += p * vv.z;
                    acc[i].w += p * vv.w;
                }
            }
        }
        __syncthreads();
    }

    const float inv = 1.0f / l;
    #pragma unroll
    for (int i = 0; i < 16; i++) {
        float4 o;
        o.x = acc[i].x * inv; o.y = acc[i].y * inv;
        o.z = acc[i].z * inv; o.w = acc[i].w * inv;
        *reinterpret_cast<float4*>(O + qoff + i * 4) = o;
    }
}

// ---------------------------------------------------------------------------
// Launch: QKV projections -> attention -> output projection.
// ---------------------------------------------------------------------------
extern "C" void kernel_launch(void* const* d_in, const int* in_sizes, int n_in,
                              void* d_out, int out_size)
{
    const float* x  = (const float*)d_in[0];
    const float* Wq = (const float*)d_in[1];
    const float* bq = (const float*)d_in[2];
    const float* Wk = (const float*)d_in[3];
    const float* bk = (const float*)d_in[4];
    const float* Wv = (const float*)d_in[5];
    const float* bv = (const float*)d_in[6];
    const float* Wo = (const float*)d_in[7];
    const float* bo = (const float*)d_in[8];
    float* out = (float*)d_out;

    const int M = in_sizes[0] / D_MODEL;   // 4096
    const int B = M / SEQ_LEN;             // 2

    float *Qp, *Kp, *Vp, *Op;
    cudaGetSymbolAddress((void**)&Qp, g_Q);
    cudaGetSymbolAddress((void**)&Kp, g_K);
    cudaGetSymbolAddress((void**)&Vp, g_V);
    cudaGetSymbolAddress((void**)&Op, g_O);

    dim3 gemm_grid(D_MODEL / 128, M / 128);   // (8, 32)
    sgemm_bias_kernel<<<gemm_grid, 256>>>(x, Wq, bq, Qp, M, D_MODEL, D_MODEL);
    sgemm_bias_kernel<<<gemm_grid, 256>>>(x, Wk, bk, Kp, M, D_MODEL, D_MODEL);
    sgemm_bias_kernel<<<gemm_grid, 256>>>(x, Wv, bv, Vp, M, D_MODEL, D_MODEL);

    dim3 attn_grid(SEQ_LEN / BR, B * NUM_HEADS);  // (16, 32)
    attn_kernel<<<attn_grid, 128>>>(Qp, Kp, Vp, Op);

    sgemm_bias_kernel<<<gemm_grid, 256>>>(Op, Wo, bo, out, M, D_MODEL, D_MODEL);
}

// round 2
// speedup vs baseline: 1.2801x; 1.2801x over previous
#include <cuda_runtime.h>
#include <cstdint>

// ---------------------------------------------------------------------------
// Problem constants: x [B=2, S=2048, d=1024], H=16, Dh=64, causal MHA, fp32.
// ---------------------------------------------------------------------------
#define D_MODEL 1024
#define NUM_HEADS 16
#define D_HEAD 64
#define SEQ_LEN 2048
#define BATCH 2
#define M_ROWS (BATCH * SEQ_LEN)   // 4096

// Scratch (alloc-free rule: __device__ globals). 4 x 16 MB.
__device__ float g_Q[M_ROWS * D_MODEL];
__device__ float g_K[M_ROWS * D_MODEL];
__device__ float g_V[M_ROWS * D_MODEL];
__device__ float g_O[M_ROWS * D_MODEL];

__device__ __forceinline__ uint32_t f2tf32(float x) {
    uint32_t r;
    asm("cvt.rna.tf32.f32 %0, %1;" : "=r"(r) : "f"(x));
    return r;
}

// ---------------------------------------------------------------------------
// TF32 tensor-core GEMM: C[M,N] = round_tf32(A[M,K]) @ round_tf32(B[K,N]) + bias
// CTA 128x128, BK=32, 8 warps; warp tile 32x64 via mma.sync.m16n8k8.tf32.
// SMEM rows padded +4 floats -> all fragment LDS are bank-conflict-free.
// ---------------------------------------------------------------------------
#define GBK 32
#define APAD 4
#define LDA (128 + APAD)   // As row length (m-dim)  -- As[k][m]
#define LDB (128 + APAD)   // Bs row length (n-dim)  -- Bs[k][n]

__global__ __launch_bounds__(256) void gemm_tf32_bias_kernel(
    const float* __restrict__ A, const float* __restrict__ B,
    const float* __restrict__ bias, float* __restrict__ C,
    int M, int N, int K)
{
    __shared__ uint32_t As[GBK][LDA];
    __shared__ uint32_t Bs[GBK][LDB];

    const int tid  = threadIdx.x;
    const int lane = tid & 31;
    const int warp = tid >> 5;
    const int wm = (warp & 3) * 32;   // warp row offset in tile
    const int wn = (warp >> 2) * 64;  // warp col offset in tile
    const int lrow = lane >> 2;       // 0..7
    const int lcol = lane & 3;        // 0..3

    const int block_row = blockIdx.y * 128;
    const int block_col = blockIdx.x * 128;

    float c[2][8][4];
    #pragma unroll
    for (int mi = 0; mi < 2; mi++)
        #pragma unroll
        for (int ni = 0; ni < 8; ni++)
            #pragma unroll
            for (int r = 0; r < 4; r++) c[mi][ni][r] = 0.0f;

    for (int k0 = 0; k0 < K; k0 += GBK) {
        // Load A tile (128 x 32) -> As[k][m] (transposed), tf32-rounded.
        // 4096 floats / 256 threads = 4 float4 loads per thread.
        #pragma unroll
        for (int l = 0; l < 4; l++) {
            int fid = tid + l * 256;          // 0..1023
            int r   = fid >> 3;               // 0..127
            int kq  = (fid & 7) * 4;          // 0..28
            float4 v = *reinterpret_cast<const float4*>(
                A + (size_t)(block_row + r) * K + k0 + kq);
            As[kq + 0][r] = f2tf32(v.x);
            As[kq + 1][r] = f2tf32(v.y);
            As[kq + 2][r] = f2tf32(v.z);
            As[kq + 3][r] = f2tf32(v.w);
        }
        // Load B tile (32 x 128) -> Bs[k][n], tf32-rounded.
        #pragma unroll
        for (int l = 0; l < 4; l++) {
            int fid = tid + l * 256;
            int kr  = fid >> 5;               // 0..31
            int nq  = (fid & 31) * 4;         // 0..124
            float4 v = *reinterpret_cast<const float4*>(
                B + (size_t)(k0 + kr) * N + block_col + nq);
            Bs[kr][nq + 0] = f2tf32(v.x);
            Bs[kr][nq + 1] = f2tf32(v.y);
            Bs[kr][nq + 2] = f2tf32(v.z);
            Bs[kr][nq + 3] = f2tf32(v.w);
        }
        __syncthreads();

        #pragma unroll
        for (int kk = 0; kk < GBK; kk += 8) {
            uint32_t a[2][4];
            #pragma unroll
            for (int mi = 0; mi < 2; mi++) {
                int m0 = wm + mi * 16;
                a[mi][0] = As[kk + lcol    ][m0 + lrow    ];
                a[mi][1] = As[kk + lcol    ][m0 + 8 + lrow];
                a[mi][2] = As[kk + lcol + 4][m0 + lrow    ];
                a[mi][3] = As[kk + lcol + 4][m0 + 8 + lrow];
            }
            uint32_t b[8][2];
            #pragma unroll
            for (int ni = 0; ni < 8; ni++) {
                int n0 = wn + ni * 8;
                b[ni][0] = Bs[kk + lcol    ][n0 + lrow];
                b[ni][1] = Bs[kk + lcol + 4][n0 + lrow];
            }
            #pragma unroll
            for (int mi = 0; mi < 2; mi++)
                #pragma unroll
                for (int ni = 0; ni < 8; ni++) {
                    asm volatile(
                        "mma.sync.aligned.m16n8k8.row.col.f32.tf32.tf32.f32 "
                        "{%0,%1,%2,%3}, {%4,%5,%6,%7}, {%8,%9}, {%0,%1,%2,%3};\n"
                        : "+f"(c[mi][ni][0]), "+f"(c[mi][ni][1]),
                          "+f"(c[mi][ni][2]), "+f"(c[mi][ni][3])
                        : "r"(a[mi][0]), "r"(a[mi][1]), "r"(a[mi][2]), "r"(a[mi][3]),
                          "r"(b[ni][0]), "r"(b[ni][1]));
                }
        }
        __syncthreads();
    }

    // Epilogue: c0,c1 -> (row, col), (row, col+1); c2,c3 -> (row+8, ...)
    #pragma unroll
    for (int mi = 0; mi < 2; mi++) {
        int r0 = block_row + wm + mi * 16 + lrow;
        #pragma unroll
        for (int ni = 0; ni < 8; ni++) {
            int col = block_col + wn + ni * 8 + lcol * 2;
            float b0 = bias[col];
            float b1 = bias[col + 1];
            float2 v0 = make_float2(c[mi][ni][0] + b0, c[mi][ni][1] + b1);
            float2 v1 = make_float2(c[mi][ni][2] + b0, c[mi][ni][3] + b1);
            *reinterpret_cast<float2*>(C + (size_t)r0 * N + col) = v0;
            *reinterpret_cast<float2*>(C + (size_t)(r0 + 8) * N + col) = v1;
        }
    }
}

// ---------------------------------------------------------------------------
// Flash-attention (fp32, causal). One CTA = 128 query rows of one (b,h).
// ---------------------------------------------------------------------------
#define BR 128
#define BC 64

__global__ __launch_bounds__(128) void attn_kernel(
    const float* __restrict__ Q, const float* __restrict__ K,
    const float* __restrict__ V, float* __restrict__ O)
{
    __shared__ float Ks[BC][D_HEAD];
    __shared__ float Vs[BC][D_HEAD];

    const int qt = (int)gridDim.x - 1 - (int)blockIdx.x;  // heavy tiles first
    const int bh = blockIdx.y;
    const int b  = bh >> 4;
    const int h  = bh & 15;
    const int tid = threadIdx.x;
    const int row = qt * BR + tid;

    const size_t qoff = ((size_t)(b * SEQ_LEN + row)) * D_MODEL + h * D_HEAD;

    float4 q[16];
    #pragma unroll
    for (int i = 0; i < 16; i++)
        q[i] = *reinterpret_cast<const float4*>(Q + qoff + i * 4);

    float4 acc[16];
    #pragma unroll
    for (int i = 0; i < 16; i++) acc[i] = make_float4(0.f, 0.f, 0.f, 0.f);

    float m = -3.0e38f;
    float l = 0.0f;
    const float scale = 0.125f;

    const int nkt = 2 * qt + 2;

    for (int kt = 0; kt < nkt; kt++) {
        const int k0 = kt * BC;
        {
            int r = tid >> 1;
            int cc = (tid & 1) * 32;
            size_t off = ((size_t)(b * SEQ_LEN + k0 + r)) * D_MODEL + h * D_HEAD + cc;
            #pragma unroll
            for (int i = 0; i < 8; i++) {
                *reinterpret_cast<float4*>(&Ks[r][cc + i * 4]) =
                    *reinterpret_cast<const float4*>(K + off + i * 4);
                *reinterpret_cast<float4*>(&Vs[r][cc + i * 4]) =
                    *reinterpret_cast<const float4*>(V + off + i * 4);
            }
        }
        __syncthreads();

        const bool need_mask = (kt >= nkt - 2);

        #pragma unroll 1
        for (int jc = 0; jc < BC; jc += 16) {
            float s[16];
            #pragma unroll
            for (int j = 0; j < 16; j++) {
                float4 d0 = make_float4(0.f, 0.f, 0.f, 0.f);
                #pragma unroll
                for (int i = 0; i < 16; i++) {
                    float4 kv = *reinterpret_cast<const float4*>(&Ks[jc + j][i * 4]);
                    d0.x += q[i].x * kv.x;
                    d0.y += q[i].y * kv.y;
                    d0.z += q[i].z * kv.z;
                    d0.w += q[i].w * kv.w;
                }
                float sv = ((d0.x + d0.y) + (d0.z + d0.w)) * scale;
                if (need_mask && (k0 + jc + j > row)) sv = -3.0e38f;
                s[j] = sv;
            }

            float cmax = s[0];
            #pragma unroll
            for (int j = 1; j < 16; j++) cmax = fmaxf(cmax, s[j]);
            float mnew = fmaxf(m, cmax);
            float corr = __expf(m - mnew);
            m = mnew;
            l *= corr;
            #pragma unroll
            for (int i = 0; i < 16; i++) {
                acc[i].x *= corr; acc[i].y *= corr;
                acc[i].z *= corr; acc[i].w *= corr;
            }

            #pragma unroll
            for (int j = 0; j < 16; j++) {
                float p = __expf(s[j] - mnew);
                if (need_mask && (k0 + jc + j > row)) p = 0.0f;
                l += p;
                #pragma unroll
                for (int i = 0; i < 16; i++) {
                    float4 vv = *reinterpret_cast<const float4*>(&Vs[jc + j][i * 4]);
                    acc[i].x += p * vv.x;
                    acc[i].y += p * vv.y;
                    acc[i].z += p * vv.z;
                    acc[i].w += p * vv.w;
                }
            }
        }
        __syncthreads();
    }

    const float inv = 1.0f / l;
    #pragma unroll
    for (int i = 0; i < 16; i++) {
        float4 o;
        o.x = acc[i].x * inv; o.y = acc[i].y * inv;
        o.z = acc[i].z * inv; o.w = acc[i].w * inv;
        *reinterpret_cast<float4*>(O + qoff + i * 4) = o;
    }
}

// ---------------------------------------------------------------------------
// Launch: QKV projections -> attention -> output projection.
// ---------------------------------------------------------------------------
extern "C" void kernel_launch(void* const* d_in, const int* in_sizes, int n_in,
                              void* d_out, int out_size)
{
    const float* x  = (const float*)d_in[0];
    const float* Wq = (const float*)d_in[1];
    const float* bq = (const float*)d_in[2];
    const float* Wk = (const float*)d_in[3];
    const float* bk = (const float*)d_in[4];
    const float* Wv = (const float*)d_in[5];
    const float* bv = (const float*)d_in[6];
    const float* Wo = (const float*)d_in[7];
    const float* bo = (const float*)d_in[8];
    float* out = (float*)d_out;

    const int M = in_sizes[0] / D_MODEL;   // 4096
    const int B = M / SEQ_LEN;             // 2

    float *Qp, *Kp, *Vp, *Op;
    cudaGetSymbolAddress((void**)&Qp, g_Q);
    cudaGetSymbolAddress((void**)&Kp, g_K);
    cudaGetSymbolAddress((void**)&Vp, g_V);
    cudaGetSymbolAddress((void**)&Op, g_O);

    dim3 gemm_grid(D_MODEL / 128, M / 128);   // (8, 32)
    gemm_tf32_bias_kernel<<<gemm_grid, 256>>>(x, Wq, bq, Qp, M, D_MODEL, D_MODEL);
    gemm_tf32_bias_kernel<<<gemm_grid, 256>>>(x, Wk, bk, Kp, M, D_MODEL, D_MODEL);
    gemm_tf32_bias_kernel<<<gemm_grid, 256>>>(x, Wv, bv, Vp, M, D_MODEL, D_MODEL);

    dim3 attn_grid(SEQ_LEN / BR, B * NUM_HEADS);  // (16, 32)
    attn_kernel<<<attn_grid, 128>>>(Qp, Kp, Vp, Op);

    gemm_tf32_bias_kernel<<<gemm_grid, 256>>>(Op, Wo, bo, out, M, D_MODEL, D_MODEL);
}

// round 3
// speedup vs baseline: 2.1638x; 1.6904x over previous
#include <cuda_runtime.h>
#include <cstdint>

// ---------------------------------------------------------------------------
// Problem constants: x [B=2, S=2048, d=1024], H=16, Dh=64, causal MHA, fp32.
// ---------------------------------------------------------------------------
#define D_MODEL 1024
#define NUM_HEADS 16
#define D_HEAD 64
#define SEQ_LEN 2048
#define BATCH 2
#define M_ROWS (BATCH * SEQ_LEN)   // 4096

// Scratch (alloc-free rule: __device__ globals). 4 x 16 MB.
__device__ float g_Q[M_ROWS * D_MODEL];
__device__ float g_K[M_ROWS * D_MODEL];
__device__ float g_V[M_ROWS * D_MODEL];
__device__ float g_O[M_ROWS * D_MODEL];

__device__ __forceinline__ uint32_t f2tf32(float x) {
    uint32_t r;
    asm("cvt.rna.tf32.f32 %0, %1;" : "=r"(r) : "f"(x));
    return r;
}

__device__ __forceinline__ void mma_tf32(float c[4], const uint32_t a[4],
                                         uint32_t b0, uint32_t b1) {
    asm volatile(
        "mma.sync.aligned.m16n8k8.row.col.f32.tf32.tf32.f32 "
        "{%0,%1,%2,%3}, {%4,%5,%6,%7}, {%8,%9}, {%0,%1,%2,%3};\n"
        : "+f"(c[0]), "+f"(c[1]), "+f"(c[2]), "+f"(c[3])
        : "r"(a[0]), "r"(a[1]), "r"(a[2]), "r"(a[3]), "r"(b0), "r"(b1));
}

// ---------------------------------------------------------------------------
// TF32 tensor-core GEMM: C = tf32(A) @ tf32(B) + bias  (unchanged from R1)
// ---------------------------------------------------------------------------
#define GBK 32
#define APAD 4
#define LDA (128 + APAD)
#define LDB (128 + APAD)

__global__ __launch_bounds__(256) void gemm_tf32_bias_kernel(
    const float* __restrict__ A, const float* __restrict__ B,
    const float* __restrict__ bias, float* __restrict__ C,
    int M, int N, int K)
{
    __shared__ uint32_t As[GBK][LDA];
    __shared__ uint32_t Bs[GBK][LDB];

    const int tid  = threadIdx.x;
    const int lane = tid & 31;
    const int warp = tid >> 5;
    const int wm = (warp & 3) * 32;
    const int wn = (warp >> 2) * 64;
    const int lrow = lane >> 2;
    const int lcol = lane & 3;

    const int block_row = blockIdx.y * 128;
    const int block_col = blockIdx.x * 128;

    float c[2][8][4];
    #pragma unroll
    for (int mi = 0; mi < 2; mi++)
        #pragma unroll
        for (int ni = 0; ni < 8; ni++)
            #pragma unroll
            for (int r = 0; r < 4; r++) c[mi][ni][r] = 0.0f;

    for (int k0 = 0; k0 < K; k0 += GBK) {
        #pragma unroll
        for (int l = 0; l < 4; l++) {
            int fid = tid + l * 256;
            int r   = fid >> 3;
            int kq  = (fid & 7) * 4;
            float4 v = *reinterpret_cast<const float4*>(
                A + (size_t)(block_row + r) * K + k0 + kq);
            As[kq + 0][r] = f2tf32(v.x);
            As[kq + 1][r] = f2tf32(v.y);
            As[kq + 2][r] = f2tf32(v.z);
            As[kq + 3][r] = f2tf32(v.w);
        }
        #pragma unroll
        for (int l = 0; l < 4; l++) {
            int fid = tid + l * 256;
            int kr  = fid >> 5;
            int nq  = (fid & 31) * 4;
            float4 v = *reinterpret_cast<const float4*>(
                B + (size_t)(k0 + kr) * N + block_col + nq);
            Bs[kr][nq + 0] = f2tf32(v.x);
            Bs[kr][nq + 1] = f2tf32(v.y);
            Bs[kr][nq + 2] = f2tf32(v.z);
            Bs[kr][nq + 3] = f2tf32(v.w);
        }
        __syncthreads();

        #pragma unroll
        for (int kk = 0; kk < GBK; kk += 8) {
            uint32_t a[2][4];
            #pragma unroll
            for (int mi = 0; mi < 2; mi++) {
                int m0 = wm + mi * 16;
                a[mi][0] = As[kk + lcol    ][m0 + lrow    ];
                a[mi][1] = As[kk + lcol    ][m0 + 8 + lrow];
                a[mi][2] = As[kk + lcol + 4][m0 + lrow    ];
                a[mi][3] = As[kk + lcol + 4][m0 + 8 + lrow];
            }
            uint32_t b[8][2];
            #pragma unroll
            for (int ni = 0; ni < 8; ni++) {
                int n0 = wn + ni * 8;
                b[ni][0] = Bs[kk + lcol    ][n0 + lrow];
                b[ni][1] = Bs[kk + lcol + 4][n0 + lrow];
            }
            #pragma unroll
            for (int mi = 0; mi < 2; mi++)
                #pragma unroll
                for (int ni = 0; ni < 8; ni++)
                    mma_tf32(c[mi][ni], a[mi], b[ni][0], b[ni][1]);
        }
        __syncthreads();
    }

    #pragma unroll
    for (int mi = 0; mi < 2; mi++) {
        int r0 = block_row + wm + mi * 16 + lrow;
        #pragma unroll
        for (int ni = 0; ni < 8; ni++) {
            int col = block_col + wn + ni * 8 + lcol * 2;
            float b0 = bias[col];
            float b1 = bias[col + 1];
            float2 v0 = make_float2(c[mi][ni][0] + b0, c[mi][ni][1] + b1);
            float2 v1 = make_float2(c[mi][ni][2] + b0, c[mi][ni][3] + b1);
            *reinterpret_cast<float2*>(C + (size_t)r0 * N + col) = v0;
            *reinterpret_cast<float2*>(C + (size_t)(r0 + 8) * N + col) = v1;
        }
    }
}

// ---------------------------------------------------------------------------
// Tensor-core flash attention (3xTF32 precision-compensated, causal).
// CTA = 128 queries of one (b,h); 8 warps, each a 16-query m-tile.
// Key tile BC=32. K/V stored in SMEM in B-fragment order, hi/lo split.
// ---------------------------------------------------------------------------
#define BC32 32
#define KTILE_U32 2048   // 32 keys x 64 dh

__global__ __launch_bounds__(256, 2) void attn_mma_kernel(
    const float* __restrict__ Q, const float* __restrict__ K,
    const float* __restrict__ V, float* __restrict__ O)
{
    __shared__ __align__(16) uint32_t Khi[KTILE_U32];
    __shared__ __align__(16) uint32_t Klo[KTILE_U32];
    __shared__ __align__(16) uint32_t Vhi[KTILE_U32];
    __shared__ __align__(16) uint32_t Vlo[KTILE_U32];

    const int qt   = (int)gridDim.x - 1 - (int)blockIdx.x;  // heavy first
    const int bh   = blockIdx.y;
    const int b    = bh >> 4;
    const int h    = bh & 15;
    const int tid  = threadIdx.x;
    const int lane = tid & 31;
    const int warp = tid >> 5;
    const int g    = lane >> 2;   // 0..7
    const int t    = lane & 3;    // 0..3

    const int wq0 = qt * 128 + warp * 16;           // warp's first query row
    const size_t base = ((size_t)b * SEQ_LEN) * D_MODEL + h * D_HEAD;

    // --- Load Q fragments (fp32, scaled by 1/sqrt(Dh)); split at use time ---
    float qa[8][4];
    {
        const int row0 = wq0 + g, row1 = row0 + 8;
        #pragma unroll
        for (int kd = 0; kd < 8; kd++) {
            int c0 = kd * 8 + t, c1 = c0 + 4;
            qa[kd][0] = Q[base + (size_t)row0 * D_MODEL + c0] * 0.125f;
            qa[kd][1] = Q[base + (size_t)row1 * D_MODEL + c0] * 0.125f;
            qa[kd][2] = Q[base + (size_t)row0 * D_MODEL + c1] * 0.125f;
            qa[kd][3] = Q[base + (size_t)row1 * D_MODEL + c1] * 0.125f;
        }
    }

    float oc[8][4];
    #pragma unroll
    for (int nv = 0; nv < 8; nv++)
        #pragma unroll
        for (int r = 0; r < 4; r++) oc[nv][r] = 0.0f;

    float m0 = -1.0e30f, m1 = -1.0e30f;
    float l0 = 0.0f, l1 = 0.0f;

    // Producer decomposition: this thread handles key row (tid>>3), 8 dh vals.
    const int pkey = tid >> 3;            // 0..31
    const int pdq  = (tid & 7) * 8;       // 0..56
    const int pkd  = pdq >> 3;            // dh k-atom for K-fragments

    const int nkt = 4 * qt + 4;

    for (int kt = 0; kt < nkt; kt++) {
        const int k0 = kt * BC32;

        // ---- producer: load K/V rows, split tf32 hi/lo, scatter to frag order
        {
            const size_t goff = base + (size_t)(k0 + pkey) * D_MODEL + pdq;
            float4 kv0 = *reinterpret_cast<const float4*>(K + goff);
            float4 kv1 = *reinterpret_cast<const float4*>(K + goff + 4);
            float4 vv0 = *reinterpret_cast<const float4*>(V + goff);
            float4 vv1 = *reinterpret_cast<const float4*>(V + goff + 4);
            float kvals[8] = {kv0.x, kv0.y, kv0.z, kv0.w, kv1.x, kv1.y, kv1.z, kv1.w};
            float vvals[8] = {vv0.x, vv0.y, vv0.z, vv0.w, vv1.x, vv1.y, vv1.z, vv1.w};

            const int knt  = pkey >> 3;       // key n-tile (QK)
            const int knin = pkey & 7;        // key within n-tile
            const int vkv  = pkey >> 3;       // key k-atom (PV)
            const int vkin = pkey & 7;        // key within k-atom

            #pragma unroll
            for (int e = 0; e < 8; e++) {
                // K element: dh = pdq + e -> B-frag (katom=pkd, ntile=knt)
                uint32_t hi = f2tf32(kvals[e]);
                uint32_t lo = f2tf32(kvals[e] - __uint_as_float(hi));
                int koff = (((pkd * 4 + knt) * 32) + knin * 4 + (e & 3)) * 2 + (e >> 2);
                Khi[koff] = hi;
                Klo[koff] = lo;
                // V element: dh = pdq + e -> B-frag (katom=vkv, ntile=dh>>3)
                int dh = pdq + e;
                uint32_t vh = f2tf32(vvals[e]);
                uint32_t vl = f2tf32(vvals[e] - __uint_as_float(vh));
                int voff = (((vkv * 8 + (dh >> 3)) * 32) + (dh & 7) * 4 + (vkin & 3)) * 2
                           + (vkin >> 2);
                Vhi[voff] = vh;
                Vlo[voff] = vl;
            }
        }
        __syncthreads();

        if (k0 <= wq0 + 15) {   // warp has at least one unmasked key this tile
            // ---- S = QK^T (3xtf32) ----
            float sc[4][4];
            #pragma unroll
            for (int nt = 0; nt < 4; nt++)
                #pragma unroll
                for (int r = 0; r < 4; r++) sc[nt][r] = 0.0f;

            #pragma unroll
            for (int kd = 0; kd < 8; kd++) {
                uint32_t qh[4], ql[4];
                #pragma unroll
                for (int r = 0; r < 4; r++) {
                    qh[r] = f2tf32(qa[kd][r]);
                    ql[r] = f2tf32(qa[kd][r] - __uint_as_float(qh[r]));
                }
                #pragma unroll
                for (int nt = 0; nt < 4; nt++) {
                    uint2 bh2 = reinterpret_cast<const uint2*>(Khi)[(kd * 4 + nt) * 32 + lane];
                    uint2 bl2 = reinterpret_cast<const uint2*>(Klo)[(kd * 4 + nt) * 32 + lane];
                    mma_tf32(sc[nt], qh, bh2.x, bh2.y);
                    mma_tf32(sc[nt], qh, bl2.x, bl2.y);
                    mma_tf32(sc[nt], ql, bh2.x, bh2.y);
                }
            }

            const int row0 = wq0 + g, row1 = row0 + 8;

            // ---- causal mask (only for diagonal-crossing tiles) ----
            if (k0 + BC32 - 1 > wq0) {
                #pragma unroll
                for (int nt = 0; nt < 4; nt++) {
                    int col = k0 + nt * 8 + 2 * t;
                    if (col     > row0) sc[nt][0] = -1.0e30f;
                    if (col + 1 > row0) sc[nt][1] = -1.0e30f;
                    if (col     > row1) sc[nt][2] = -1.0e30f;
                    if (col + 1 > row1) sc[nt][3] = -1.0e30f;
                }
            }

            // ---- online softmax ----
            float mt0 = sc[0][0], mt1 = sc[0][2];
            #pragma unroll
            for (int nt = 0; nt < 4; nt++) {
                mt0 = fmaxf(mt0, fmaxf(sc[nt][0], sc[nt][1]));
                mt1 = fmaxf(mt1, fmaxf(sc[nt][2], sc[nt][3]));
            }
            #pragma unroll
            for (int w = 1; w < 4; w <<= 1) {
                mt0 = fmaxf(mt0, __shfl_xor_sync(0xffffffff, mt0, w));
                mt1 = fmaxf(mt1, __shfl_xor_sync(0xffffffff, mt1, w));
            }
            float mn0 = fmaxf(m0, mt0), mn1 = fmaxf(m1, mt1);
            float cr0 = __expf(m0 - mn0), cr1 = __expf(m1 - mn1);
            m0 = mn0; m1 = mn1;
            l0 *= cr0; l1 *= cr1;
            #pragma unroll
            for (int nv = 0; nv < 8; nv++) {
                oc[nv][0] *= cr0; oc[nv][1] *= cr0;
                oc[nv][2] *= cr1; oc[nv][3] *= cr1;
            }

            float ps[4][4];
            #pragma unroll
            for (int nt = 0; nt < 4; nt++) {
                ps[nt][0] = __expf(sc[nt][0] - m0);
                ps[nt][1] = __expf(sc[nt][1] - m0);
                ps[nt][2] = __expf(sc[nt][2] - m1);
                ps[nt][3] = __expf(sc[nt][3] - m1);
                l0 += ps[nt][0] + ps[nt][1];
                l1 += ps[nt][2] + ps[nt][3];
            }

            // ---- O += P V (3xtf32); P C-layout -> A-layout via shfl ----
            const int src0 = (lane & ~3) | (t >> 1);
            const int src1 = src0 + 2;
            const bool odd = (t & 1);
            #pragma unroll
            for (int kv = 0; kv < 4; kv++) {
                float a0f, a1f, a2f, a3f;
                {
                    float t00 = __shfl_sync(0xffffffff, ps[kv][0], src0);
                    float t01 = __shfl_sync(0xffffffff, ps[kv][1], src0);
                    a0f = odd ? t01 : t00;
                    float t10 = __shfl_sync(0xffffffff, ps[kv][2], src0);
                    float t11 = __shfl_sync(0xffffffff, ps[kv][3], src0);
                    a1f = odd ? t11 : t10;
                    float t20 = __shfl_sync(0xffffffff, ps[kv][0], src1);
                    float t21 = __shfl_sync(0xffffffff, ps[kv][1], src1);
                    a2f = odd ? t21 : t20;
                    float t30 = __shfl_sync(0xffffffff, ps[kv][2], src1);
                    float t31 = __shfl_sync(0xffffffff, ps[kv][3], src1);
                    a3f = odd ? t31 : t30;
                }
                uint32_t ph[4], pl[4];
                ph[0] = f2tf32(a0f); pl[0] = f2tf32(a0f - __uint_as_float(ph[0]));
                ph[1] = f2tf32(a1f); pl[1] = f2tf32(a1f - __uint_as_float(ph[1]));
                ph[2] = f2tf32(a2f); pl[2] = f2tf32(a2f - __uint_as_float(ph[2]));
                ph[3] = f2tf32(a3f); pl[3] = f2tf32(a3f - __uint_as_float(ph[3]));

                #pragma unroll
                for (int nv = 0; nv < 8; nv++) {
                    uint2 vh2 = reinterpret_cast<const uint2*>(Vhi)[(kv * 8 + nv) * 32 + lane];
                    uint2 vl2 = reinterpret_cast<const uint2*>(Vlo)[(kv * 8 + nv) * 32 + lane];
                    mma_tf32(oc[nv], ph, vh2.x, vh2.y);
                    mma_tf32(oc[nv], ph, vl2.x, vl2.y);
                    mma_tf32(oc[nv], pl, vh2.x, vh2.y);
                }
            }
        }
        __syncthreads();
    }

    // ---- finalize: cross-lane l reduce, normalize, store ----
    #pragma unroll
    for (int w = 1; w < 4; w <<= 1) {
        l0 += __shfl_xor_sync(0xffffffff, l0, w);
        l1 += __shfl_xor_sync(0xffffffff, l1, w);
    }
    const float inv0 = 1.0f / l0, inv1 = 1.0f / l1;
    const int row0 = wq0 + g, row1 = row0 + 8;
    #pragma unroll
    for (int nv = 0; nv < 8; nv++) {
        int col = nv * 8 + 2 * t;
        *reinterpret_cast<float2*>(O + base + (size_t)row0 * D_MODEL + col) =
            make_float2(oc[nv][0] * inv0, oc[nv][1] * inv0);
        *reinterpret_cast<float2*>(O + base + (size_t)row1 * D_MODEL + col) =
            make_float2(oc[nv][2] * inv1, oc[nv][3] * inv1);
    }
}

// ---------------------------------------------------------------------------
// Launch: QKV projections -> attention -> output projection.
// ---------------------------------------------------------------------------
extern "C" void kernel_launch(void* const* d_in, const int* in_sizes, int n_in,
                              void* d_out, int out_size)
{
    const float* x  = (const float*)d_in[0];
    const float* Wq = (const float*)d_in[1];
    const float* bq = (const float*)d_in[2];
    const float* Wk = (const float*)d_in[3];
    const float* bk = (const float*)d_in[4];
    const float* Wv = (const float*)d_in[5];
    const float* bv = (const float*)d_in[6];
    const float* Wo = (const float*)d_in[7];
    const float* bo = (const float*)d_in[8];
    float* out = (float*)d_out;

    const int M = in_sizes[0] / D_MODEL;   // 4096
    const int B = M / SEQ_LEN;             // 2

    float *Qp, *Kp, *Vp, *Op;
    cudaGetSymbolAddress((void**)&Qp, g_Q);
    cudaGetSymbolAddress((void**)&Kp, g_K);
    cudaGetSymbolAddress((void**)&Vp, g_V);
    cudaGetSymbolAddress((void**)&Op, g_O);

    dim3 gemm_grid(D_MODEL / 128, M / 128);   // (8, 32)
    gemm_tf32_bias_kernel<<<gemm_grid, 256>>>(x, Wq, bq, Qp, M, D_MODEL, D_MODEL);
    gemm_tf32_bias_kernel<<<gemm_grid, 256>>>(x, Wk, bk, Kp, M, D_MODEL, D_MODEL);
    gemm_tf32_bias_kernel<<<gemm_grid, 256>>>(x, Wv, bv, Vp, M, D_MODEL, D_MODEL);

    dim3 attn_grid(SEQ_LEN / 128, B * NUM_HEADS);  // (16, 32)
    attn_mma_kernel<<<attn_grid, 256>>>(Qp, Kp, Vp, Op);

    gemm_tf32_bias_kernel<<<gemm_grid, 256>>>(Op, Wo, bo, out, M, D_MODEL, D_MODEL);
}

// round 4
// speedup vs baseline: 2.5881x; 1.1961x over previous
#include <cuda_runtime.h>
#include <cstdint>

// ---------------------------------------------------------------------------
// Problem constants: x [B=2, S=2048, d=1024], H=16, Dh=64, causal MHA, fp32.
// ---------------------------------------------------------------------------
#define D_MODEL 1024
#define NUM_HEADS 16
#define D_HEAD 64
#define SEQ_LEN 2048
#define BATCH 2
#define M_ROWS (BATCH * SEQ_LEN)   // 4096
#define NTILES (SEQ_LEN / 32)      // 64 key tiles per (b,h)
#define STAGE_WORDS 8192           // 32KB per tile: [Khi 2048][Klo][Vhi][Vlo]

// Scratch (alloc-free rule: __device__ globals).
__device__ float g_Q[M_ROWS * D_MODEL];
__device__ float g_K[M_ROWS * D_MODEL];
__device__ float g_V[M_ROWS * D_MODEL];
__device__ float g_O[M_ROWS * D_MODEL];
// Packed K/V in tf32 hi/lo, fragment order, SMEM stage image per (bh, tile).
__device__ uint32_t g_KVP[(size_t)BATCH * NUM_HEADS * NTILES * STAGE_WORDS];

__device__ __forceinline__ uint32_t f2tf32(float x) {
    uint32_t r;
    asm("cvt.rna.tf32.f32 %0, %1;" : "=r"(r) : "f"(x));
    return r;
}

__device__ __forceinline__ void mma_tf32(float c[4], const uint32_t a[4],
                                         uint32_t b0, uint32_t b1) {
    asm volatile(
        "mma.sync.aligned.m16n8k8.row.col.f32.tf32.tf32.f32 "
        "{%0,%1,%2,%3}, {%4,%5,%6,%7}, {%8,%9}, {%0,%1,%2,%3};\n"
        : "+f"(c[0]), "+f"(c[1]), "+f"(c[2]), "+f"(c[3])
        : "r"(a[0]), "r"(a[1]), "r"(a[2]), "r"(a[3]), "r"(b0), "r"(b1));
}

// ---------------------------------------------------------------------------
// TF32 tensor-core GEMM: C = tf32(A) @ tf32(B) + bias  (unchanged, passing)
// ---------------------------------------------------------------------------
#define GBK 32
#define APAD 4
#define LDA (128 + APAD)
#define LDB (128 + APAD)

__global__ __launch_bounds__(256) void gemm_tf32_bias_kernel(
    const float* __restrict__ A, const float* __restrict__ B,
    const float* __restrict__ bias, float* __restrict__ C,
    int M, int N, int K)
{
    __shared__ uint32_t As[GBK][LDA];
    __shared__ uint32_t Bs[GBK][LDB];

    const int tid  = threadIdx.x;
    const int lane = tid & 31;
    const int warp = tid >> 5;
    const int wm = (warp & 3) * 32;
    const int wn = (warp >> 2) * 64;
    const int lrow = lane >> 2;
    const int lcol = lane & 3;

    const int block_row = blockIdx.y * 128;
    const int block_col = blockIdx.x * 128;

    float c[2][8][4];
    #pragma unroll
    for (int mi = 0; mi < 2; mi++)
        #pragma unroll
        for (int ni = 0; ni < 8; ni++)
            #pragma unroll
            for (int r = 0; r < 4; r++) c[mi][ni][r] = 0.0f;

    for (int k0 = 0; k0 < K; k0 += GBK) {
        #pragma unroll
        for (int l = 0; l < 4; l++) {
            int fid = tid + l * 256;
            int r   = fid >> 3;
            int kq  = (fid & 7) * 4;
            float4 v = *reinterpret_cast<const float4*>(
                A + (size_t)(block_row + r) * K + k0 + kq);
            As[kq + 0][r] = f2tf32(v.x);
            As[kq + 1][r] = f2tf32(v.y);
            As[kq + 2][r] = f2tf32(v.z);
            As[kq + 3][r] = f2tf32(v.w);
        }
        #pragma unroll
        for (int l = 0; l < 4; l++) {
            int fid = tid + l * 256;
            int kr  = fid >> 5;
            int nq  = (fid & 31) * 4;
            float4 v = *reinterpret_cast<const float4*>(
                B + (size_t)(k0 + kr) * N + block_col + nq);
            Bs[kr][nq + 0] = f2tf32(v.x);
            Bs[kr][nq + 1] = f2tf32(v.y);
            Bs[kr][nq + 2] = f2tf32(v.z);
            Bs[kr][nq + 3] = f2tf32(v.w);
        }
        __syncthreads();

        #pragma unroll
        for (int kk = 0; kk < GBK; kk += 8) {
            uint32_t a[2][4];
            #pragma unroll
            for (int mi = 0; mi < 2; mi++) {
                int m0 = wm + mi * 16;
                a[mi][0] = As[kk + lcol    ][m0 + lrow    ];
                a[mi][1] = As[kk + lcol    ][m0 + 8 + lrow];
                a[mi][2] = As[kk + lcol + 4][m0 + lrow    ];
                a[mi][3] = As[kk + lcol + 4][m0 + 8 + lrow];
            }
            uint32_t b[8][2];
            #pragma unroll
            for (int ni = 0; ni < 8; ni++) {
                int n0 = wn + ni * 8;
                b[ni][0] = Bs[kk + lcol    ][n0 + lrow];
                b[ni][1] = Bs[kk + lcol + 4][n0 + lrow];
            }
            #pragma unroll
            for (int mi = 0; mi < 2; mi++)
                #pragma unroll
                for (int ni = 0; ni < 8; ni++)
                    mma_tf32(c[mi][ni], a[mi], b[ni][0], b[ni][1]);
        }
        __syncthreads();
    }

    #pragma unroll
    for (int mi = 0; mi < 2; mi++) {
        int r0 = block_row + wm + mi * 16 + lrow;
        #pragma unroll
        for (int ni = 0; ni < 8; ni++) {
            int col = block_col + wn + ni * 8 + lcol * 2;
            float b0 = bias[col];
            float b1 = bias[col + 1];
            float2 v0 = make_float2(c[mi][ni][0] + b0, c[mi][ni][1] + b1);
            float2 v1 = make_float2(c[mi][ni][2] + b0, c[mi][ni][3] + b1);
            *reinterpret_cast<float2*>(C + (size_t)r0 * N + col) = v0;
            *reinterpret_cast<float2*>(C + (size_t)(r0 + 8) * N + col) = v1;
        }
    }
}

// ---------------------------------------------------------------------------
// Pack kernel: K,V -> tf32 hi/lo fragment-order stage images in g_KVP.
// One block per (tile, bh). Threads 0-255: K; 256-511: V.
// Mapping identical to R2's (verified-passing) in-attention producer:
//   K word: (kd*4+nt)*64 + (key&7)*8 + (dh&3)*2 + ((dh&7)>>2)
//   V word: (kv*8+nv)*64 + (dh&7)*8 + (key&3)*2 + ((key&7)>>2)
// ---------------------------------------------------------------------------
__global__ __launch_bounds__(512) void pack_kv_kernel(
    const float* __restrict__ K, const float* __restrict__ V,
    uint32_t* __restrict__ P)
{
    const int kt = blockIdx.x;
    const int bh = blockIdx.y;
    const int b  = bh >> 4;
    const int h  = bh & 15;
    const size_t base = ((size_t)b * SEQ_LEN) * D_MODEL + h * D_HEAD;
    uint32_t* blk = P + ((size_t)bh * NTILES + kt) * STAGE_WORDS;
    const int tid = threadIdx.x;

    if (tid < 256) {
        // K: thread = (key 0..31, kd 0..7); reads 8 contiguous dh.
        const int key = tid & 31;
        const int kd  = tid >> 5;
        const float* src = K + base + (size_t)(kt * 32 + key) * D_MODEL + kd * 8;
        float4 v0 = *reinterpret_cast<const float4*>(src);
        float4 v1 = *reinterpret_cast<const float4*>(src + 4);
        float e[8] = {v0.x, v0.y, v0.z, v0.w, v1.x, v1.y, v1.z, v1.w};
        uint32_t hi[8], lo[8];
        #pragma unroll
        for (int i = 0; i < 8; i++) {
            hi[i] = f2tf32(e[i]);
            lo[i] = f2tf32(e[i] - __uint_as_float(hi[i]));
        }
        const int nt = key >> 3, g = key & 7;
        uint32_t* dhi = blk + (kd * 4 + nt) * 64 + g * 8;
        uint32_t* dlo = dhi + 2048;
        // word order over e: [0,4,1,5,2,6,3,7]
        *reinterpret_cast<uint4*>(dhi)     = make_uint4(hi[0], hi[4], hi[1], hi[5]);
        *reinterpret_cast<uint4*>(dhi + 4) = make_uint4(hi[2], hi[6], hi[3], hi[7]);
        *reinterpret_cast<uint4*>(dlo)     = make_uint4(lo[0], lo[4], lo[1], lo[5]);
        *reinterpret_cast<uint4*>(dlo + 4) = make_uint4(lo[2], lo[6], lo[3], lo[7]);
    } else {
        // V: thread = (dh 0..63, kv 0..3); reads 8 keys (strided, coalesced over dh).
        const int t2 = tid - 256;
        const int dh = t2 & 63;
        const int kv = t2 >> 6;
        float e[8];
        #pragma unroll
        for (int k = 0; k < 8; k++)
            e[k] = V[base + (size_t)(kt * 32 + kv * 8 + k) * D_MODEL + dh];
        uint32_t hi[8], lo[8];
        #pragma unroll
        for (int i = 0; i < 8; i++) {
            hi[i] = f2tf32(e[i]);
            lo[i] = f2tf32(e[i] - __uint_as_float(hi[i]));
        }
        const int nv = dh >> 3;
        uint32_t* dhi = blk + 4096 + (kv * 8 + nv) * 64 + (dh & 7) * 8;
        uint32_t* dlo = dhi + 2048;
        // word order over k: [0,4,1,5,2,6,3,7]
        *reinterpret_cast<uint4*>(dhi)     = make_uint4(hi[0], hi[4], hi[1], hi[5]);
        *reinterpret_cast<uint4*>(dhi + 4) = make_uint4(hi[2], hi[6], hi[3], hi[7]);
        *reinterpret_cast<uint4*>(dlo)     = make_uint4(lo[0], lo[4], lo[1], lo[5]);
        *reinterpret_cast<uint4*>(dlo + 4) = make_uint4(lo[2], lo[6], lo[3], lo[7]);
    }
}

// ---------------------------------------------------------------------------
// Tensor-core flash attention, 3-stage cp.async pipeline over packed K/V.
// CTA = 128 queries of one (b,h); 8 warps x 16-query m-tile; BC=32.
// ---------------------------------------------------------------------------
__global__ __launch_bounds__(256, 2) void attn_mma_kernel(
    const float* __restrict__ Q, const uint32_t* __restrict__ KVP,
    float* __restrict__ O)
{
    extern __shared__ __align__(16) uint32_t sm[];

    const int qt   = (int)gridDim.x - 1 - (int)blockIdx.x;  // heavy first
    const int bh   = blockIdx.y;
    const int b    = bh >> 4;
    const int h    = bh & 15;
    const int tid  = threadIdx.x;
    const int lane = tid & 31;
    const int warp = tid >> 5;
    const int g    = lane >> 2;
    const int t    = lane & 3;

    const int wq0 = qt * 128 + warp * 16;
    const size_t base = ((size_t)b * SEQ_LEN) * D_MODEL + h * D_HEAD;
    const uint32_t* tile_base = KVP + (size_t)bh * NTILES * STAGE_WORDS;
    const uint32_t sm_addr = (uint32_t)__cvta_generic_to_shared(sm);
    const int nkt = 4 * qt + 4;

    // Q fragments (fp32, pre-scaled); hi/lo split at use time.
    float qa[8][4];
    {
        const int row0 = wq0 + g, row1 = row0 + 8;
        #pragma unroll
        for (int kd = 0; kd < 8; kd++) {
            int c0 = kd * 8 + t, c1 = c0 + 4;
            qa[kd][0] = Q[base + (size_t)row0 * D_MODEL + c0] * 0.125f;
            qa[kd][1] = Q[base + (size_t)row1 * D_MODEL + c0] * 0.125f;
            qa[kd][2] = Q[base + (size_t)row0 * D_MODEL + c1] * 0.125f;
            qa[kd][3] = Q[base + (size_t)row1 * D_MODEL + c1] * 0.125f;
        }
    }

    float oc[8][4];
    #pragma unroll
    for (int nv = 0; nv < 8; nv++)
        #pragma unroll
        for (int r = 0; r < 4; r++) oc[nv][r] = 0.0f;

    float m0 = -1.0e30f, m1 = -1.0e30f;
    float l0 = 0.0f, l1 = 0.0f;

    // ---- async tile loader: linear 32KB copy, 8x16B per thread ----
    auto issue_tile = [&](int kt) {
        if (kt < nkt) {
            const uint32_t* src = tile_base + (size_t)kt * STAGE_WORDS + tid * 4;
            uint32_t dst = sm_addr + ((kt % 3) * STAGE_WORDS + tid * 4) * 4;
            #pragma unroll
            for (int c = 0; c < 8; c++) {
                asm volatile("cp.async.cg.shared.global [%0], [%1], 16;\n"
                             :: "r"(dst + c * 4096), "l"(src + c * 1024));
            }
        }
        asm volatile("cp.async.commit_group;\n");
    };

    issue_tile(0);
    issue_tile(1);

    for (int kt = 0; kt < nkt; kt++) {
        asm volatile("cp.async.wait_group 1;\n");
        __syncthreads();

        const uint2* KhiS = reinterpret_cast<const uint2*>(sm + (kt % 3) * STAGE_WORDS);
        const uint2* KloS = KhiS + 1024;
        const uint2* VhiS = KhiS + 2048;
        const uint2* VloS = KhiS + 3072;
        const int k0 = kt * 32;

        if (k0 <= wq0 + 15) {
            // ---- S = QK^T (3xtf32) ----
            float sc[4][4];
            #pragma unroll
            for (int nt = 0; nt < 4; nt++)
                #pragma unroll
                for (int r = 0; r < 4; r++) sc[nt][r] = 0.0f;

            #pragma unroll
            for (int kd = 0; kd < 8; kd++) {
                uint32_t qh[4], ql[4];
                #pragma unroll
                for (int r = 0; r < 4; r++) {
                    qh[r] = f2tf32(qa[kd][r]);
                    ql[r] = f2tf32(qa[kd][r] - __uint_as_float(qh[r]));
                }
                #pragma unroll
                for (int nt = 0; nt < 4; nt++) {
                    uint2 bh2 = KhiS[(kd * 4 + nt) * 32 + lane];
                    uint2 bl2 = KloS[(kd * 4 + nt) * 32 + lane];
                    mma_tf32(sc[nt], qh, bh2.x, bh2.y);
                    mma_tf32(sc[nt], qh, bl2.x, bl2.y);
                    mma_tf32(sc[nt], ql, bh2.x, bh2.y);
                }
            }

            const int row0 = wq0 + g, row1 = row0 + 8;

            if (k0 + 31 > wq0) {   // diagonal tile: apply causal mask
                #pragma unroll
                for (int nt = 0; nt < 4; nt++) {
                    int col = k0 + nt * 8 + 2 * t;
                    if (col     > row0) sc[nt][0] = -1.0e30f;
                    if (col + 1 > row0) sc[nt][1] = -1.0e30f;
                    if (col     > row1) sc[nt][2] = -1.0e30f;
                    if (col + 1 > row1) sc[nt][3] = -1.0e30f;
                }
            }

            // ---- online softmax ----
            float mt0 = sc[0][0], mt1 = sc[0][2];
            #pragma unroll
            for (int nt = 0; nt < 4; nt++) {
                mt0 = fmaxf(mt0, fmaxf(sc[nt][0], sc[nt][1]));
                mt1 = fmaxf(mt1, fmaxf(sc[nt][2], sc[nt][3]));
            }
            #pragma unroll
            for (int w = 1; w < 4; w <<= 1) {
                mt0 = fmaxf(mt0, __shfl_xor_sync(0xffffffff, mt0, w));
                mt1 = fmaxf(mt1, __shfl_xor_sync(0xffffffff, mt1, w));
            }
            float mn0 = fmaxf(m0, mt0), mn1 = fmaxf(m1, mt1);
            float cr0 = __expf(m0 - mn0), cr1 = __expf(m1 - mn1);
            m0 = mn0; m1 = mn1;
            l0 *= cr0; l1 *= cr1;
            #pragma unroll
            for (int nv = 0; nv < 8; nv++) {
                oc[nv][0] *= cr0; oc[nv][1] *= cr0;
                oc[nv][2] *= cr1; oc[nv][3] *= cr1;
            }

            float ps[4][4];
            #pragma unroll
            for (int nt = 0; nt < 4; nt++) {
                ps[nt][0] = __expf(sc[nt][0] - m0);
                ps[nt][1] = __expf(sc[nt][1] - m0);
                ps[nt][2] = __expf(sc[nt][2] - m1);
                ps[nt][3] = __expf(sc[nt][3] - m1);
                l0 += ps[nt][0] + ps[nt][1];
                l1 += ps[nt][2] + ps[nt][3];
            }

            // ---- O += P V (3xtf32); C-layout -> A-layout via shfl ----
            const int src0 = (lane & ~3) | (t >> 1);
            const int src1 = src0 + 2;
            const bool odd = (t & 1);
            #pragma unroll
            for (int kv = 0; kv < 4; kv++) {
                float a0f, a1f, a2f, a3f;
                {
                    float t00 = __shfl_sync(0xffffffff, ps[kv][0], src0);
                    float t01 = __shfl_sync(0xffffffff, ps[kv][1], src0);
                    a0f = odd ? t01 : t00;
                    float t10 = __shfl_sync(0xffffffff, ps[kv][2], src0);
                    float t11 = __shfl_sync(0xffffffff, ps[kv][3], src0);
                    a1f = odd ? t11 : t10;
                    float t20 = __shfl_sync(0xffffffff, ps[kv][0], src1);
                    float t21 = __shfl_sync(0xffffffff, ps[kv][1], src1);
                    a2f = odd ? t21 : t20;
                    float t30 = __shfl_sync(0xffffffff, ps[kv][2], src1);
                    float t31 = __shfl_sync(0xffffffff, ps[kv][3], src1);
                    a3f = odd ? t31 : t30;
                }
                uint32_t ph[4], pl[4];
                ph[0] = f2tf32(a0f); pl[0] = f2tf32(a0f - __uint_as_float(ph[0]));
                ph[1] = f2tf32(a1f); pl[1] = f2tf32(a1f - __uint_as_float(ph[1]));
                ph[2] = f2tf32(a2f); pl[2] = f2tf32(a2f - __uint_as_float(ph[2]));
                ph[3] = f2tf32(a3f); pl[3] = f2tf32(a3f - __uint_as_float(ph[3]));

                #pragma unroll
                for (int nv = 0; nv < 8; nv++) {
                    uint2 vh2 = VhiS[(kv * 8 + nv) * 32 + lane];
                    uint2 vl2 = VloS[(kv * 8 + nv) * 32 + lane];
                    mma_tf32(oc[nv], ph, vh2.x, vh2.y);
                    mma_tf32(oc[nv], ph, vl2.x, vl2.y);
                    mma_tf32(oc[nv], pl, vh2.x, vh2.y);
                }
            }
        }

        issue_tile(kt + 2);
    }

    // ---- finalize ----
    #pragma unroll
    for (int w = 1; w < 4; w <<= 1) {
        l0 += __shfl_xor_sync(0xffffffff, l0, w);
        l1 += __shfl_xor_sync(0xffffffff, l1, w);
    }
    const float inv0 = 1.0f / l0, inv1 = 1.0f / l1;
    const int row0 = wq0 + g, row1 = row0 + 8;
    #pragma unroll
    for (int nv = 0; nv < 8; nv++) {
        int col = nv * 8 + 2 * t;
        *reinterpret_cast<float2*>(O + base + (size_t)row0 * D_MODEL + col) =
            make_float2(oc[nv][0] * inv0, oc[nv][1] * inv0);
        *reinterpret_cast<float2*>(O + base + (size_t)row1 * D_MODEL + col) =
            make_float2(oc[nv][2] * inv1, oc[nv][3] * inv1);
    }
}

// ---------------------------------------------------------------------------
// Launch: QKV projections -> pack -> attention -> output projection.
// ---------------------------------------------------------------------------
extern "C" void kernel_launch(void* const* d_in, const int* in_sizes, int n_in,
                              void* d_out, int out_size)
{
    const float* x  = (const float*)d_in[0];
    const float* Wq = (const float*)d_in[1];
    const float* bq = (const float*)d_in[2];
    const float* Wk = (const float*)d_in[3];
    const float* bk = (const float*)d_in[4];
    const float* Wv = (const float*)d_in[5];
    const float* bv = (const float*)d_in[6];
    const float* Wo = (const float*)d_in[7];
    const float* bo = (const float*)d_in[8];
    float* out = (float*)d_out;

    const int M = in_sizes[0] / D_MODEL;   // 4096
    const int B = M / SEQ_LEN;             // 2

    float *Qp, *Kp, *Vp, *Op;
    uint32_t* KVPp;
    cudaGetSymbolAddress((void**)&Qp, g_Q);
    cudaGetSymbolAddress((void**)&Kp, g_K);
    cudaGetSymbolAddress((void**)&Vp, g_V);
    cudaGetSymbolAddress((void**)&Op, g_O);
    cudaGetSymbolAddress((void**)&KVPp, g_KVP);

    static bool attr_set = false;
    if (!attr_set) {
        cudaFuncSetAttribute(attn_mma_kernel,
                             cudaFuncAttributeMaxDynamicSharedMemorySize,
                             3 * STAGE_WORDS * 4);
        attr_set = true;
    }

    dim3 gemm_grid(D_MODEL / 128, M / 128);   // (8, 32)
    gemm_tf32_bias_kernel<<<gemm_grid, 256>>>(x, Wq, bq, Qp, M, D_MODEL, D_MODEL);
    gemm_tf32_bias_kernel<<<gemm_grid, 256>>>(x, Wk, bk, Kp, M, D_MODEL, D_MODEL);
    gemm_tf32_bias_kernel<<<gemm_grid, 256>>>(x, Wv, bv, Vp, M, D_MODEL, D_MODEL);

    dim3 pack_grid(NTILES, B * NUM_HEADS);    // (64, 32)
    pack_kv_kernel<<<pack_grid, 512>>>(Kp, Vp, KVPp);

    dim3 attn_grid(SEQ_LEN / 128, B * NUM_HEADS);  // (16, 32)
    attn_mma_kernel<<<attn_grid, 256, 3 * STAGE_WORDS * 4>>>(Qp, KVPp, out ? Op : Op);

    gemm_tf32_bias_kernel<<<gemm_grid, 256>>>(Op, Wo, bo, out, M, D_MODEL, D_MODEL);
}

// round 5
// speedup vs baseline: 2.7086x; 1.0466x over previous
#include <cuda_runtime.h>
#include <cstdint>

// ---------------------------------------------------------------------------
// Problem constants: x [B=2, S=2048, d=1024], H=16, Dh=64, causal MHA, fp32.
// ---------------------------------------------------------------------------
#define D_MODEL 1024
#define NUM_HEADS 16
#define D_HEAD 64
#define SEQ_LEN 2048
#define BATCH 2
#define M_ROWS (BATCH * SEQ_LEN)   // 4096
#define NTILES (SEQ_LEN / 32)      // 64 key tiles per (b,h)
#define STAGE_WORDS 8192           // 32KB per tile: [Khi 2048][Klo][Vhi][Vlo]

// Scratch (alloc-free rule: __device__ globals).
__device__ float g_Q[M_ROWS * D_MODEL];
__device__ float g_K[M_ROWS * D_MODEL];
__device__ float g_V[M_ROWS * D_MODEL];
__device__ float g_O[M_ROWS * D_MODEL];
// Packed K/V in tf32 hi/lo, fragment order, SMEM stage image per (bh, tile).
__device__ uint32_t g_KVP[(size_t)BATCH * NUM_HEADS * NTILES * STAGE_WORDS];

__device__ __forceinline__ uint32_t f2tf32(float x) {
    uint32_t r;
    asm("cvt.rna.tf32.f32 %0, %1;" : "=r"(r) : "f"(x));
    return r;
}

__device__ __forceinline__ void mma_tf32(float c[4], const uint32_t a[4],
                                         uint32_t b0, uint32_t b1) {
    asm volatile(
        "mma.sync.aligned.m16n8k8.row.col.f32.tf32.tf32.f32 "
        "{%0,%1,%2,%3}, {%4,%5,%6,%7}, {%8,%9}, {%0,%1,%2,%3};\n"
        : "+f"(c[0]), "+f"(c[1]), "+f"(c[2]), "+f"(c[3])
        : "r"(a[0]), "r"(a[1]), "r"(a[2]), "r"(a[3]), "r"(b0), "r"(b1));
}

// ---------------------------------------------------------------------------
// TF32 GEMM, double-buffered SMEM + register prefetch, 1 barrier per k-tile.
// CTA 128x128, BK=32, 8 warps; warp tile 32x64 via mma.sync.m16n8k8.
// ---------------------------------------------------------------------------
#define GBK 32
#define APAD 4
#define LDA (128 + APAD)
#define LDB (128 + APAD)
#define AOFF (GBK * LDA)                  // Bs offset within a buffer
#define BUFW (GBK * LDA + GBK * LDB)      // words per buffer (8448)

__global__ __launch_bounds__(256) void gemm_tf32_bias_kernel(
    const float* __restrict__ A, const float* __restrict__ B,
    const float* __restrict__ bias, float* __restrict__ C,
    int M, int N, int K)
{
    extern __shared__ __align__(16) uint32_t gsm[];

    const int tid  = threadIdx.x;
    const int lane = tid & 31;
    const int warp = tid >> 5;
    const int wm = (warp & 3) * 32;
    const int wn = (warp >> 2) * 64;
    const int lrow = lane >> 2;
    const int lcol = lane & 3;

    const int block_row = blockIdx.y * 128;
    const int block_col = blockIdx.x * 128;

    float c[2][8][4];
    #pragma unroll
    for (int mi = 0; mi < 2; mi++)
        #pragma unroll
        for (int ni = 0; ni < 8; ni++)
            #pragma unroll
            for (int r = 0; r < 4; r++) c[mi][ni][r] = 0.0f;

    float4 pa[4], pb[4];

    auto ldg_tile = [&](int k0) {
        #pragma unroll
        for (int l = 0; l < 4; l++) {
            int fid = tid + l * 256;
            int r   = fid >> 3;
            int kq  = (fid & 7) * 4;
            pa[l] = *reinterpret_cast<const float4*>(
                A + (size_t)(block_row + r) * K + k0 + kq);
        }
        #pragma unroll
        for (int l = 0; l < 4; l++) {
            int fid = tid + l * 256;
            int kr  = fid >> 5;
            int nq  = (fid & 31) * 4;
            pb[l] = *reinterpret_cast<const float4*>(
                B + (size_t)(k0 + kr) * N + block_col + nq);
        }
    };

    auto sts_tile = [&](int p) {
        uint32_t* buf = gsm + p * BUFW;
        #pragma unroll
        for (int l = 0; l < 4; l++) {
            int fid = tid + l * 256;
            int r   = fid >> 3;
            int kq  = (fid & 7) * 4;
            buf[(kq + 0) * LDA + r] = f2tf32(pa[l].x);
            buf[(kq + 1) * LDA + r] = f2tf32(pa[l].y);
            buf[(kq + 2) * LDA + r] = f2tf32(pa[l].z);
            buf[(kq + 3) * LDA + r] = f2tf32(pa[l].w);
        }
        #pragma unroll
        for (int l = 0; l < 4; l++) {
            int fid = tid + l * 256;
            int kr  = fid >> 5;
            int nq  = (fid & 31) * 4;
            uint32_t* d = buf + AOFF + kr * LDB + nq;
            d[0] = f2tf32(pb[l].x);
            d[1] = f2tf32(pb[l].y);
            d[2] = f2tf32(pb[l].z);
            d[3] = f2tf32(pb[l].w);
        }
    };

    const int T = K / GBK;
    ldg_tile(0);
    sts_tile(0);

    for (int t = 0; t < T; t++) {
        if (t + 1 < T) ldg_tile((t + 1) * GBK);
        __syncthreads();

        const uint32_t* As = gsm + (t & 1) * BUFW;
        const uint32_t* Bs = As + AOFF;

        #pragma unroll
        for (int kk = 0; kk < GBK; kk += 8) {
            uint32_t a[2][4];
            #pragma unroll
            for (int mi = 0; mi < 2; mi++) {
                int m0 = wm + mi * 16;
                a[mi][0] = As[(kk + lcol    ) * LDA + m0 + lrow    ];
                a[mi][1] = As[(kk + lcol    ) * LDA + m0 + 8 + lrow];
                a[mi][2] = As[(kk + lcol + 4) * LDA + m0 + lrow    ];
                a[mi][3] = As[(kk + lcol + 4) * LDA + m0 + 8 + lrow];
            }
            uint32_t b[8][2];
            #pragma unroll
            for (int ni = 0; ni < 8; ni++) {
                int n0 = wn + ni * 8;
                b[ni][0] = Bs[(kk + lcol    ) * LDB + n0 + lrow];
                b[ni][1] = Bs[(kk + lcol + 4) * LDB + n0 + lrow];
            }
            #pragma unroll
            for (int mi = 0; mi < 2; mi++)
                #pragma unroll
                for (int ni = 0; ni < 8; ni++)
                    mma_tf32(c[mi][ni], a[mi], b[ni][0], b[ni][1]);
        }

        if (t + 1 < T) sts_tile((t + 1) & 1);
    }

    #pragma unroll
    for (int mi = 0; mi < 2; mi++) {
        int r0 = block_row + wm + mi * 16 + lrow;
        #pragma unroll
        for (int ni = 0; ni < 8; ni++) {
            int col = block_col + wn + ni * 8 + lcol * 2;
            float b0 = bias[col];
            float b1 = bias[col + 1];
            float2 v0 = make_float2(c[mi][ni][0] + b0, c[mi][ni][1] + b1);
            float2 v1 = make_float2(c[mi][ni][2] + b0, c[mi][ni][3] + b1);
            *reinterpret_cast<float2*>(C + (size_t)r0 * N + col) = v0;
            *reinterpret_cast<float2*>(C + (size_t)(r0 + 8) * N + col) = v1;
        }
    }
}

// ---------------------------------------------------------------------------
// Pack kernel: K,V -> tf32 hi/lo fragment-order stage images (unchanged).
// ---------------------------------------------------------------------------
__global__ __launch_bounds__(512) void pack_kv_kernel(
    const float* __restrict__ K, const float* __restrict__ V,
    uint32_t* __restrict__ P)
{
    const int kt = blockIdx.x;
    const int bh = blockIdx.y;
    const int b  = bh >> 4;
    const int h  = bh & 15;
    const size_t base = ((size_t)b * SEQ_LEN) * D_MODEL + h * D_HEAD;
    uint32_t* blk = P + ((size_t)bh * NTILES + kt) * STAGE_WORDS;
    const int tid = threadIdx.x;

    if (tid < 256) {
        const int key = tid & 31;
        const int kd  = tid >> 5;
        const float* src = K + base + (size_t)(kt * 32 + key) * D_MODEL + kd * 8;
        float4 v0 = *reinterpret_cast<const float4*>(src);
        float4 v1 = *reinterpret_cast<const float4*>(src + 4);
        float e[8] = {v0.x, v0.y, v0.z, v0.w, v1.x, v1.y, v1.z, v1.w};
        uint32_t hi[8], lo[8];
        #pragma unroll
        for (int i = 0; i < 8; i++) {
            hi[i] = f2tf32(e[i]);
            lo[i] = f2tf32(e[i] - __uint_as_float(hi[i]));
        }
        const int nt = key >> 3, g = key & 7;
        uint32_t* dhi = blk + (kd * 4 + nt) * 64 + g * 8;
        uint32_t* dlo = dhi + 2048;
        *reinterpret_cast<uint4*>(dhi)     = make_uint4(hi[0], hi[4], hi[1], hi[5]);
        *reinterpret_cast<uint4*>(dhi + 4) = make_uint4(hi[2], hi[6], hi[3], hi[7]);
        *reinterpret_cast<uint4*>(dlo)     = make_uint4(lo[0], lo[4], lo[1], lo[5]);
        *reinterpret_cast<uint4*>(dlo + 4) = make_uint4(lo[2], lo[6], lo[3], lo[7]);
    } else {
        const int t2 = tid - 256;
        const int dh = t2 & 63;
        const int kv = t2 >> 6;
        float e[8];
        #pragma unroll
        for (int k = 0; k < 8; k++)
            e[k] = V[base + (size_t)(kt * 32 + kv * 8 + k) * D_MODEL + dh];
        uint32_t hi[8], lo[8];
        #pragma unroll
        for (int i = 0; i < 8; i++) {
            hi[i] = f2tf32(e[i]);
            lo[i] = f2tf32(e[i] - __uint_as_float(hi[i]));
        }
        const int nv = dh >> 3;
        uint32_t* dhi = blk + 4096 + (kv * 8 + nv) * 64 + (dh & 7) * 8;
        uint32_t* dlo = dhi + 2048;
        *reinterpret_cast<uint4*>(dhi)     = make_uint4(hi[0], hi[4], hi[1], hi[5]);
        *reinterpret_cast<uint4*>(dhi + 4) = make_uint4(hi[2], hi[6], hi[3], hi[7]);
        *reinterpret_cast<uint4*>(dlo)     = make_uint4(lo[0], lo[4], lo[1], lo[5]);
        *reinterpret_cast<uint4*>(dlo + 4) = make_uint4(lo[2], lo[6], lo[3], lo[7]);
    }
}

// ---------------------------------------------------------------------------
// Tensor-core flash attention, 3-stage cp.async pipeline over packed K/V.
// QK^T: 3xTF32; PV: 2xTF32 (ph*Vhi + ph*Vlo; pl term dropped, error ~1e-4).
// ---------------------------------------------------------------------------
__global__ __launch_bounds__(256, 2) void attn_mma_kernel(
    const float* __restrict__ Q, const uint32_t* __restrict__ KVP,
    float* __restrict__ O)
{
    extern __shared__ __align__(16) uint32_t sm[];

    const int qt   = (int)gridDim.x - 1 - (int)blockIdx.x;  // heavy first
    const int bh   = blockIdx.y;
    const int b    = bh >> 4;
    const int h    = bh & 15;
    const int tid  = threadIdx.x;
    const int lane = tid & 31;
    const int warp = tid >> 5;
    const int g    = lane >> 2;
    const int t    = lane & 3;

    const int wq0 = qt * 128 + warp * 16;
    const size_t base = ((size_t)b * SEQ_LEN) * D_MODEL + h * D_HEAD;
    const uint32_t* tile_base = KVP + (size_t)bh * NTILES * STAGE_WORDS;
    const uint32_t sm_addr = (uint32_t)__cvta_generic_to_shared(sm);
    const int nkt = 4 * qt + 4;

    float qa[8][4];
    {
        const int row0 = wq0 + g, row1 = row0 + 8;
        #pragma unroll
        for (int kd = 0; kd < 8; kd++) {
            int c0 = kd * 8 + t, c1 = c0 + 4;
            qa[kd][0] = Q[base + (size_t)row0 * D_MODEL + c0] * 0.125f;
            qa[kd][1] = Q[base + (size_t)row1 * D_MODEL + c0] * 0.125f;
            qa[kd][2] = Q[base + (size_t)row0 * D_MODEL + c1] * 0.125f;
            qa[kd][3] = Q[base + (size_t)row1 * D_MODEL + c1] * 0.125f;
        }
    }

    float oc[8][4];
    #pragma unroll
    for (int nv = 0; nv < 8; nv++)
        #pragma unroll
        for (int r = 0; r < 4; r++) oc[nv][r] = 0.0f;

    float m0 = -1.0e30f, m1 = -1.0e30f;
    float l0 = 0.0f, l1 = 0.0f;

    auto issue_tile = [&](int kt) {
        if (kt < nkt) {
            const uint32_t* src = tile_base + (size_t)kt * STAGE_WORDS + tid * 4;
            uint32_t dst = sm_addr + ((kt % 3) * STAGE_WORDS + tid * 4) * 4;
            #pragma unroll
            for (int c = 0; c < 8; c++) {
                asm volatile("cp.async.cg.shared.global [%0], [%1], 16;\n"
                             :: "r"(dst + c * 4096), "l"(src + c * 1024));
            }
        }
        asm volatile("cp.async.commit_group;\n");
    };

    issue_tile(0);
    issue_tile(1);

    for (int kt = 0; kt < nkt; kt++) {
        asm volatile("cp.async.wait_group 1;\n");
        __syncthreads();

        const uint2* KhiS = reinterpret_cast<const uint2*>(sm + (kt % 3) * STAGE_WORDS);
        const uint2* KloS = KhiS + 1024;
        const uint2* VhiS = KhiS + 2048;
        const uint2* VloS = KhiS + 3072;
        const int k0 = kt * 32;

        if (k0 <= wq0 + 15) {
            // ---- S = QK^T (3xtf32) ----
            float sc[4][4];
            #pragma unroll
            for (int nt = 0; nt < 4; nt++)
                #pragma unroll
                for (int r = 0; r < 4; r++) sc[nt][r] = 0.0f;

            #pragma unroll
            for (int kd = 0; kd < 8; kd++) {
                uint32_t qh[4], ql[4];
                #pragma unroll
                for (int r = 0; r < 4; r++) {
                    qh[r] = f2tf32(qa[kd][r]);
                    ql[r] = f2tf32(qa[kd][r] - __uint_as_float(qh[r]));
                }
                #pragma unroll
                for (int nt = 0; nt < 4; nt++) {
                    uint2 bh2 = KhiS[(kd * 4 + nt) * 32 + lane];
                    uint2 bl2 = KloS[(kd * 4 + nt) * 32 + lane];
                    mma_tf32(sc[nt], qh, bh2.x, bh2.y);
                    mma_tf32(sc[nt], qh, bl2.x, bl2.y);
                    mma_tf32(sc[nt], ql, bh2.x, bh2.y);
                }
            }

            const int row0 = wq0 + g, row1 = row0 + 8;

            if (k0 + 31 > wq0) {
                #pragma unroll
                for (int nt = 0; nt < 4; nt++) {
                    int col = k0 + nt * 8 + 2 * t;
                    if (col     > row0) sc[nt][0] = -1.0e30f;
                    if (col + 1 > row0) sc[nt][1] = -1.0e30f;
                    if (col     > row1) sc[nt][2] = -1.0e30f;
                    if (col + 1 > row1) sc[nt][3] = -1.0e30f;
                }
            }

            // ---- online softmax ----
            float mt0 = sc[0][0], mt1 = sc[0][2];
            #pragma unroll
            for (int nt = 0; nt < 4; nt++) {
                mt0 = fmaxf(mt0, fmaxf(sc[nt][0], sc[nt][1]));
                mt1 = fmaxf(mt1, fmaxf(sc[nt][2], sc[nt][3]));
            }
            #pragma unroll
            for (int w = 1; w < 4; w <<= 1) {
                mt0 = fmaxf(mt0, __shfl_xor_sync(0xffffffff, mt0, w));
                mt1 = fmaxf(mt1, __shfl_xor_sync(0xffffffff, mt1, w));
            }
            float mn0 = fmaxf(m0, mt0), mn1 = fmaxf(m1, mt1);
            float cr0 = __expf(m0 - mn0), cr1 = __expf(m1 - mn1);
            m0 = mn0; m1 = mn1;
            l0 *= cr0; l1 *= cr1;
            #pragma unroll
            for (int nv = 0; nv < 8; nv++) {
                oc[nv][0] *= cr0; oc[nv][1] *= cr0;
                oc[nv][2] *= cr1; oc[nv][3] *= cr1;
            }

            float ps[4][4];
            #pragma unroll
            for (int nt = 0; nt < 4; nt++) {
                ps[nt][0] = __expf(sc[nt][0] - m0);
                ps[nt][1] = __expf(sc[nt][1] - m0);
                ps[nt][2] = __expf(sc[nt][2] - m1);
                ps[nt][3] = __expf(sc[nt][3] - m1);
                l0 += ps[nt][0] + ps[nt][1];
                l1 += ps[nt][2] + ps[nt][3];
            }

            // ---- O += P V (2xtf32); C-layout -> A-layout via shfl ----
            const int src0 = (lane & ~3) | (t >> 1);
            const int src1 = src0 + 2;
            const bool odd = (t & 1);
            #pragma unroll
            for (int kv = 0; kv < 4; kv++) {
                float a0f, a1f, a2f, a3f;
                {
                    float t00 = __shfl_sync(0xffffffff, ps[kv][0], src0);
                    float t01 = __shfl_sync(0xffffffff, ps[kv][1], src0);
                    a0f = odd ? t01 : t00;
                    float t10 = __shfl_sync(0xffffffff, ps[kv][2], src0);
                    float t11 = __shfl_sync(0xffffffff, ps[kv][3], src0);
                    a1f = odd ? t11 : t10;
                    float t20 = __shfl_sync(0xffffffff, ps[kv][0], src1);
                    float t21 = __shfl_sync(0xffffffff, ps[kv][1], src1);
                    a2f = odd ? t21 : t20;
                    float t30 = __shfl_sync(0xffffffff, ps[kv][2], src1);
                    float t31 = __shfl_sync(0xffffffff, ps[kv][3], src1);
                    a3f = odd ? t31 : t30;
                }
                uint32_t ph[4];
                ph[0] = f2tf32(a0f);
                ph[1] = f2tf32(a1f);
                ph[2] = f2tf32(a2f);
                ph[3] = f2tf32(a3f);

                #pragma unroll
                for (int nv = 0; nv < 8; nv++) {
                    uint2 vh2 = VhiS[(kv * 8 + nv) * 32 + lane];
                    uint2 vl2 = VloS[(kv * 8 + nv) * 32 + lane];
                    mma_tf32(oc[nv], ph, vh2.x, vh2.y);
                    mma_tf32(oc[nv], ph, vl2.x, vl2.y);
                }
            }
        }

        issue_tile(kt + 2);
    }

    // ---- finalize ----
    #pragma unroll
    for (int w = 1; w < 4; w <<= 1) {
        l0 += __shfl_xor_sync(0xffffffff, l0, w);
        l1 += __shfl_xor_sync(0xffffffff, l1, w);
    }
    const float inv0 = 1.0f / l0, inv1 = 1.0f / l1;
    const int row0 = wq0 + g, row1 = row0 + 8;
    #pragma unroll
    for (int nv = 0; nv < 8; nv++) {
        int col = nv * 8 + 2 * t;
        *reinterpret_cast<float2*>(O + base + (size_t)row0 * D_MODEL + col) =
            make_float2(oc[nv][0] * inv0, oc[nv][1] * inv0);
        *reinterpret_cast<float2*>(O + base + (size_t)row1 * D_MODEL + col) =
            make_float2(oc[nv][2] * inv1, oc[nv][3] * inv1);
    }
}

// ---------------------------------------------------------------------------
// Launch: QKV projections -> pack -> attention -> output projection.
// ---------------------------------------------------------------------------
extern "C" void kernel_launch(void* const* d_in, const int* in_sizes, int n_in,
                              void* d_out, int out_size)
{
    const float* x  = (const float*)d_in[0];
    const float* Wq = (const float*)d_in[1];
    const float* bq = (const float*)d_in[2];
    const float* Wk = (const float*)d_in[3];
    const float* bk = (const float*)d_in[4];
    const float* Wv = (const float*)d_in[5];
    const float* bv = (const float*)d_in[6];
    const float* Wo = (const float*)d_in[7];
    const float* bo = (const float*)d_in[8];
    float* out = (float*)d_out;

    const int M = in_sizes[0] / D_MODEL;   // 4096
    const int B = M / SEQ_LEN;             // 2

    float *Qp, *Kp, *Vp, *Op;
    uint32_t* KVPp;
    cudaGetSymbolAddress((void**)&Qp, g_Q);
    cudaGetSymbolAddress((void**)&Kp, g_K);
    cudaGetSymbolAddress((void**)&Vp, g_V);
    cudaGetSymbolAddress((void**)&Op, g_O);
    cudaGetSymbolAddress((void**)&KVPp, g_KVP);

    static bool attr_set = false;
    if (!attr_set) {
        cudaFuncSetAttribute(attn_mma_kernel,
                             cudaFuncAttributeMaxDynamicSharedMemorySize,
                             3 * STAGE_WORDS * 4);
        cudaFuncSetAttribute(gemm_tf32_bias_kernel,
                             cudaFuncAttributeMaxDynamicSharedMemorySize,
                             2 * BUFW * 4);
        attr_set = true;
    }

    const int gemm_smem = 2 * BUFW * 4;
    dim3 gemm_grid(D_MODEL / 128, M / 128);   // (8, 32)
    gemm_tf32_bias_kernel<<<gemm_grid, 256, gemm_smem>>>(x, Wq, bq, Qp, M, D_MODEL, D_MODEL);
    gemm_tf32_bias_kernel<<<gemm_grid, 256, gemm_smem>>>(x, Wk, bk, Kp, M, D_MODEL, D_MODEL);
    gemm_tf32_bias_kernel<<<gemm_grid, 256, gemm_smem>>>(x, Wv, bv, Vp, M, D_MODEL, D_MODEL);

    dim3 pack_grid(NTILES, B * NUM_HEADS);    // (64, 32)
    pack_kv_kernel<<<pack_grid, 512>>>(Kp, Vp, KVPp);

    dim3 attn_grid(SEQ_LEN / 128, B * NUM_HEADS);  // (16, 32)
    attn_mma_kernel<<<attn_grid, 256, 3 * STAGE_WORDS * 4>>>(Qp, KVPp, Op);

    gemm_tf32_bias_kernel<<<gemm_grid, 256, gemm_smem>>>(Op, Wo, bo, out, M, D_MODEL, D_MODEL);
}

// round 6
// speedup vs baseline: 3.2173x; 1.1878x over previous
#include <cuda_runtime.h>
#include <cstdint>

// ---------------------------------------------------------------------------
// Problem constants: x [B=2, S=2048, d=1024], H=16, Dh=64, causal MHA, fp32.
// ---------------------------------------------------------------------------
#define D_MODEL 1024
#define NUM_HEADS 16
#define D_HEAD 64
#define SEQ_LEN 2048
#define BATCH 2
#define M_ROWS (BATCH * SEQ_LEN)   // 4096
#define NTILES (SEQ_LEN / 32)      // 64 key tiles per (b,h)
#define STAGE_WORDS 6144           // 24KB per tile: [Khi 2048][Vhi 2048][Vlo 2048]

// Scratch (alloc-free rule: __device__ globals).
__device__ float g_Q[M_ROWS * D_MODEL];
__device__ float g_K[M_ROWS * D_MODEL];
__device__ float g_V[M_ROWS * D_MODEL];
__device__ float g_O[M_ROWS * D_MODEL];
// Packed K/V, fragment order, SMEM stage image per (bh, tile).
__device__ uint32_t g_KVP[(size_t)BATCH * NUM_HEADS * NTILES * STAGE_WORDS];

__device__ __forceinline__ uint32_t f2tf32(float x) {
    uint32_t r;
    asm("cvt.rna.tf32.f32 %0, %1;" : "=r"(r) : "f"(x));
    return r;
}

__device__ __forceinline__ void mma_tf32(float c[4], const uint32_t a[4],
                                         uint32_t b0, uint32_t b1) {
    asm volatile(
        "mma.sync.aligned.m16n8k8.row.col.f32.tf32.tf32.f32 "
        "{%0,%1,%2,%3}, {%4,%5,%6,%7}, {%8,%9}, {%0,%1,%2,%3};\n"
        : "+f"(c[0]), "+f"(c[1]), "+f"(c[2]), "+f"(c[3])
        : "r"(a[0]), "r"(a[1]), "r"(a[2]), "r"(a[3]), "r"(b0), "r"(b1));
}

// ---------------------------------------------------------------------------
// TF32 GEMM, double-buffered SMEM + register prefetch (unchanged, passing).
// ---------------------------------------------------------------------------
#define GBK 32
#define APAD 4
#define LDA (128 + APAD)
#define LDB (128 + APAD)
#define AOFF (GBK * LDA)
#define BUFW (GBK * LDA + GBK * LDB)

__global__ __launch_bounds__(256) void gemm_tf32_bias_kernel(
    const float* __restrict__ A, const float* __restrict__ B,
    const float* __restrict__ bias, float* __restrict__ C,
    int M, int N, int K)
{
    extern __shared__ __align__(16) uint32_t gsm[];

    const int tid  = threadIdx.x;
    const int lane = tid & 31;
    const int warp = tid >> 5;
    const int wm = (warp & 3) * 32;
    const int wn = (warp >> 2) * 64;
    const int lrow = lane >> 2;
    const int lcol = lane & 3;

    const int block_row = blockIdx.y * 128;
    const int block_col = blockIdx.x * 128;

    float c[2][8][4];
    #pragma unroll
    for (int mi = 0; mi < 2; mi++)
        #pragma unroll
        for (int ni = 0; ni < 8; ni++)
            #pragma unroll
            for (int r = 0; r < 4; r++) c[mi][ni][r] = 0.0f;

    float4 pa[4], pb[4];

    auto ldg_tile = [&](int k0) {
        #pragma unroll
        for (int l = 0; l < 4; l++) {
            int fid = tid + l * 256;
            int r   = fid >> 3;
            int kq  = (fid & 7) * 4;
            pa[l] = *reinterpret_cast<const float4*>(
                A + (size_t)(block_row + r) * K + k0 + kq);
        }
        #pragma unroll
        for (int l = 0; l < 4; l++) {
            int fid = tid + l * 256;
            int kr  = fid >> 5;
            int nq  = (fid & 31) * 4;
            pb[l] = *reinterpret_cast<const float4*>(
                B + (size_t)(k0 + kr) * N + block_col + nq);
        }
    };

    auto sts_tile = [&](int p) {
        uint32_t* buf = gsm + p * BUFW;
        #pragma unroll
        for (int l = 0; l < 4; l++) {
            int fid = tid + l * 256;
            int r   = fid >> 3;
            int kq  = (fid & 7) * 4;
            buf[(kq + 0) * LDA + r] = f2tf32(pa[l].x);
            buf[(kq + 1) * LDA + r] = f2tf32(pa[l].y);
            buf[(kq + 2) * LDA + r] = f2tf32(pa[l].z);
            buf[(kq + 3) * LDA + r] = f2tf32(pa[l].w);
        }
        #pragma unroll
        for (int l = 0; l < 4; l++) {
            int fid = tid + l * 256;
            int kr  = fid >> 5;
            int nq  = (fid & 31) * 4;
            uint32_t* d = buf + AOFF + kr * LDB + nq;
            d[0] = f2tf32(pb[l].x);
            d[1] = f2tf32(pb[l].y);
            d[2] = f2tf32(pb[l].z);
            d[3] = f2tf32(pb[l].w);
        }
    };

    const int T = K / GBK;
    ldg_tile(0);
    sts_tile(0);

    for (int t = 0; t < T; t++) {
        if (t + 1 < T) ldg_tile((t + 1) * GBK);
        __syncthreads();

        const uint32_t* As = gsm + (t & 1) * BUFW;
        const uint32_t* Bs = As + AOFF;

        #pragma unroll
        for (int kk = 0; kk < GBK; kk += 8) {
            uint32_t a[2][4];
            #pragma unroll
            for (int mi = 0; mi < 2; mi++) {
                int m0 = wm + mi * 16;
                a[mi][0] = As[(kk + lcol    ) * LDA + m0 + lrow    ];
                a[mi][1] = As[(kk + lcol    ) * LDA + m0 + 8 + lrow];
                a[mi][2] = As[(kk + lcol + 4) * LDA + m0 + lrow    ];
                a[mi][3] = As[(kk + lcol + 4) * LDA + m0 + 8 + lrow];
            }
            uint32_t b[8][2];
            #pragma unroll
            for (int ni = 0; ni < 8; ni++) {
                int n0 = wn + ni * 8;
                b[ni][0] = Bs[(kk + lcol    ) * LDB + n0 + lrow];
                b[ni][1] = Bs[(kk + lcol + 4) * LDB + n0 + lrow];
            }
            #pragma unroll
            for (int mi = 0; mi < 2; mi++)
                #pragma unroll
                for (int ni = 0; ni < 8; ni++)
                    mma_tf32(c[mi][ni], a[mi], b[ni][0], b[ni][1]);
        }

        if (t + 1 < T) sts_tile((t + 1) & 1);
    }

    #pragma unroll
    for (int mi = 0; mi < 2; mi++) {
        int r0 = block_row + wm + mi * 16 + lrow;
        #pragma unroll
        for (int ni = 0; ni < 8; ni++) {
            int col = block_col + wn + ni * 8 + lcol * 2;
            float b0 = bias[col];
            float b1 = bias[col + 1];
            float2 v0 = make_float2(c[mi][ni][0] + b0, c[mi][ni][1] + b1);
            float2 v1 = make_float2(c[mi][ni][2] + b0, c[mi][ni][3] + b1);
            *reinterpret_cast<float2*>(C + (size_t)r0 * N + col) = v0;
            *reinterpret_cast<float2*>(C + (size_t)(r0 + 8) * N + col) = v1;
        }
    }
}

// ---------------------------------------------------------------------------
// Pack kernel: K (hi only) + V (hi/lo) -> fragment-order stage images.
//   stage: [Khi 2048][Vhi 2048][Vlo 2048]
// ---------------------------------------------------------------------------
__global__ __launch_bounds__(512) void pack_kv_kernel(
    const float* __restrict__ K, const float* __restrict__ V,
    uint32_t* __restrict__ P)
{
    const int kt = blockIdx.x;
    const int bh = blockIdx.y;
    const int b  = bh >> 4;
    const int h  = bh & 15;
    const size_t base = ((size_t)b * SEQ_LEN) * D_MODEL + h * D_HEAD;
    uint32_t* blk = P + ((size_t)bh * NTILES + kt) * STAGE_WORDS;
    const int tid = threadIdx.x;

    if (tid < 256) {
        const int key = tid & 31;
        const int kd  = tid >> 5;
        const float* src = K + base + (size_t)(kt * 32 + key) * D_MODEL + kd * 8;
        float4 v0 = *reinterpret_cast<const float4*>(src);
        float4 v1 = *reinterpret_cast<const float4*>(src + 4);
        float e[8] = {v0.x, v0.y, v0.z, v0.w, v1.x, v1.y, v1.z, v1.w};
        uint32_t hi[8];
        #pragma unroll
        for (int i = 0; i < 8; i++) hi[i] = f2tf32(e[i]);
        const int nt = key >> 3, g = key & 7;
        uint32_t* dhi = blk + (kd * 4 + nt) * 64 + g * 8;
        *reinterpret_cast<uint4*>(dhi)     = make_uint4(hi[0], hi[4], hi[1], hi[5]);
        *reinterpret_cast<uint4*>(dhi + 4) = make_uint4(hi[2], hi[6], hi[3], hi[7]);
    } else {
        const int t2 = tid - 256;
        const int dh = t2 & 63;
        const int kv = t2 >> 6;
        float e[8];
        #pragma unroll
        for (int k = 0; k < 8; k++)
            e[k] = V[base + (size_t)(kt * 32 + kv * 8 + k) * D_MODEL + dh];
        uint32_t hi[8], lo[8];
        #pragma unroll
        for (int i = 0; i < 8; i++) {
            hi[i] = f2tf32(e[i]);
            lo[i] = f2tf32(e[i] - __uint_as_float(hi[i]));
        }
        const int nv = dh >> 3;
        uint32_t* dhi = blk + 2048 + (kv * 8 + nv) * 64 + (dh & 7) * 8;
        uint32_t* dlo = dhi + 2048;
        *reinterpret_cast<uint4*>(dhi)     = make_uint4(hi[0], hi[4], hi[1], hi[5]);
        *reinterpret_cast<uint4*>(dhi + 4) = make_uint4(hi[2], hi[6], hi[3], hi[7]);
        *reinterpret_cast<uint4*>(dlo)     = make_uint4(lo[0], lo[4], lo[1], lo[5]);
        *reinterpret_cast<uint4*>(dlo + 4) = make_uint4(lo[2], lo[6], lo[3], lo[7]);
    }
}

// ---------------------------------------------------------------------------
// Tensor-core flash attention, 3-stage cp.async pipeline.
// QK^T: 1xTF32 (softmax differential-error analysis: ~3e-4 contribution).
// PV:   2xTF32 (ph*Vhi + ph*Vlo).
// ---------------------------------------------------------------------------
__global__ __launch_bounds__(256, 2) void attn_mma_kernel(
    const float* __restrict__ Q, const uint32_t* __restrict__ KVP,
    float* __restrict__ O)
{
    extern __shared__ __align__(16) uint32_t sm[];

    const int qt   = (int)gridDim.x - 1 - (int)blockIdx.x;  // heavy first
    const int bh   = blockIdx.y;
    const int b    = bh >> 4;
    const int h    = bh & 15;
    const int tid  = threadIdx.x;
    const int lane = tid & 31;
    const int warp = tid >> 5;
    const int g    = lane >> 2;
    const int t    = lane & 3;

    const int wq0 = qt * 128 + warp * 16;
    const size_t base = ((size_t)b * SEQ_LEN) * D_MODEL + h * D_HEAD;
    const uint32_t* tile_base = KVP + (size_t)bh * NTILES * STAGE_WORDS;
    const uint32_t sm_addr = (uint32_t)__cvta_generic_to_shared(sm);
    const int nkt = 4 * qt + 4;

    // Q fragments, converted to tf32 once (single-precision QK path).
    uint32_t qh[8][4];
    {
        const int row0 = wq0 + g, row1 = row0 + 8;
        #pragma unroll
        for (int kd = 0; kd < 8; kd++) {
            int c0 = kd * 8 + t, c1 = c0 + 4;
            qh[kd][0] = f2tf32(Q[base + (size_t)row0 * D_MODEL + c0] * 0.125f);
            qh[kd][1] = f2tf32(Q[base + (size_t)row1 * D_MODEL + c0] * 0.125f);
            qh[kd][2] = f2tf32(Q[base + (size_t)row0 * D_MODEL + c1] * 0.125f);
            qh[kd][3] = f2tf32(Q[base + (size_t)row1 * D_MODEL + c1] * 0.125f);
        }
    }

    float oc[8][4];
    #pragma unroll
    for (int nv = 0; nv < 8; nv++)
        #pragma unroll
        for (int r = 0; r < 4; r++) oc[nv][r] = 0.0f;

    float m0 = -1.0e30f, m1 = -1.0e30f;
    float l0 = 0.0f, l1 = 0.0f;

    // 24KB linear copy per tile: 6 x (256 threads x 16B).
    auto issue_tile = [&](int kt) {
        if (kt < nkt) {
            const uint32_t* src = tile_base + (size_t)kt * STAGE_WORDS + tid * 4;
            uint32_t dst = sm_addr + ((kt % 3) * STAGE_WORDS + tid * 4) * 4;
            #pragma unroll
            for (int c = 0; c < 6; c++) {
                asm volatile("cp.async.cg.shared.global [%0], [%1], 16;\n"
                             :: "r"(dst + c * 4096), "l"(src + c * 1024));
            }
        }
        asm volatile("cp.async.commit_group;\n");
    };

    issue_tile(0);
    issue_tile(1);

    for (int kt = 0; kt < nkt; kt++) {
        asm volatile("cp.async.wait_group 1;\n");
        __syncthreads();

        const uint2* KhiS = reinterpret_cast<const uint2*>(sm + (kt % 3) * STAGE_WORDS);
        const uint2* VhiS = KhiS + 1024;
        const uint2* VloS = KhiS + 2048;
        const int k0 = kt * 32;

        if (k0 <= wq0 + 15) {
            // ---- S = QK^T (1xtf32) ----
            float sc[4][4];
            #pragma unroll
            for (int nt = 0; nt < 4; nt++)
                #pragma unroll
                for (int r = 0; r < 4; r++) sc[nt][r] = 0.0f;

            #pragma unroll
            for (int kd = 0; kd < 8; kd++) {
                #pragma unroll
                for (int nt = 0; nt < 4; nt++) {
                    uint2 bh2 = KhiS[(kd * 4 + nt) * 32 + lane];
                    mma_tf32(sc[nt], qh[kd], bh2.x, bh2.y);
                }
            }

            const int row0 = wq0 + g, row1 = row0 + 8;

            if (k0 + 31 > wq0) {
                #pragma unroll
                for (int nt = 0; nt < 4; nt++) {
                    int col = k0 + nt * 8 + 2 * t;
                    if (col     > row0) sc[nt][0] = -1.0e30f;
                    if (col + 1 > row0) sc[nt][1] = -1.0e30f;
                    if (col     > row1) sc[nt][2] = -1.0e30f;
                    if (col + 1 > row1) sc[nt][3] = -1.0e30f;
                }
            }

            // ---- online softmax ----
            float mt0 = sc[0][0], mt1 = sc[0][2];
            #pragma unroll
            for (int nt = 0; nt < 4; nt++) {
                mt0 = fmaxf(mt0, fmaxf(sc[nt][0], sc[nt][1]));
                mt1 = fmaxf(mt1, fmaxf(sc[nt][2], sc[nt][3]));
            }
            #pragma unroll
            for (int w = 1; w < 4; w <<= 1) {
                mt0 = fmaxf(mt0, __shfl_xor_sync(0xffffffff, mt0, w));
                mt1 = fmaxf(mt1, __shfl_xor_sync(0xffffffff, mt1, w));
            }
            float mn0 = fmaxf(m0, mt0), mn1 = fmaxf(m1, mt1);
            float cr0 = __expf(m0 - mn0), cr1 = __expf(m1 - mn1);
            m0 = mn0; m1 = mn1;
            l0 *= cr0; l1 *= cr1;
            #pragma unroll
            for (int nv = 0; nv < 8; nv++) {
                oc[nv][0] *= cr0; oc[nv][1] *= cr0;
                oc[nv][2] *= cr1; oc[nv][3] *= cr1;
            }

            float ps[4][4];
            #pragma unroll
            for (int nt = 0; nt < 4; nt++) {
                ps[nt][0] = __expf(sc[nt][0] - m0);
                ps[nt][1] = __expf(sc[nt][1] - m0);
                ps[nt][2] = __expf(sc[nt][2] - m1);
                ps[nt][3] = __expf(sc[nt][3] - m1);
                l0 += ps[nt][0] + ps[nt][1];
                l1 += ps[nt][2] + ps[nt][3];
            }

            // ---- O += P V (2xtf32); C-layout -> A-layout via shfl ----
            const int src0 = (lane & ~3) | (t >> 1);
            const int src1 = src0 + 2;
            const bool odd = (t & 1);
            #pragma unroll
            for (int kv = 0; kv < 4; kv++) {
                float a0f, a1f, a2f, a3f;
                {
                    float t00 = __shfl_sync(0xffffffff, ps[kv][0], src0);
                    float t01 = __shfl_sync(0xffffffff, ps[kv][1], src0);
                    a0f = odd ? t01 : t00;
                    float t10 = __shfl_sync(0xffffffff, ps[kv][2], src0);
                    float t11 = __shfl_sync(0xffffffff, ps[kv][3], src0);
                    a1f = odd ? t11 : t10;
                    float t20 = __shfl_sync(0xffffffff, ps[kv][0], src1);
                    float t21 = __shfl_sync(0xffffffff, ps[kv][1], src1);
                    a2f = odd ? t21 : t20;
                    float t30 = __shfl_sync(0xffffffff, ps[kv][2], src1);
                    float t31 = __shfl_sync(0xffffffff, ps[kv][3], src1);
                    a3f = odd ? t31 : t30;
                }
                uint32_t ph[4];
                ph[0] = f2tf32(a0f);
                ph[1] = f2tf32(a1f);
                ph[2] = f2tf32(a2f);
                ph[3] = f2tf32(a3f);

                #pragma unroll
                for (int nv = 0; nv < 8; nv++) {
                    uint2 vh2 = VhiS[(kv * 8 + nv) * 32 + lane];
                    uint2 vl2 = VloS[(kv * 8 + nv) * 32 + lane];
                    mma_tf32(oc[nv], ph, vh2.x, vh2.y);
                    mma_tf32(oc[nv], ph, vl2.x, vl2.y);
                }
            }
        }

        issue_tile(kt + 2);
    }

    // ---- finalize ----
    #pragma unroll
    for (int w = 1; w < 4; w <<= 1) {
        l0 += __shfl_xor_sync(0xffffffff, l0, w);
        l1 += __shfl_xor_sync(0xffffffff, l1, w);
    }
    const float inv0 = 1.0f / l0, inv1 = 1.0f / l1;
    const int row0 = wq0 + g, row1 = row0 + 8;
    #pragma unroll
    for (int nv = 0; nv < 8; nv++) {
        int col = nv * 8 + 2 * t;
        *reinterpret_cast<float2*>(O + base + (size_t)row0 * D_MODEL + col) =
            make_float2(oc[nv][0] * inv0, oc[nv][1] * inv0);
        *reinterpret_cast<float2*>(O + base + (size_t)row1 * D_MODEL + col) =
            make_float2(oc[nv][2] * inv1, oc[nv][3] * inv1);
    }
}

// ---------------------------------------------------------------------------
// Launch: QKV projections -> pack -> attention -> output projection.
// ---------------------------------------------------------------------------
extern "C" void kernel_launch(void* const* d_in, const int* in_sizes, int n_in,
                              void* d_out, int out_size)
{
    const float* x  = (const float*)d_in[0];
    const float* Wq = (const float*)d_in[1];
    const float* bq = (const float*)d_in[2];
    const float* Wk = (const float*)d_in[3];
    const float* bk = (const float*)d_in[4];
    const float* Wv = (const float*)d_in[5];
    const float* bv = (const float*)d_in[6];
    const float* Wo = (const float*)d_in[7];
    const float* bo = (const float*)d_in[8];
    float* out = (float*)d_out;

    const int M = in_sizes[0] / D_MODEL;   // 4096
    const int B = M / SEQ_LEN;             // 2

    float *Qp, *Kp, *Vp, *Op;
    uint32_t* KVPp;
    cudaGetSymbolAddress((void**)&Qp, g_Q);
    cudaGetSymbolAddress((void**)&Kp, g_K);
    cudaGetSymbolAddress((void**)&Vp, g_V);
    cudaGetSymbolAddress((void**)&Op, g_O);
    cudaGetSymbolAddress((void**)&KVPp, g_KVP);

    static bool attr_set = false;
    if (!attr_set) {
        cudaFuncSetAttribute(attn_mma_kernel,
                             cudaFuncAttributeMaxDynamicSharedMemorySize,
                             3 * STAGE_WORDS * 4);
        cudaFuncSetAttribute(gemm_tf32_bias_kernel,
                             cudaFuncAttributeMaxDynamicSharedMemorySize,
                             2 * BUFW * 4);
        attr_set = true;
    }

    const int gemm_smem = 2 * BUFW * 4;
    dim3 gemm_grid(D_MODEL / 128, M / 128);   // (8, 32)
    gemm_tf32_bias_kernel<<<gemm_grid, 256, gemm_smem>>>(x, Wq, bq, Qp, M, D_MODEL, D_MODEL);
    gemm_tf32_bias_kernel<<<gemm_grid, 256, gemm_smem>>>(x, Wk, bk, Kp, M, D_MODEL, D_MODEL);
    gemm_tf32_bias_kernel<<<gemm_grid, 256, gemm_smem>>>(x, Wv, bv, Vp, M, D_MODEL, D_MODEL);

    dim3 pack_grid(NTILES, B * NUM_HEADS);    // (64, 32)
    pack_kv_kernel<<<pack_grid, 512>>>(Kp, Vp, KVPp);

    dim3 attn_grid(SEQ_LEN / 128, B * NUM_HEADS);  // (16, 32)
    attn_mma_kernel<<<attn_grid, 256, 3 * STAGE_WORDS * 4>>>(Qp, KVPp, Op);

    gemm_tf32_bias_kernel<<<gemm_grid, 256, gemm_smem>>>(Op, Wo, bo, out, M, D_MODEL, D_MODEL);
}

// round 8
// speedup vs baseline: 4.1076x; 1.2767x over previous
#include <cuda_runtime.h>
#include <cstdint>

// ---------------------------------------------------------------------------
// Problem constants: x [B=2, S=2048, d=1024], H=16, Dh=64, causal MHA, fp32.
// ---------------------------------------------------------------------------
#define D_MODEL 1024
#define NUM_HEADS 16
#define D_HEAD 64
#define SEQ_LEN 2048
#define BATCH 2
#define M_ROWS (BATCH * SEQ_LEN)   // 4096
#define NTILES (SEQ_LEN / 32)      // 64 key tiles per (b,h)
#define STAGE_WORDS 4096           // 16KB per tile: [Khi 2048][Vhi 2048]

// Scratch (alloc-free rule: __device__ globals).
__device__ float    g_Q[M_ROWS * D_MODEL];
__device__ float    g_K[M_ROWS * D_MODEL];
__device__ float    g_V[M_ROWS * D_MODEL];
__device__ float    g_O[M_ROWS * D_MODEL];
__device__ uint32_t g_AT[M_ROWS * D_MODEL];          // tf32 A^T [K][M] (x, then attn-out)
__device__ uint32_t g_W4[4 * D_MODEL * D_MODEL];     // tf32-rounded Wq,Wk,Wv,Wo
__device__ uint32_t g_KVP[(size_t)BATCH * NUM_HEADS * NTILES * STAGE_WORDS];

__device__ __forceinline__ uint32_t f2tf32(float x) {
    uint32_t r;
    asm("cvt.rna.tf32.f32 %0, %1;" : "=r"(r) : "f"(x));
    return r;
}

__device__ __forceinline__ void mma_tf32(float c[4], const uint32_t a[4],
                                         uint32_t b0, uint32_t b1) {
    asm volatile(
        "mma.sync.aligned.m16n8k8.row.col.f32.tf32.tf32.f32 "
        "{%0,%1,%2,%3}, {%4,%5,%6,%7}, {%8,%9}, {%0,%1,%2,%3};\n"
        : "+f"(c[0]), "+f"(c[1]), "+f"(c[2]), "+f"(c[3])
        : "r"(a[0]), "r"(a[1]), "r"(a[2]), "r"(a[3]), "r"(b0), "r"(b1));
}

// ---------------------------------------------------------------------------
// Pre-pass 1: transpose + tf32-round. in [R][C] fp32 -> out [C][R] tf32 bits.
// ---------------------------------------------------------------------------
__global__ __launch_bounds__(256) void transpose_round_kernel(
    const float* __restrict__ in, uint32_t* __restrict__ out, int R, int C)
{
    __shared__ float tile[32][33];
    const int bc = blockIdx.x * 32;   // column (out-row) base
    const int br = blockIdx.y * 32;   // row (out-col) base
    const int tx = threadIdx.x & 31;
    const int ty = threadIdx.x >> 5;  // 0..7
    #pragma unroll
    for (int i = 0; i < 32; i += 8)
        tile[ty + i][tx] = in[(size_t)(br + ty + i) * C + bc + tx];
    __syncthreads();
    #pragma unroll
    for (int i = 0; i < 32; i += 8)
        out[(size_t)(bc + ty + i) * R + br + tx] = f2tf32(tile[tx][ty + i]);
}

// Pre-pass 2: elementwise tf32-round of the 4 weight matrices.
__global__ __launch_bounds__(256) void round_weights_kernel(
    const float* __restrict__ w0, const float* __restrict__ w1,
    const float* __restrict__ w2, const float* __restrict__ w3,
    uint32_t* __restrict__ out)
{
    const float* srcs[4] = {w0, w1, w2, w3};
    const int m = blockIdx.y;
    const size_t idx = (size_t)blockIdx.x * 256 + threadIdx.x;
    float4 v = reinterpret_cast<const float4*>(srcs[m])[idx];
    uint4 r = make_uint4(f2tf32(v.x), f2tf32(v.y), f2tf32(v.z), f2tf32(v.w));
    reinterpret_cast<uint4*>(out + (size_t)m * D_MODEL * D_MODEL)[idx] = r;
}

// ---------------------------------------------------------------------------
// TF32 GEMM over pre-rounded inputs: C[M,N] = A^T-stored(A) @ B + bias.
//   A: [K][M] tf32 bits (pre-transposed+rounded), B: [K][N] tf32 bits.
// Pure cp.async 3-stage pipeline; no conversion in-kernel.
// CTA 128x128, BK=32, 8 warps; warp tile 32x64 via mma.sync.m16n8k8.
// ---------------------------------------------------------------------------
#define GBK 32
#define LDT 132                       // padded row (128+4)
#define AOFF (GBK * LDT)              // Bs offset inside a stage (4224 words)
#define BUFW (2 * GBK * LDT)          // words per stage (8448)

__global__ __launch_bounds__(256) void gemm_tf32_bias_kernel(
    const uint32_t* __restrict__ A, const uint32_t* __restrict__ B,
    const float* __restrict__ bias, float* __restrict__ C,
    int M, int N, int K)
{
    extern __shared__ __align__(16) uint32_t gsm[];

    const int tid  = threadIdx.x;
    const int lane = tid & 31;
    const int warp = tid >> 5;
    const int wm = (warp & 3) * 32;
    const int wn = (warp >> 2) * 64;
    const int lrow = lane >> 2;
    const int lcol = lane & 3;

    const int block_row = blockIdx.y * 128;
    const int block_col = blockIdx.x * 128;

    const uint32_t sm_addr = (uint32_t)__cvta_generic_to_shared(gsm);
    const int T = K / GBK;

    // Per-thread copy coords: row = fid>>5 (0..31), chunk = fid&31 (16B units).
    auto issue_stage = [&](int t) {
        if (t < T) {
            const int k0 = t * GBK;
            uint32_t dst0 = sm_addr + ((t % 3) * BUFW) * 4;
            #pragma unroll
            for (int l = 0; l < 4; l++) {
                int fid = tid + l * 256;
                int row = fid >> 5, ch = fid & 31;
                const uint32_t* srcA = A + (size_t)(k0 + row) * M + block_row + ch * 4;
                uint32_t dA = dst0 + (row * LDT + ch * 4) * 4;
                asm volatile("cp.async.cg.shared.global [%0], [%1], 16;\n"
                             :: "r"(dA), "l"(srcA));
            }
            #pragma unroll
            for (int l = 0; l < 4; l++) {
                int fid = tid + l * 256;
                int row = fid >> 5, ch = fid & 31;
                const uint32_t* srcB = B + (size_t)(k0 + row) * N + block_col + ch * 4;
                uint32_t dB = dst0 + (AOFF + row * LDT + ch * 4) * 4;
                asm volatile("cp.async.cg.shared.global [%0], [%1], 16;\n"
                             :: "r"(dB), "l"(srcB));
            }
        }
        asm volatile("cp.async.commit_group;\n");
    };

    float c[2][8][4];
    #pragma unroll
    for (int mi = 0; mi < 2; mi++)
        #pragma unroll
        for (int ni = 0; ni < 8; ni++)
            #pragma unroll
            for (int r = 0; r < 4; r++) c[mi][ni][r] = 0.0f;

    issue_stage(0);
    issue_stage(1);

    for (int t = 0; t < T; t++) {
        asm volatile("cp.async.wait_group 1;\n");
        __syncthreads();

        const uint32_t* As = gsm + (t % 3) * BUFW;
        const uint32_t* Bs = As + AOFF;

        #pragma unroll
        for (int kk = 0; kk < GBK; kk += 8) {
            uint32_t a[2][4];
            #pragma unroll
            for (int mi = 0; mi < 2; mi++) {
                int m0 = wm + mi * 16;
                a[mi][0] = As[(kk + lcol    ) * LDT + m0 + lrow    ];
                a[mi][1] = As[(kk + lcol    ) * LDT + m0 + 8 + lrow];
                a[mi][2] = As[(kk + lcol + 4) * LDT + m0 + lrow    ];
                a[mi][3] = As[(kk + lcol + 4) * LDT + m0 + 8 + lrow];
            }
            uint32_t b[8][2];
            #pragma unroll
            for (int ni = 0; ni < 8; ni++) {
                int n0 = wn + ni * 8;
                b[ni][0] = Bs[(kk + lcol    ) * LDT + n0 + lrow];
                b[ni][1] = Bs[(kk + lcol + 4) * LDT + n0 + lrow];
            }
            #pragma unroll
            for (int mi = 0; mi < 2; mi++)
                #pragma unroll
                for (int ni = 0; ni < 8; ni++)
                    mma_tf32(c[mi][ni], a[mi], b[ni][0], b[ni][1]);
        }

        issue_stage(t + 2);
    }

    #pragma unroll
    for (int mi = 0; mi < 2; mi++) {
        int r0 = block_row + wm + mi * 16 + lrow;
        #pragma unroll
        for (int ni = 0; ni < 8; ni++) {
            int col = block_col + wn + ni * 8 + lcol * 2;
            float b0 = bias[col];
            float b1 = bias[col + 1];
            float2 v0 = make_float2(c[mi][ni][0] + b0, c[mi][ni][1] + b1);
            float2 v1 = make_float2(c[mi][ni][2] + b0, c[mi][ni][3] + b1);
            *reinterpret_cast<float2*>(C + (size_t)r0 * N + col) = v0;
            *reinterpret_cast<float2*>(C + (size_t)(r0 + 8) * N + col) = v1;
        }
    }
}

// ---------------------------------------------------------------------------
// Pack kernel: K,V -> tf32 (hi only) fragment-order stage images.
//   stage: [Khi 2048][Vhi 2048]
// ---------------------------------------------------------------------------
__global__ __launch_bounds__(512) void pack_kv_kernel(
    const float* __restrict__ K, const float* __restrict__ V,
    uint32_t* __restrict__ P)
{
    const int kt = blockIdx.x;
    const int bh = blockIdx.y;
    const int b  = bh >> 4;
    const int h  = bh & 15;
    const size_t base = ((size_t)b * SEQ_LEN) * D_MODEL + h * D_HEAD;
    uint32_t* blk = P + ((size_t)bh * NTILES + kt) * STAGE_WORDS;
    const int tid = threadIdx.x;

    if (tid < 256) {
        const int key = tid & 31;
        const int kd  = tid >> 5;
        const float* src = K + base + (size_t)(kt * 32 + key) * D_MODEL + kd * 8;
        float4 v0 = *reinterpret_cast<const float4*>(src);
        float4 v1 = *reinterpret_cast<const float4*>(src + 4);
        float e[8] = {v0.x, v0.y, v0.z, v0.w, v1.x, v1.y, v1.z, v1.w};
        uint32_t hi[8];
        #pragma unroll
        for (int i = 0; i < 8; i++) hi[i] = f2tf32(e[i]);
        const int nt = key >> 3, g = key & 7;
        uint32_t* dhi = blk + (kd * 4 + nt) * 64 + g * 8;
        *reinterpret_cast<uint4*>(dhi)     = make_uint4(hi[0], hi[4], hi[1], hi[5]);
        *reinterpret_cast<uint4*>(dhi + 4) = make_uint4(hi[2], hi[6], hi[3], hi[7]);
    } else {
        const int t2 = tid - 256;
        const int dh = t2 & 63;
        const int kv = t2 >> 6;
        float e[8];
        #pragma unroll
        for (int k = 0; k < 8; k++)
            e[k] = V[base + (size_t)(kt * 32 + kv * 8 + k) * D_MODEL + dh];
        uint32_t hi[8];
        #pragma unroll
        for (int i = 0; i < 8; i++) hi[i] = f2tf32(e[i]);
        const int nv = dh >> 3;
        uint32_t* dhi = blk + 2048 + (kv * 8 + nv) * 64 + (dh & 7) * 8;
        *reinterpret_cast<uint4*>(dhi)     = make_uint4(hi[0], hi[4], hi[1], hi[5]);
        *reinterpret_cast<uint4*>(dhi + 4) = make_uint4(hi[2], hi[6], hi[3], hi[7]);
    }
}

// ---------------------------------------------------------------------------
// Tensor-core flash attention, 3-stage cp.async pipeline.
// QK^T: 1xTF32. PV: 1xTF32 (V rounding unbiased; error in quadrature budget).
// ---------------------------------------------------------------------------
__global__ __launch_bounds__(256, 2) void attn_mma_kernel(
    const float* __restrict__ Q, const uint32_t* __restrict__ KVP,
    float* __restrict__ O)
{
    extern __shared__ __align__(16) uint32_t sm[];

    const int qt   = (int)gridDim.x - 1 - (int)blockIdx.x;  // heavy first
    const int bh   = blockIdx.y;
    const int b    = bh >> 4;
    const int h    = bh & 15;
    const int tid  = threadIdx.x;
    const int lane = tid & 31;
    const int warp = tid >> 5;
    const int g    = lane >> 2;
    const int t    = lane & 3;

    const int wq0 = qt * 128 + warp * 16;
    const size_t base = ((size_t)b * SEQ_LEN) * D_MODEL + h * D_HEAD;
    const uint32_t* tile_base = KVP + (size_t)bh * NTILES * STAGE_WORDS;
    const uint32_t sm_addr = (uint32_t)__cvta_generic_to_shared(sm);
    const int nkt = 4 * qt + 4;

    uint32_t qh[8][4];
    {
        const int row0 = wq0 + g, row1 = row0 + 8;
        #pragma unroll
        for (int kd = 0; kd < 8; kd++) {
            int c0 = kd * 8 + t, c1 = c0 + 4;
            qh[kd][0] = f2tf32(Q[base + (size_t)row0 * D_MODEL + c0] * 0.125f);
            qh[kd][1] = f2tf32(Q[base + (size_t)row1 * D_MODEL + c0] * 0.125f);
            qh[kd][2] = f2tf32(Q[base + (size_t)row0 * D_MODEL + c1] * 0.125f);
            qh[kd][3] = f2tf32(Q[base + (size_t)row1 * D_MODEL + c1] * 0.125f);
        }
    }

    float oc[8][4];
    #pragma unroll
    for (int nv = 0; nv < 8; nv++)
        #pragma unroll
        for (int r = 0; r < 4; r++) oc[nv][r] = 0.0f;

    float m0 = -1.0e30f, m1 = -1.0e30f;
    float l0 = 0.0f, l1 = 0.0f;

    // 16KB linear copy per tile: 4 x (256 threads x 16B).
    auto issue_tile = [&](int kt) {
        if (kt < nkt) {
            const uint32_t* src = tile_base + (size_t)kt * STAGE_WORDS + tid * 4;
            uint32_t dst = sm_addr + ((kt % 3) * STAGE_WORDS + tid * 4) * 4;
            #pragma unroll
            for (int c = 0; c < 4; c++) {
                asm volatile("cp.async.cg.shared.global [%0], [%1], 16;\n"
                             :: "r"(dst + c * 4096), "l"(src + c * 1024));
            }
        }
        asm volatile("cp.async.commit_group;\n");
    };

    issue_tile(0);
    issue_tile(1);

    for (int kt = 0; kt < nkt; kt++) {
        asm volatile("cp.async.wait_group 1;\n");
        __syncthreads();

        const uint2* KhiS = reinterpret_cast<const uint2*>(sm + (kt % 3) * STAGE_WORDS);
        const uint2* VhiS = KhiS + 1024;
        const int k0 = kt * 32;

        if (k0 <= wq0 + 15) {
            // ---- S = QK^T (1xtf32) ----
            float sc[4][4];
            #pragma unroll
            for (int nt = 0; nt < 4; nt++)
                #pragma unroll
                for (int r = 0; r < 4; r++) sc[nt][r] = 0.0f;

            #pragma unroll
            for (int kd = 0; kd < 8; kd++) {
                #pragma unroll
                for (int nt = 0; nt < 4; nt++) {
                    uint2 bh2 = KhiS[(kd * 4 + nt) * 32 + lane];
                    mma_tf32(sc[nt], qh[kd], bh2.x, bh2.y);
                }
            }

            const int row0 = wq0 + g, row1 = row0 + 8;

            if (k0 + 31 > wq0) {
                #pragma unroll
                for (int nt = 0; nt < 4; nt++) {
                    int col = k0 + nt * 8 + 2 * t;
                    if (col     > row0) sc[nt][0] = -1.0e30f;
                    if (col + 1 > row0) sc[nt][1] = -1.0e30f;
                    if (col     > row1) sc[nt][2] = -1.0e30f;
                    if (col + 1 > row1) sc[nt][3] = -1.0e30f;
                }
            }

            // ---- online softmax ----
            float mt0 = sc[0][0], mt1 = sc[0][2];
            #pragma unroll
            for (int nt = 0; nt < 4; nt++) {
                mt0 = fmaxf(mt0, fmaxf(sc[nt][0], sc[nt][1]));
                mt1 = fmaxf(mt1, fmaxf(sc[nt][2], sc[nt][3]));
            }
            #pragma unroll
            for (int w = 1; w < 4; w <<= 1) {
                mt0 = fmaxf(mt0, __shfl_xor_sync(0xffffffff, mt0, w));
                mt1 = fmaxf(mt1, __shfl_xor_sync(0xffffffff, mt1, w));
            }
            float mn0 = fmaxf(m0, mt0), mn1 = fmaxf(m1, mt1);
            float cr0 = __expf(m0 - mn0), cr1 = __expf(m1 - mn1);
            m0 = mn0; m1 = mn1;
            l0 *= cr0; l1 *= cr1;
            #pragma unroll
            for (int nv = 0; nv < 8; nv++) {
                oc[nv][0] *= cr0; oc[nv][1] *= cr0;
                oc[nv][2] *= cr1; oc[nv][3] *= cr1;
            }

            float ps[4][4];
            #pragma unroll
            for (int nt = 0; nt < 4; nt++) {
                ps[nt][0] = __expf(sc[nt][0] - m0);
                ps[nt][1] = __expf(sc[nt][1] - m0);
                ps[nt][2] = __expf(sc[nt][2] - m1);
                ps[nt][3] = __expf(sc[nt][3] - m1);
                l0 += ps[nt][0] + ps[nt][1];
                l1 += ps[nt][2] + ps[nt][3];
            }

            // ---- O += P V (1xtf32); C-layout -> A-layout via shfl ----
            const int src0 = (lane & ~3) | (t >> 1);
            const int src1 = src0 + 2;
            const bool odd = (t & 1);
            #pragma unroll
            for (int kv = 0; kv < 4; kv++) {
                float a0f, a1f, a2f, a3f;
                {
                    float t00 = __shfl_sync(0xffffffff, ps[kv][0], src0);
                    float t01 = __shfl_sync(0xffffffff, ps[kv][1], src0);
                    a0f = odd ? t01 : t00;
                    float t10 = __shfl_sync(0xffffffff, ps[kv][2], src0);
                    float t11 = __shfl_sync(0xffffffff, ps[kv][3], src0);
                    a1f = odd ? t11 : t10;
                    float t20 = __shfl_sync(0xffffffff, ps[kv][0], src1);
                    float t21 = __shfl_sync(0xffffffff, ps[kv][1], src1);
                    a2f = odd ? t21 : t20;
                    float t30 = __shfl_sync(0xffffffff, ps[kv][2], src1);
                    float t31 = __shfl_sync(0xffffffff, ps[kv][3], src1);
                    a3f = odd ? t31 : t30;
                }
                uint32_t ph[4];
                ph[0] = f2tf32(a0f);
                ph[1] = f2tf32(a1f);
                ph[2] = f2tf32(a2f);
                ph[3] = f2tf32(a3f);

                #pragma unroll
                for (int nv = 0; nv < 8; nv++) {
                    uint2 vh2 = VhiS[(kv * 8 + nv) * 32 + lane];
                    mma_tf32(oc[nv], ph, vh2.x, vh2.y);
                }
            }
        }

        issue_tile(kt + 2);
    }

    // ---- finalize ----
    #pragma unroll
    for (int w = 1; w < 4; w <<= 1) {
        l0 += __shfl_xor_sync(0xffffffff, l0, w);
        l1 += __shfl_xor_sync(0xffffffff, l1, w);
    }
    const float inv0 = 1.0f / l0, inv1 = 1.0f / l1;
    const int row0 = wq0 + g, row1 = row0 + 8;
    #pragma unroll
    for (int nv = 0; nv < 8; nv++) {
        int col = nv * 8 + 2 * t;
        *reinterpret_cast<float2*>(O + base + (size_t)row0 * D_MODEL + col) =
            make_float2(oc[nv][0] * inv0, oc[nv][1] * inv0);
        *reinterpret_cast<float2*>(O + base + (size_t)row1 * D_MODEL + col) =
            make_float2(oc[nv][2] * inv1, oc[nv][3] * inv1);
    }
}

// ---------------------------------------------------------------------------
// Launch: round/transpose pre-pass -> QKV GEMMs -> pack -> attn -> out GEMM.
// ---------------------------------------------------------------------------
extern "C" void kernel_launch(void* const* d_in, const int* in_sizes, int n_in,
                              void* d_out, int out_size)
{
    const float* x  = (const float*)d_in[0];
    const float* Wq = (const float*)d_in[1];
    const float* bq = (const float*)d_in[2];
    const float* Wk = (const float*)d_in[3];
    const float* bk = (const float*)d_in[4];
    const float* Wv = (const float*)d_in[5];
    const float* bv = (const float*)d_in[6];
    const float* Wo = (const float*)d_in[7];
    const float* bo = (const float*)d_in[8];
    float* out = (float*)d_out;

    const int M = in_sizes[0] / D_MODEL;   // 4096
    const int B = M / SEQ_LEN;             // 2

    float *Qp, *Kp, *Vp, *Op;
    uint32_t *ATp, *W4p, *KVPp;
    cudaGetSymbolAddress((void**)&Qp, g_Q);
    cudaGetSymbolAddress((void**)&Kp, g_K);
    cudaGetSymbolAddress((void**)&Vp, g_V);
    cudaGetSymbolAddress((void**)&Op, g_O);
    cudaGetSymbolAddress((void**)&ATp, g_AT);
    cudaGetSymbolAddress((void**)&W4p, g_W4);
    cudaGetSymbolAddress((void**)&KVPp, g_KVP);

    static bool attr_set = false;
    if (!attr_set) {
        cudaFuncSetAttribute(attn_mma_kernel,
                             cudaFuncAttributeMaxDynamicSharedMemorySize,
                             3 * STAGE_WORDS * 4);
        cudaFuncSetAttribute(gemm_tf32_bias_kernel,
                             cudaFuncAttributeMaxDynamicSharedMemorySize,
                             3 * BUFW * 4);
        attr_set = true;
    }

    const int gemm_smem = 3 * BUFW * 4;   // 101376 B
    dim3 gemm_grid(D_MODEL / 128, M / 128);      // (8, 32)
    dim3 tr_grid(D_MODEL / 32, M / 32);          // (32, 128): [M][D] -> [D][M]

    // Pre-pass: xT (tf32) + rounded weights.
    transpose_round_kernel<<<tr_grid, 256>>>(x, ATp, M, D_MODEL);
    round_weights_kernel<<<dim3(D_MODEL * D_MODEL / 1024, 4), 256>>>(Wq, Wk, Wv, Wo, W4p);

    // QKV projections.
    gemm_tf32_bias_kernel<<<gemm_grid, 256, gemm_smem>>>(ATp, W4p + 0 * D_MODEL * D_MODEL, bq, Qp, M, D_MODEL, D_MODEL);
    gemm_tf32_bias_kernel<<<gemm_grid, 256, gemm_smem>>>(ATp, W4p + 1 * D_MODEL * D_MODEL, bk, Kp, M, D_MODEL, D_MODEL);
    gemm_tf32_bias_kernel<<<gemm_grid, 256, gemm_smem>>>(ATp, W4p + 2 * D_MODEL * D_MODEL, bv, Vp, M, D_MODEL, D_MODEL);

    // Pack K/V to fragment order.
    dim3 pack_grid(NTILES, B * NUM_HEADS);       // (64, 32)
    pack_kv_kernel<<<pack_grid, 512>>>(Kp, Vp, KVPp);

    // Attention.
    dim3 attn_grid(SEQ_LEN / 128, B * NUM_HEADS);  // (16, 32)
    attn_mma_kernel<<<attn_grid, 256, 3 * STAGE_WORDS * 4>>>(Qp, KVPp, Op);

    // Output projection (reuse g_AT for transposed attn output).
    transpose_round_kernel<<<tr_grid, 256>>>(Op, ATp, M, D_MODEL);
    gemm_tf32_bias_kernel<<<gemm_grid, 256, gemm_smem>>>(ATp, W4p + 3 * D_MODEL * D_MODEL, bo, out, M, D_MODEL, D_MODEL);
}

// round 9
// speedup vs baseline: 5.2658x; 1.2820x over previous
#include <cuda_runtime.h>
#include <cstdint>

// ---------------------------------------------------------------------------
// Problem constants: x [B=2, S=2048, d=1024], H=16, Dh=64, causal MHA, fp32.
// ---------------------------------------------------------------------------
#define D_MODEL 1024
#define NUM_HEADS 16
#define D_HEAD 64
#define SEQ_LEN 2048
#define BATCH 2
#define M_ROWS (BATCH * SEQ_LEN)   // 4096
#define NTILES (SEQ_LEN / 32)      // 64 key tiles per (b,h)
#define STAGE_WORDS 4096           // attn: 16KB per tile [Khi 2048][Vhi 2048]
#define GW 8192                    // gemm stage words: [A 4096][B 4096] = 32KB
#define KT_N 32                    // k-tiles per GEMM (K=1024 / 32)

// Scratch (alloc-free rule: __device__ globals).
__device__ float    g_Q[M_ROWS * D_MODEL];
__device__ float    g_K[M_ROWS * D_MODEL];
__device__ float    g_V[M_ROWS * D_MODEL];
__device__ float    g_O[M_ROWS * D_MODEL];
__device__ uint32_t g_APK[(size_t)(M_ROWS / 128) * KT_N * 4096];      // A frag-packed
__device__ uint32_t g_WPK[(size_t)4 * 8 * KT_N * 4096];               // W frag-packed
__device__ uint32_t g_KVP[(size_t)BATCH * NUM_HEADS * NTILES * STAGE_WORDS];

__device__ __forceinline__ uint32_t f2tf32(float x) {
    uint32_t r;
    asm("cvt.rna.tf32.f32 %0, %1;" : "=r"(r) : "f"(x));
    return r;
}

__device__ __forceinline__ void mma_tf32(float c[4], const uint32_t a[4],
                                         uint32_t b0, uint32_t b1) {
    asm volatile(
        "mma.sync.aligned.m16n8k8.row.col.f32.tf32.tf32.f32 "
        "{%0,%1,%2,%3}, {%4,%5,%6,%7}, {%8,%9}, {%0,%1,%2,%3};\n"
        : "+f"(c[0]), "+f"(c[1]), "+f"(c[2]), "+f"(c[3])
        : "r"(a[0]), "r"(a[1]), "r"(a[2]), "r"(a[3]), "r"(b0), "r"(b1));
}

// ---------------------------------------------------------------------------
// pack_a: A [M_ROWS][D_MODEL] fp32 -> frag-order tf32.
// Block (kt, rb): 128x32 tile -> 4096 words: [kat 4][mt 8][lane 32][word 4]
//   word0 = A[m0+lrow][k+lcol], word1 = A[m0+8+lrow][k+lcol],
//   word2 = A[m0+lrow][k+lcol+4], word3 = A[m0+8+lrow][k+lcol+4]
// ---------------------------------------------------------------------------
__global__ __launch_bounds__(256) void pack_a_kernel(
    const float* __restrict__ A, uint32_t* __restrict__ out)
{
    __shared__ float s[128][36];
    const int kt = blockIdx.x;
    const int rb = blockIdx.y;
    const int tid = threadIdx.x;

    #pragma unroll
    for (int i = 0; i < 4; i++) {
        int idx = tid + i * 256;           // 0..1023 float4 slots
        int row = idx >> 3;                // 0..127
        int c4  = idx & 7;                 // 0..7
        float4 v = *reinterpret_cast<const float4*>(
            A + (size_t)(rb * 128 + row) * D_MODEL + kt * 32 + c4 * 4);
        *reinterpret_cast<float4*>(&s[row][c4 * 4]) = v;
    }
    __syncthreads();

    const int lane = tid & 31;
    const int lrow = lane >> 2, lcol = lane & 3;
    uint32_t* blk = out + ((size_t)rb * KT_N + kt) * 4096;
    #pragma unroll
    for (int i = 0; i < 4; i++) {
        int combo = (tid >> 5) + i * 8;    // 0..31
        int kat = combo >> 3, mt = combo & 7;
        int m0 = mt * 16, kk = kat * 8;
        uint4 w;
        w.x = f2tf32(s[m0 + lrow    ][kk + lcol    ]);
        w.y = f2tf32(s[m0 + 8 + lrow][kk + lcol    ]);
        w.z = f2tf32(s[m0 + lrow    ][kk + lcol + 4]);
        w.w = f2tf32(s[m0 + 8 + lrow][kk + lcol + 4]);
        *reinterpret_cast<uint4*>(blk + (size_t)(combo * 32 + lane) * 4) = w;
    }
}

// ---------------------------------------------------------------------------
// pack_w: W [K][N] fp32 (4 matrices) -> frag-order tf32.
// Block (kt, cb, mat): 32x128 tile -> 4096 words: [kat 4][nt 16][lane 32][word 2]
//   word0 = W[k+lcol][n0+lrow], word1 = W[k+lcol+4][n0+lrow]
// ---------------------------------------------------------------------------
__global__ __launch_bounds__(256) void pack_w_kernel(
    const float* __restrict__ w0, const float* __restrict__ w1,
    const float* __restrict__ w2, const float* __restrict__ w3,
    uint32_t* __restrict__ out)
{
    __shared__ float s[32][132];
    const float* srcs[4] = {w0, w1, w2, w3};
    const int kt  = blockIdx.x;
    const int cb  = blockIdx.y;
    const int mat = blockIdx.z;
    const int tid = threadIdx.x;
    const float* W = srcs[mat];

    #pragma unroll
    for (int i = 0; i < 4; i++) {
        int idx = tid + i * 256;           // 0..1023 float4 slots
        int row = idx >> 5;                // 0..31
        int c4  = idx & 31;                // 0..31
        float4 v = *reinterpret_cast<const float4*>(
            W + (size_t)(kt * 32 + row) * D_MODEL + cb * 128 + c4 * 4);
        *reinterpret_cast<float4*>(&s[row][c4 * 4]) = v;
    }
    __syncthreads();

    const int lane = tid & 31;
    const int lrow = lane >> 2, lcol = lane & 3;
    uint32_t* blk = out + (((size_t)mat * 8 + cb) * KT_N + kt) * 4096;
    #pragma unroll
    for (int i = 0; i < 8; i++) {
        int combo = (tid >> 5) + i * 8;    // 0..63
        int kat = combo >> 4, nt = combo & 15;
        int kk = kat * 8, n0 = nt * 8;
        uint2 w;
        w.x = f2tf32(s[kk + lcol    ][n0 + lrow]);
        w.y = f2tf32(s[kk + lcol + 4][n0 + lrow]);
        *reinterpret_cast<uint2*>(blk + (size_t)(combo * 32 + lane) * 2) = w;
    }
}

// ---------------------------------------------------------------------------
// TF32 GEMM over frag-packed inputs. CTA 128x128; pure cp.async 3-stage
// pipeline; inner loop = 2xLDS.128 + 8xLDS.64 + 16 MMA per k-atom.
// ---------------------------------------------------------------------------
__global__ __launch_bounds__(256) void gemm_tf32_bias_kernel(
    const uint32_t* __restrict__ APK, const uint32_t* __restrict__ BPK,
    const float* __restrict__ bias, float* __restrict__ C)
{
    extern __shared__ __align__(16) uint32_t gsm[];

    const int tid  = threadIdx.x;
    const int lane = tid & 31;
    const int warp = tid >> 5;
    const int wmt = (warp & 3) * 2;    // warp m-tile base (of 8)
    const int wnt = (warp >> 2) * 8;   // warp n-tile base (of 16)
    const int lrow = lane >> 2;
    const int lcol = lane & 3;

    const int cb = blockIdx.x;
    const int rb = blockIdx.y;

    const uint32_t* Asrc = APK + (size_t)rb * KT_N * 4096;
    const uint32_t* Bsrc = BPK + (size_t)cb * KT_N * 4096;
    const uint32_t sm_addr = (uint32_t)__cvta_generic_to_shared(gsm);

    auto issue_stage = [&](int t) {
        if (t < KT_N) {
            uint32_t dst0 = sm_addr + ((t % 3) * GW) * 4;
            const uint32_t* sa = Asrc + (size_t)t * 4096;
            const uint32_t* sb = Bsrc + (size_t)t * 4096;
            #pragma unroll
            for (int c = 0; c < 4; c++) {
                uint32_t off16 = (c * 256 + tid) * 16;  // bytes within 16KB half
                asm volatile("cp.async.cg.shared.global [%0], [%1], 16;\n"
                             :: "r"(dst0 + off16), "l"((const char*)sa + off16));
                asm volatile("cp.async.cg.shared.global [%0], [%1], 16;\n"
                             :: "r"(dst0 + 16384 + off16), "l"((const char*)sb + off16));
            }
        }
        asm volatile("cp.async.commit_group;\n");
    };

    float c[2][8][4];
    #pragma unroll
    for (int mi = 0; mi < 2; mi++)
        #pragma unroll
        for (int ni = 0; ni < 8; ni++)
            #pragma unroll
            for (int r = 0; r < 4; r++) c[mi][ni][r] = 0.0f;

    issue_stage(0);
    issue_stage(1);

    for (int t = 0; t < KT_N; t++) {
        asm volatile("cp.async.wait_group 1;\n");
        __syncthreads();

        const uint32_t* As = gsm + (t % 3) * GW;
        const uint32_t* Bs = As + 4096;

        #pragma unroll
        for (int kat = 0; kat < 4; kat++) {
            uint32_t a[2][4];
            #pragma unroll
            for (int mi = 0; mi < 2; mi++) {
                uint4 av = *reinterpret_cast<const uint4*>(
                    As + (size_t)(((kat * 8 + wmt + mi) * 32 + lane) * 4));
                a[mi][0] = av.x; a[mi][1] = av.y; a[mi][2] = av.z; a[mi][3] = av.w;
            }
            uint2 b[8];
            #pragma unroll
            for (int ni = 0; ni < 8; ni++)
                b[ni] = *reinterpret_cast<const uint2*>(
                    Bs + (size_t)(((kat * 16 + wnt + ni) * 32 + lane) * 2));
            #pragma unroll
            for (int mi = 0; mi < 2; mi++)
                #pragma unroll
                for (int ni = 0; ni < 8; ni++)
                    mma_tf32(c[mi][ni], a[mi], b[ni].x, b[ni].y);
        }

        issue_stage(t + 2);
    }

    #pragma unroll
    for (int mi = 0; mi < 2; mi++) {
        int r0 = rb * 128 + (wmt + mi) * 16 + lrow;
        #pragma unroll
        for (int ni = 0; ni < 8; ni++) {
            int col = cb * 128 + (wnt + ni) * 8 + lcol * 2;
            float b0 = bias[col];
            float b1 = bias[col + 1];
            float2 v0 = make_float2(c[mi][ni][0] + b0, c[mi][ni][1] + b1);
            float2 v1 = make_float2(c[mi][ni][2] + b0, c[mi][ni][3] + b1);
            *reinterpret_cast<float2*>(C + (size_t)r0 * D_MODEL + col) = v0;
            *reinterpret_cast<float2*>(C + (size_t)(r0 + 8) * D_MODEL + col) = v1;
        }
    }
}

// ---------------------------------------------------------------------------
// Pack kernel: K,V -> tf32 fragment-order stage images (unchanged, passing).
// ---------------------------------------------------------------------------
__global__ __launch_bounds__(512) void pack_kv_kernel(
    const float* __restrict__ K, const float* __restrict__ V,
    uint32_t* __restrict__ P)
{
    const int kt = blockIdx.x;
    const int bh = blockIdx.y;
    const int b  = bh >> 4;
    const int h  = bh & 15;
    const size_t base = ((size_t)b * SEQ_LEN) * D_MODEL + h * D_HEAD;
    uint32_t* blk = P + ((size_t)bh * NTILES + kt) * STAGE_WORDS;
    const int tid = threadIdx.x;

    if (tid < 256) {
        const int key = tid & 31;
        const int kd  = tid >> 5;
        const float* src = K + base + (size_t)(kt * 32 + key) * D_MODEL + kd * 8;
        float4 v0 = *reinterpret_cast<const float4*>(src);
        float4 v1 = *reinterpret_cast<const float4*>(src + 4);
        float e[8] = {v0.x, v0.y, v0.z, v0.w, v1.x, v1.y, v1.z, v1.w};
        uint32_t hi[8];
        #pragma unroll
        for (int i = 0; i < 8; i++) hi[i] = f2tf32(e[i]);
        const int nt = key >> 3, g = key & 7;
        uint32_t* dhi = blk + (kd * 4 + nt) * 64 + g * 8;
        *reinterpret_cast<uint4*>(dhi)     = make_uint4(hi[0], hi[4], hi[1], hi[5]);
        *reinterpret_cast<uint4*>(dhi + 4) = make_uint4(hi[2], hi[6], hi[3], hi[7]);
    } else {
        const int t2 = tid - 256;
        const int dh = t2 & 63;
        const int kv = t2 >> 6;
        float e[8];
        #pragma unroll
        for (int k = 0; k < 8; k++)
            e[k] = V[base + (size_t)(kt * 32 + kv * 8 + k) * D_MODEL + dh];
        uint32_t hi[8];
        #pragma unroll
        for (int i = 0; i < 8; i++) hi[i] = f2tf32(e[i]);
        const int nv = dh >> 3;
        uint32_t* dhi = blk + 2048 + (kv * 8 + nv) * 64 + (dh & 7) * 8;
        *reinterpret_cast<uint4*>(dhi)     = make_uint4(hi[0], hi[4], hi[1], hi[5]);
        *reinterpret_cast<uint4*>(dhi + 4) = make_uint4(hi[2], hi[6], hi[3], hi[7]);
    }
}

// ---------------------------------------------------------------------------
// Tensor-core flash attention (unchanged, passing). QK 1xTF32, PV 1xTF32.
// ---------------------------------------------------------------------------
__global__ __launch_bounds__(256, 2) void attn_mma_kernel(
    const float* __restrict__ Q, const uint32_t* __restrict__ KVP,
    float* __restrict__ O)
{
    extern __shared__ __align__(16) uint32_t sm[];

    const int qt   = (int)gridDim.x - 1 - (int)blockIdx.x;
    const int bh   = blockIdx.y;
    const int b    = bh >> 4;
    const int h    = bh & 15;
    const int tid  = threadIdx.x;
    const int lane = tid & 31;
    const int warp = tid >> 5;
    const int g    = lane >> 2;
    const int t    = lane & 3;

    const int wq0 = qt * 128 + warp * 16;
    const size_t base = ((size_t)b * SEQ_LEN) * D_MODEL + h * D_HEAD;
    const uint32_t* tile_base = KVP + (size_t)bh * NTILES * STAGE_WORDS;
    const uint32_t sm_addr = (uint32_t)__cvta_generic_to_shared(sm);
    const int nkt = 4 * qt + 4;

    uint32_t qh[8][4];
    {
        const int row0 = wq0 + g, row1 = row0 + 8;
        #pragma unroll
        for (int kd = 0; kd < 8; kd++) {
            int c0 = kd * 8 + t, c1 = c0 + 4;
            qh[kd][0] = f2tf32(Q[base + (size_t)row0 * D_MODEL + c0] * 0.125f);
            qh[kd][1] = f2tf32(Q[base + (size_t)row1 * D_MODEL + c0] * 0.125f);
            qh[kd][2] = f2tf32(Q[base + (size_t)row0 * D_MODEL + c1] * 0.125f);
            qh[kd][3] = f2tf32(Q[base + (size_t)row1 * D_MODEL + c1] * 0.125f);
        }
    }

    float oc[8][4];
    #pragma unroll
    for (int nv = 0; nv < 8; nv++)
        #pragma unroll
        for (int r = 0; r < 4; r++) oc[nv][r] = 0.0f;

    float m0 = -1.0e30f, m1 = -1.0e30f;
    float l0 = 0.0f, l1 = 0.0f;

    auto issue_tile = [&](int kt) {
        if (kt < nkt) {
            const uint32_t* src = tile_base + (size_t)kt * STAGE_WORDS + tid * 4;
            uint32_t dst = sm_addr + ((kt % 3) * STAGE_WORDS + tid * 4) * 4;
            #pragma unroll
            for (int c = 0; c < 4; c++) {
                asm volatile("cp.async.cg.shared.global [%0], [%1], 16;\n"
                             :: "r"(dst + c * 4096), "l"(src + c * 1024));
            }
        }
        asm volatile("cp.async.commit_group;\n");
    };

    issue_tile(0);
    issue_tile(1);

    for (int kt = 0; kt < nkt; kt++) {
        asm volatile("cp.async.wait_group 1;\n");
        __syncthreads();

        const uint2* KhiS = reinterpret_cast<const uint2*>(sm + (kt % 3) * STAGE_WORDS);
        const uint2* VhiS = KhiS + 1024;
        const int k0 = kt * 32;

        if (k0 <= wq0 + 15) {
            float sc[4][4];
            #pragma unroll
            for (int nt = 0; nt < 4; nt++)
                #pragma unroll
                for (int r = 0; r < 4; r++) sc[nt][r] = 0.0f;

            #pragma unroll
            for (int kd = 0; kd < 8; kd++) {
                #pragma unroll
                for (int nt = 0; nt < 4; nt++) {
                    uint2 bh2 = KhiS[(kd * 4 + nt) * 32 + lane];
                    mma_tf32(sc[nt], qh[kd], bh2.x, bh2.y);
                }
            }

            const int row0 = wq0 + g, row1 = row0 + 8;

            if (k0 + 31 > wq0) {
                #pragma unroll
                for (int nt = 0; nt < 4; nt++) {
                    int col = k0 + nt * 8 + 2 * t;
                    if (col     > row0) sc[nt][0] = -1.0e30f;
                    if (col + 1 > row0) sc[nt][1] = -1.0e30f;
                    if (col     > row1) sc[nt][2] = -1.0e30f;
                    if (col + 1 > row1) sc[nt][3] = -1.0e30f;
                }
            }

            float mt0 = sc[0][0], mt1 = sc[0][2];
            #pragma unroll
            for (int nt = 0; nt < 4; nt++) {
                mt0 = fmaxf(mt0, fmaxf(sc[nt][0], sc[nt][1]));
                mt1 = fmaxf(mt1, fmaxf(sc[nt][2], sc[nt][3]));
            }
            #pragma unroll
            for (int w = 1; w < 4; w <<= 1) {
                mt0 = fmaxf(mt0, __shfl_xor_sync(0xffffffff, mt0, w));
                mt1 = fmaxf(mt1, __shfl_xor_sync(0xffffffff, mt1, w));
            }
            float mn0 = fmaxf(m0, mt0), mn1 = fmaxf(m1, mt1);
            float cr0 = __expf(m0 - mn0), cr1 = __expf(m1 - mn1);
            m0 = mn0; m1 = mn1;
            l0 *= cr0; l1 *= cr1;
            #pragma unroll
            for (int nv = 0; nv < 8; nv++) {
                oc[nv][0] *= cr0; oc[nv][1] *= cr0;
                oc[nv][2] *= cr1; oc[nv][3] *= cr1;
            }

            float ps[4][4];
            #pragma unroll
            for (int nt = 0; nt < 4; nt++) {
                ps[nt][0] = __expf(sc[nt][0] - m0);
                ps[nt][1] = __expf(sc[nt][1] - m0);
                ps[nt][2] = __expf(sc[nt][2] - m1);
                ps[nt][3] = __expf(sc[nt][3] - m1);
                l0 += ps[nt][0] + ps[nt][1];
                l1 += ps[nt][2] + ps[nt][3];
            }

            const int src0 = (lane & ~3) | (t >> 1);
            const int src1 = src0 + 2;
            const bool odd = (t & 1);
            #pragma unroll
            for (int kv = 0; kv < 4; kv++) {
                float a0f, a1f, a2f, a3f;
                {
                    float t00 = __shfl_sync(0xffffffff, ps[kv][0], src0);
                    float t01 = __shfl_sync(0xffffffff, ps[kv][1], src0);
                    a0f = odd ? t01 : t00;
                    float t10 = __shfl_sync(0xffffffff, ps[kv][2], src0);
                    float t11 = __shfl_sync(0xffffffff, ps[kv][3], src0);
                    a1f = odd ? t11 : t10;
                    float t20 = __shfl_sync(0xffffffff, ps[kv][0], src1);
                    float t21 = __shfl_sync(0xffffffff, ps[kv][1], src1);
                    a2f = odd ? t21 : t20;
                    float t30 = __shfl_sync(0xffffffff, ps[kv][2], src1);
                    float t31 = __shfl_sync(0xffffffff, ps[kv][3], src1);
                    a3f = odd ? t31 : t30;
                }
                uint32_t ph[4];
                ph[0] = f2tf32(a0f);
                ph[1] = f2tf32(a1f);
                ph[2] = f2tf32(a2f);
                ph[3] = f2tf32(a3f);

                #pragma unroll
                for (int nv = 0; nv < 8; nv++) {
                    uint2 vh2 = VhiS[(kv * 8 + nv) * 32 + lane];
                    mma_tf32(oc[nv], ph, vh2.x, vh2.y);
                }
            }
        }

        issue_tile(kt + 2);
    }

    #pragma unroll
    for (int w = 1; w < 4; w <<= 1) {
        l0 += __shfl_xor_sync(0xffffffff, l0, w);
        l1 += __shfl_xor_sync(0xffffffff, l1, w);
    }
    const float inv0 = 1.0f / l0, inv1 = 1.0f / l1;
    const int row0 = wq0 + g, row1 = row0 + 8;
    #pragma unroll
    for (int nv = 0; nv < 8; nv++) {
        int col = nv * 8 + 2 * t;
        *reinterpret_cast<float2*>(O + base + (size_t)row0 * D_MODEL + col) =
            make_float2(oc[nv][0] * inv0, oc[nv][1] * inv0);
        *reinterpret_cast<float2*>(O + base + (size_t)row1 * D_MODEL + col) =
            make_float2(oc[nv][2] * inv1, oc[nv][3] * inv1);
    }
}

// ---------------------------------------------------------------------------
// Launch: pack prepass -> QKV GEMMs -> pack KV -> attn -> out GEMM.
// ---------------------------------------------------------------------------
extern "C" void kernel_launch(void* const* d_in, const int* in_sizes, int n_in,
                              void* d_out, int out_size)
{
    const float* x  = (const float*)d_in[0];
    const float* Wq = (const float*)d_in[1];
    const float* bq = (const float*)d_in[2];
    const float* Wk = (const float*)d_in[3];
    const float* bk = (const float*)d_in[4];
    const float* Wv = (const float*)d_in[5];
    const float* bv = (const float*)d_in[6];
    const float* Wo = (const float*)d_in[7];
    const float* bo = (const float*)d_in[8];
    float* out = (float*)d_out;

    const int M = in_sizes[0] / D_MODEL;   // 4096
    const int B = M / SEQ_LEN;             // 2

    float *Qp, *Kp, *Vp, *Op;
    uint32_t *APKp, *WPKp, *KVPp;
    cudaGetSymbolAddress((void**)&Qp, g_Q);
    cudaGetSymbolAddress((void**)&Kp, g_K);
    cudaGetSymbolAddress((void**)&Vp, g_V);
    cudaGetSymbolAddress((void**)&Op, g_O);
    cudaGetSymbolAddress((void**)&APKp, g_APK);
    cudaGetSymbolAddress((void**)&WPKp, g_WPK);
    cudaGetSymbolAddress((void**)&KVPp, g_KVP);

    static bool attr_set = false;
    if (!attr_set) {
        cudaFuncSetAttribute(attn_mma_kernel,
                             cudaFuncAttributeMaxDynamicSharedMemorySize,
                             3 * STAGE_WORDS * 4);
        cudaFuncSetAttribute(gemm_tf32_bias_kernel,
                             cudaFuncAttributeMaxDynamicSharedMemorySize,
                             3 * GW * 4);
        attr_set = true;
    }

    const int gemm_smem = 3 * GW * 4;             // 98304 B
    const size_t WSTRIDE = (size_t)8 * KT_N * 4096;
    dim3 gemm_grid(8, M / 128);                   // (8, 32)
    dim3 pa_grid(KT_N, M / 128);                  // (32, 32)
    dim3 pw_grid(KT_N, 8, 4);                     // (32, 8, 4)

    // Pre-pass: fragment-pack A (x) and all 4 weight matrices.
    pack_a_kernel<<<pa_grid, 256>>>(x, APKp);
    pack_w_kernel<<<pw_grid, 256>>>(Wq, Wk, Wv, Wo, WPKp);

    // QKV projections.
    gemm_tf32_bias_kernel<<<gemm_grid, 256, gemm_smem>>>(APKp, WPKp + 0 * WSTRIDE, bq, Qp);
    gemm_tf32_bias_kernel<<<gemm_grid, 256, gemm_smem>>>(APKp, WPKp + 1 * WSTRIDE, bk, Kp);
    gemm_tf32_bias_kernel<<<gemm_grid, 256, gemm_smem>>>(APKp, WPKp + 2 * WSTRIDE, bv, Vp);

    // Pack K/V to fragment order.
    dim3 pack_grid(NTILES, B * NUM_HEADS);        // (64, 32)
    pack_kv_kernel<<<pack_grid, 512>>>(Kp, Vp, KVPp);

    // Attention.
    dim3 attn_grid(SEQ_LEN / 128, B * NUM_HEADS); // (16, 32)
    attn_mma_kernel<<<attn_grid, 256, 3 * STAGE_WORDS * 4>>>(Qp, KVPp, Op);

    // Output projection (re-pack attn output as A).
    pack_a_kernel<<<pa_grid, 256>>>(Op, APKp);
    gemm_tf32_bias_kernel<<<gemm_grid, 256, gemm_smem>>>(APKp, WPKp + 3 * WSTRIDE, bo, out);
}

// round 10
// speedup vs baseline: 5.3789x; 1.0215x over previous
#include <cuda_runtime.h>
#include <cstdint>

// ---------------------------------------------------------------------------
// Problem constants: x [B=2, S=2048, d=1024], H=16, Dh=64, causal MHA, fp32.
// ---------------------------------------------------------------------------
#define D_MODEL 1024
#define NUM_HEADS 16
#define D_HEAD 64
#define SEQ_LEN 2048
#define BATCH 2
#define M_ROWS (BATCH * SEQ_LEN)   // 4096
#define NTILES (SEQ_LEN / 32)      // 64 key tiles per (b,h)
#define STAGE_WORDS 4096           // attn: 16KB per tile [Khi 2048][Vhi 2048]
#define GW 8192                    // gemm stage words: [A 4096][B 4096] = 32KB
#define KT_N 32                    // k-tiles per GEMM (K=1024 / 32)
#define WSTRIDE ((size_t)8 * KT_N * 4096)

// Scratch (alloc-free rule: __device__ globals).
__device__ float    g_Q[M_ROWS * D_MODEL];
__device__ float    g_K[M_ROWS * D_MODEL];
__device__ float    g_V[M_ROWS * D_MODEL];
__device__ uint32_t g_APK[(size_t)(M_ROWS / 128) * KT_N * 4096];      // A frag-packed
__device__ uint32_t g_WPK[4 * WSTRIDE];                               // W frag-packed
__device__ uint32_t g_KVP[(size_t)BATCH * NUM_HEADS * NTILES * STAGE_WORDS];

__device__ __forceinline__ uint32_t f2tf32(float x) {
    uint32_t r;
    asm("cvt.rna.tf32.f32 %0, %1;" : "=r"(r) : "f"(x));
    return r;
}

__device__ __forceinline__ void mma_tf32(float c[4], const uint32_t a[4],
                                         uint32_t b0, uint32_t b1) {
    asm volatile(
        "mma.sync.aligned.m16n8k8.row.col.f32.tf32.tf32.f32 "
        "{%0,%1,%2,%3}, {%4,%5,%6,%7}, {%8,%9}, {%0,%1,%2,%3};\n"
        : "+f"(c[0]), "+f"(c[1]), "+f"(c[2]), "+f"(c[3])
        : "r"(a[0]), "r"(a[1]), "r"(a[2]), "r"(a[3]), "r"(b0), "r"(b1));
}

// ---------------------------------------------------------------------------
// pack_a: A [M_ROWS][D_MODEL] fp32 -> frag-order tf32 (used for x only now).
// Block (kt, rb): 128x32 tile -> 4096 words: [kat 4][mt 8][lane 32][word 4]
// ---------------------------------------------------------------------------
__global__ __launch_bounds__(256) void pack_a_kernel(
    const float* __restrict__ A, uint32_t* __restrict__ out)
{
    __shared__ float s[128][36];
    const int kt = blockIdx.x;
    const int rb = blockIdx.y;
    const int tid = threadIdx.x;

    #pragma unroll
    for (int i = 0; i < 4; i++) {
        int idx = tid + i * 256;
        int row = idx >> 3;
        int c4  = idx & 7;
        float4 v = *reinterpret_cast<const float4*>(
            A + (size_t)(rb * 128 + row) * D_MODEL + kt * 32 + c4 * 4);
        *reinterpret_cast<float4*>(&s[row][c4 * 4]) = v;
    }
    __syncthreads();

    const int lane = tid & 31;
    const int lrow = lane >> 2, lcol = lane & 3;
    uint32_t* blk = out + ((size_t)rb * KT_N + kt) * 4096;
    #pragma unroll
    for (int i = 0; i < 4; i++) {
        int combo = (tid >> 5) + i * 8;
        int kat = combo >> 3, mt = combo & 7;
        int m0 = mt * 16, kk = kat * 8;
        uint4 w;
        w.x = f2tf32(s[m0 + lrow    ][kk + lcol    ]);
        w.y = f2tf32(s[m0 + 8 + lrow][kk + lcol    ]);
        w.z = f2tf32(s[m0 + lrow    ][kk + lcol + 4]);
        w.w = f2tf32(s[m0 + 8 + lrow][kk + lcol + 4]);
        *reinterpret_cast<uint4*>(blk + (size_t)(combo * 32 + lane) * 4) = w;
    }
}

// ---------------------------------------------------------------------------
// pack_w: W [K][N] fp32 (4 matrices) -> frag-order tf32.
// ---------------------------------------------------------------------------
__global__ __launch_bounds__(256) void pack_w_kernel(
    const float* __restrict__ w0, const float* __restrict__ w1,
    const float* __restrict__ w2, const float* __restrict__ w3,
    uint32_t* __restrict__ out)
{
    __shared__ float s[32][132];
    const float* srcs[4] = {w0, w1, w2, w3};
    const int kt  = blockIdx.x;
    const int cb  = blockIdx.y;
    const int mat = blockIdx.z;
    const int tid = threadIdx.x;
    const float* W = srcs[mat];

    #pragma unroll
    for (int i = 0; i < 4; i++) {
        int idx = tid + i * 256;
        int row = idx >> 5;
        int c4  = idx & 31;
        float4 v = *reinterpret_cast<const float4*>(
            W + (size_t)(kt * 32 + row) * D_MODEL + cb * 128 + c4 * 4);
        *reinterpret_cast<float4*>(&s[row][c4 * 4]) = v;
    }
    __syncthreads();

    const int lane = tid & 31;
    const int lrow = lane >> 2, lcol = lane & 3;
    uint32_t* blk = out + (((size_t)mat * 8 + cb) * KT_N + kt) * 4096;
    #pragma unroll
    for (int i = 0; i < 8; i++) {
        int combo = (tid >> 5) + i * 8;
        int kat = combo >> 4, nt = combo & 15;
        int kk = kat * 8, n0 = nt * 8;
        uint2 w;
        w.x = f2tf32(s[kk + lcol    ][n0 + lrow]);
        w.y = f2tf32(s[kk + lcol + 4][n0 + lrow]);
        *reinterpret_cast<uint2*>(blk + (size_t)(combo * 32 + lane) * 2) = w;
    }
}

// ---------------------------------------------------------------------------
// GEMM body shared by the fused-QKV and single variants.
// ---------------------------------------------------------------------------
__device__ __forceinline__ void gemm_body(
    const uint32_t* __restrict__ Asrc, const uint32_t* __restrict__ Bsrc,
    const float* __restrict__ bias, float* __restrict__ C,
    uint32_t* gsm, int cb, int rb)
{
    const int tid  = threadIdx.x;
    const int lane = tid & 31;
    const int warp = tid >> 5;
    const int wmt = (warp & 3) * 2;
    const int wnt = (warp >> 2) * 8;
    const int lrow = lane >> 2;
    const int lcol = lane & 3;

    const uint32_t sm_addr = (uint32_t)__cvta_generic_to_shared(gsm);

    auto issue_stage = [&](int t) {
        if (t < KT_N) {
            uint32_t dst0 = sm_addr + ((t % 3) * GW) * 4;
            const uint32_t* sa = Asrc + (size_t)t * 4096;
            const uint32_t* sb = Bsrc + (size_t)t * 4096;
            #pragma unroll
            for (int c = 0; c < 4; c++) {
                uint32_t off16 = (c * 256 + tid) * 16;
                asm volatile("cp.async.cg.shared.global [%0], [%1], 16;\n"
                             :: "r"(dst0 + off16), "l"((const char*)sa + off16));
                asm volatile("cp.async.cg.shared.global [%0], [%1], 16;\n"
                             :: "r"(dst0 + 16384 + off16), "l"((const char*)sb + off16));
            }
        }
        asm volatile("cp.async.commit_group;\n");
    };

    float c[2][8][4];
    #pragma unroll
    for (int mi = 0; mi < 2; mi++)
        #pragma unroll
        for (int ni = 0; ni < 8; ni++)
            #pragma unroll
            for (int r = 0; r < 4; r++) c[mi][ni][r] = 0.0f;

    issue_stage(0);
    issue_stage(1);

    for (int t = 0; t < KT_N; t++) {
        asm volatile("cp.async.wait_group 1;\n");
        __syncthreads();

        const uint32_t* As = gsm + (t % 3) * GW;
        const uint32_t* Bs = As + 4096;

        #pragma unroll
        for (int kat = 0; kat < 4; kat++) {
            uint32_t a[2][4];
            #pragma unroll
            for (int mi = 0; mi < 2; mi++) {
                uint4 av = *reinterpret_cast<const uint4*>(
                    As + (size_t)(((kat * 8 + wmt + mi) * 32 + lane) * 4));
                a[mi][0] = av.x; a[mi][1] = av.y; a[mi][2] = av.z; a[mi][3] = av.w;
            }
            uint2 b[8];
            #pragma unroll
            for (int ni = 0; ni < 8; ni++)
                b[ni] = *reinterpret_cast<const uint2*>(
                    Bs + (size_t)(((kat * 16 + wnt + ni) * 32 + lane) * 2));
            #pragma unroll
            for (int mi = 0; mi < 2; mi++)
                #pragma unroll
                for (int ni = 0; ni < 8; ni++)
                    mma_tf32(c[mi][ni], a[mi], b[ni].x, b[ni].y);
        }

        issue_stage(t + 2);
    }

    #pragma unroll
    for (int mi = 0; mi < 2; mi++) {
        int r0 = rb * 128 + (wmt + mi) * 16 + lrow;
        #pragma unroll
        for (int ni = 0; ni < 8; ni++) {
            int col = cb * 128 + (wnt + ni) * 8 + lcol * 2;
            float b0 = bias[col];
            float b1 = bias[col + 1];
            float2 v0 = make_float2(c[mi][ni][0] + b0, c[mi][ni][1] + b1);
            float2 v1 = make_float2(c[mi][ni][2] + b0, c[mi][ni][3] + b1);
            *reinterpret_cast<float2*>(C + (size_t)r0 * D_MODEL + col) = v0;
            *reinterpret_cast<float2*>(C + (size_t)(r0 + 8) * D_MODEL + col) = v1;
        }
    }
}

// Fused QKV: gridDim.z = 3 selects weight / bias / output.
__global__ __launch_bounds__(256) void gemm_qkv_kernel(
    const uint32_t* __restrict__ APK, const uint32_t* __restrict__ WPK,
    const float* __restrict__ bq, const float* __restrict__ bk,
    const float* __restrict__ bv,
    float* __restrict__ Q, float* __restrict__ K, float* __restrict__ V)
{
    extern __shared__ __align__(16) uint32_t gsm[];
    const int cb = blockIdx.x, rb = blockIdx.y, z = blockIdx.z;
    const float* bias = (z == 0) ? bq : (z == 1) ? bk : bv;
    float* C = (z == 0) ? Q : (z == 1) ? K : V;
    gemm_body(APK + (size_t)rb * KT_N * 4096,
              WPK + (size_t)z * WSTRIDE + (size_t)cb * KT_N * 4096,
              bias, C, gsm, cb, rb);
}

// Single GEMM (output projection).
__global__ __launch_bounds__(256) void gemm_tf32_bias_kernel(
    const uint32_t* __restrict__ APK, const uint32_t* __restrict__ BPK,
    const float* __restrict__ bias, float* __restrict__ C)
{
    extern __shared__ __align__(16) uint32_t gsm[];
    gemm_body(APK + (size_t)blockIdx.y * KT_N * 4096,
              BPK + (size_t)blockIdx.x * KT_N * 4096,
              bias, C, gsm, blockIdx.x, blockIdx.y);
}

// ---------------------------------------------------------------------------
// Pack kernel: K,V -> tf32 fragment-order stage images (unchanged, passing).
// ---------------------------------------------------------------------------
__global__ __launch_bounds__(512) void pack_kv_kernel(
    const float* __restrict__ K, const float* __restrict__ V,
    uint32_t* __restrict__ P)
{
    const int kt = blockIdx.x;
    const int bh = blockIdx.y;
    const int b  = bh >> 4;
    const int h  = bh & 15;
    const size_t base = ((size_t)b * SEQ_LEN) * D_MODEL + h * D_HEAD;
    uint32_t* blk = P + ((size_t)bh * NTILES + kt) * STAGE_WORDS;
    const int tid = threadIdx.x;

    if (tid < 256) {
        const int key = tid & 31;
        const int kd  = tid >> 5;
        const float* src = K + base + (size_t)(kt * 32 + key) * D_MODEL + kd * 8;
        float4 v0 = *reinterpret_cast<const float4*>(src);
        float4 v1 = *reinterpret_cast<const float4*>(src + 4);
        float e[8] = {v0.x, v0.y, v0.z, v0.w, v1.x, v1.y, v1.z, v1.w};
        uint32_t hi[8];
        #pragma unroll
        for (int i = 0; i < 8; i++) hi[i] = f2tf32(e[i]);
        const int nt = key >> 3, g = key & 7;
        uint32_t* dhi = blk + (kd * 4 + nt) * 64 + g * 8;
        *reinterpret_cast<uint4*>(dhi)     = make_uint4(hi[0], hi[4], hi[1], hi[5]);
        *reinterpret_cast<uint4*>(dhi + 4) = make_uint4(hi[2], hi[6], hi[3], hi[7]);
    } else {
        const int t2 = tid - 256;
        const int dh = t2 & 63;
        const int kv = t2 >> 6;
        float e[8];
        #pragma unroll
        for (int k = 0; k < 8; k++)
            e[k] = V[base + (size_t)(kt * 32 + kv * 8 + k) * D_MODEL + dh];
        uint32_t hi[8];
        #pragma unroll
        for (int i = 0; i < 8; i++) hi[i] = f2tf32(e[i]);
        const int nv = dh >> 3;
        uint32_t* dhi = blk + 2048 + (kv * 8 + nv) * 64 + (dh & 7) * 8;
        *reinterpret_cast<uint4*>(dhi)     = make_uint4(hi[0], hi[4], hi[1], hi[5]);
        *reinterpret_cast<uint4*>(dhi + 4) = make_uint4(hi[2], hi[6], hi[3], hi[7]);
    }
}

// ---------------------------------------------------------------------------
// Tensor-core flash attention. QK 1xTF32, PV 1xTF32.
// Epilogue writes O DIRECTLY in packed-A fragment order into g_APK
// (same shfl transpose as the P path; same f2tf32 rounding as pack_a).
// ---------------------------------------------------------------------------
__global__ __launch_bounds__(256, 2) void attn_mma_kernel(
    const float* __restrict__ Q, const uint32_t* __restrict__ KVP,
    uint32_t* __restrict__ APK)
{
    extern __shared__ __align__(16) uint32_t sm[];

    const int qt   = (int)gridDim.x - 1 - (int)blockIdx.x;
    const int bh   = blockIdx.y;
    const int b    = bh >> 4;
    const int h    = bh & 15;
    const int tid  = threadIdx.x;
    const int lane = tid & 31;
    const int warp = tid >> 5;
    const int g    = lane >> 2;
    const int t    = lane & 3;

    const int wq0 = qt * 128 + warp * 16;
    const size_t base = ((size_t)b * SEQ_LEN) * D_MODEL + h * D_HEAD;
    const uint32_t* tile_base = KVP + (size_t)bh * NTILES * STAGE_WORDS;
    const uint32_t sm_addr = (uint32_t)__cvta_generic_to_shared(sm);
    const int nkt = 4 * qt + 4;

    uint32_t qh[8][4];
    {
        const int row0 = wq0 + g, row1 = row0 + 8;
        #pragma unroll
        for (int kd = 0; kd < 8; kd++) {
            int c0 = kd * 8 + t, c1 = c0 + 4;
            qh[kd][0] = f2tf32(Q[base + (size_t)row0 * D_MODEL + c0] * 0.125f);
            qh[kd][1] = f2tf32(Q[base + (size_t)row1 * D_MODEL + c0] * 0.125f);
            qh[kd][2] = f2tf32(Q[base + (size_t)row0 * D_MODEL + c1] * 0.125f);
            qh[kd][3] = f2tf32(Q[base + (size_t)row1 * D_MODEL + c1] * 0.125f);
        }
    }

    float oc[8][4];
    #pragma unroll
    for (int nv = 0; nv < 8; nv++)
        #pragma unroll
        for (int r = 0; r < 4; r++) oc[nv][r] = 0.0f;

    float m0 = -1.0e30f, m1 = -1.0e30f;
    float l0 = 0.0f, l1 = 0.0f;

    auto issue_tile = [&](int kt) {
        if (kt < nkt) {
            const uint32_t* src = tile_base + (size_t)kt * STAGE_WORDS + tid * 4;
            uint32_t dst = sm_addr + ((kt % 3) * STAGE_WORDS + tid * 4) * 4;
            #pragma unroll
            for (int c = 0; c < 4; c++) {
                asm volatile("cp.async.cg.shared.global [%0], [%1], 16;\n"
                             :: "r"(dst + c * 4096), "l"(src + c * 1024));
            }
        }
        asm volatile("cp.async.commit_group;\n");
    };

    issue_tile(0);
    issue_tile(1);

    const int src0 = (lane & ~3) | (t >> 1);
    const int src1 = src0 + 2;
    const bool odd = (t & 1);

    for (int kt = 0; kt < nkt; kt++) {
        asm volatile("cp.async.wait_group 1;\n");
        __syncthreads();

        const uint2* KhiS = reinterpret_cast<const uint2*>(sm + (kt % 3) * STAGE_WORDS);
        const uint2* VhiS = KhiS + 1024;
        const int k0 = kt * 32;

        if (k0 <= wq0 + 15) {
            float sc[4][4];
            #pragma unroll
            for (int nt = 0; nt < 4; nt++)
                #pragma unroll
                for (int r = 0; r < 4; r++) sc[nt][r] = 0.0f;

            #pragma unroll
            for (int kd = 0; kd < 8; kd++) {
                #pragma unroll
                for (int nt = 0; nt < 4; nt++) {
                    uint2 bh2 = KhiS[(kd * 4 + nt) * 32 + lane];
                    mma_tf32(sc[nt], qh[kd], bh2.x, bh2.y);
                }
            }

            const int row0 = wq0 + g, row1 = row0 + 8;

            if (k0 + 31 > wq0) {
                #pragma unroll
                for (int nt = 0; nt < 4; nt++) {
                    int col = k0 + nt * 8 + 2 * t;
                    if (col     > row0) sc[nt][0] = -1.0e30f;
                    if (col + 1 > row0) sc[nt][1] = -1.0e30f;
                    if (col     > row1) sc[nt][2] = -1.0e30f;
                    if (col + 1 > row1) sc[nt][3] = -1.0e30f;
                }
            }

            float mt0 = sc[0][0], mt1 = sc[0][2];
            #pragma unroll
            for (int nt = 0; nt < 4; nt++) {
                mt0 = fmaxf(mt0, fmaxf(sc[nt][0], sc[nt][1]));
                mt1 = fmaxf(mt1, fmaxf(sc[nt][2], sc[nt][3]));
            }
            #pragma unroll
            for (int w = 1; w < 4; w <<= 1) {
                mt0 = fmaxf(mt0, __shfl_xor_sync(0xffffffff, mt0, w));
                mt1 = fmaxf(mt1, __shfl_xor_sync(0xffffffff, mt1, w));
            }
            float mn0 = fmaxf(m0, mt0), mn1 = fmaxf(m1, mt1);
            float cr0 = __expf(m0 - mn0), cr1 = __expf(m1 - mn1);
            m0 = mn0; m1 = mn1;
            l0 *= cr0; l1 *= cr1;
            #pragma unroll
            for (int nv = 0; nv < 8; nv++) {
                oc[nv][0] *= cr0; oc[nv][1] *= cr0;
                oc[nv][2] *= cr1; oc[nv][3] *= cr1;
            }

            float ps[4][4];
            #pragma unroll
            for (int nt = 0; nt < 4; nt++) {
                ps[nt][0] = __expf(sc[nt][0] - m0);
                ps[nt][1] = __expf(sc[nt][1] - m0);
                ps[nt][2] = __expf(sc[nt][2] - m1);
                ps[nt][3] = __expf(sc[nt][3] - m1);
                l0 += ps[nt][0] + ps[nt][1];
                l1 += ps[nt][2] + ps[nt][3];
            }

            #pragma unroll
            for (int kv = 0; kv < 4; kv++) {
                float a0f, a1f, a2f, a3f;
                {
                    float t00 = __shfl_sync(0xffffffff, ps[kv][0], src0);
                    float t01 = __shfl_sync(0xffffffff, ps[kv][1], src0);
                    a0f = odd ? t01 : t00;
                    float t10 = __shfl_sync(0xffffffff, ps[kv][2], src0);
                    float t11 = __shfl_sync(0xffffffff, ps[kv][3], src0);
                    a1f = odd ? t11 : t10;
                    float t20 = __shfl_sync(0xffffffff, ps[kv][0], src1);
                    float t21 = __shfl_sync(0xffffffff, ps[kv][1], src1);
                    a2f = odd ? t21 : t20;
                    float t30 = __shfl_sync(0xffffffff, ps[kv][2], src1);
                    float t31 = __shfl_sync(0xffffffff, ps[kv][3], src1);
                    a3f = odd ? t31 : t30;
                }
                uint32_t ph[4];
                ph[0] = f2tf32(a0f);
                ph[1] = f2tf32(a1f);
                ph[2] = f2tf32(a2f);
                ph[3] = f2tf32(a3f);

                #pragma unroll
                for (int nv = 0; nv < 8; nv++) {
                    uint2 vh2 = VhiS[(kv * 8 + nv) * 32 + lane];
                    mma_tf32(oc[nv], ph, vh2.x, vh2.y);
                }
            }
        }

        issue_tile(kt + 2);
    }

    // ---- finalize: normalize, transpose to A-frag order, store packed ----
    #pragma unroll
    for (int w = 1; w < 4; w <<= 1) {
        l0 += __shfl_xor_sync(0xffffffff, l0, w);
        l1 += __shfl_xor_sync(0xffffffff, l1, w);
    }
    const float inv0 = 1.0f / l0, inv1 = 1.0f / l1;
    const int rb = b * (SEQ_LEN / 128) + qt;
    uint32_t* ablk0 = APK + ((size_t)rb * KT_N + h * 2) * 4096;

    #pragma unroll
    for (int nv = 0; nv < 8; nv++) {
        float p0 = oc[nv][0] * inv0, p1 = oc[nv][1] * inv0;
        float p2 = oc[nv][2] * inv1, p3 = oc[nv][3] * inv1;
        float t00 = __shfl_sync(0xffffffff, p0, src0);
        float t01 = __shfl_sync(0xffffffff, p1, src0);
        float a0 = odd ? t01 : t00;
        float t10 = __shfl_sync(0xffffffff, p2, src0);
        float t11 = __shfl_sync(0xffffffff, p3, src0);
        float a1 = odd ? t11 : t10;
        float t20 = __shfl_sync(0xffffffff, p0, src1);
        float t21 = __shfl_sync(0xffffffff, p1, src1);
        float a2 = odd ? t21 : t20;
        float t30 = __shfl_sync(0xffffffff, p2, src1);
        float t31 = __shfl_sync(0xffffffff, p3, src1);
        float a3 = odd ? t31 : t30;
        uint4 wv = make_uint4(f2tf32(a0), f2tf32(a1), f2tf32(a2), f2tf32(a3));
        uint32_t* dst = ablk0 + (size_t)(nv >> 2) * 4096
                              + (size_t)(((nv & 3) * 8 + warp) * 32 + lane) * 4;
        *reinterpret_cast<uint4*>(dst) = wv;
    }
}

// ---------------------------------------------------------------------------
// Launch: pack prepass -> fused QKV GEMM -> pack KV -> attn (packed O)
//         -> output GEMM.
// ---------------------------------------------------------------------------
extern "C" void kernel_launch(void* const* d_in, const int* in_sizes, int n_in,
                              void* d_out, int out_size)
{
    const float* x  = (const float*)d_in[0];
    const float* Wq = (const float*)d_in[1];
    const float* bq = (const float*)d_in[2];
    const float* Wk = (const float*)d_in[3];
    const float* bk = (const float*)d_in[4];
    const float* Wv = (const float*)d_in[5];
    const float* bv = (const float*)d_in[6];
    const float* Wo = (const float*)d_in[7];
    const float* bo = (const float*)d_in[8];
    float* out = (float*)d_out;

    const int M = in_sizes[0] / D_MODEL;   // 4096
    const int B = M / SEQ_LEN;             // 2

    float *Qp, *Kp, *Vp;
    uint32_t *APKp, *WPKp, *KVPp;
    cudaGetSymbolAddress((void**)&Qp, g_Q);
    cudaGetSymbolAddress((void**)&Kp, g_K);
    cudaGetSymbolAddress((void**)&Vp, g_V);
    cudaGetSymbolAddress((void**)&APKp, g_APK);
    cudaGetSymbolAddress((void**)&WPKp, g_WPK);
    cudaGetSymbolAddress((void**)&KVPp, g_KVP);

    static bool attr_set = false;
    if (!attr_set) {
        cudaFuncSetAttribute(attn_mma_kernel,
                             cudaFuncAttributeMaxDynamicSharedMemorySize,
                             3 * STAGE_WORDS * 4);
        cudaFuncSetAttribute(gemm_qkv_kernel,
                             cudaFuncAttributeMaxDynamicSharedMemorySize,
                             3 * GW * 4);
        cudaFuncSetAttribute(gemm_tf32_bias_kernel,
                             cudaFuncAttributeMaxDynamicSharedMemorySize,
                             3 * GW * 4);
        attr_set = true;
    }

    const int gemm_smem = 3 * GW * 4;             // 98304 B
    dim3 qkv_grid(8, M / 128, 3);                 // (8, 32, 3)
    dim3 gemm_grid(8, M / 128);                   // (8, 32)
    dim3 pa_grid(KT_N, M / 128);                  // (32, 32)
    dim3 pw_grid(KT_N, 8, 4);                     // (32, 8, 4)

    // Pre-pass: fragment-pack A (x) and all 4 weight matrices.
    pack_a_kernel<<<pa_grid, 256>>>(x, APKp);
    pack_w_kernel<<<pw_grid, 256>>>(Wq, Wk, Wv, Wo, WPKp);

    // Fused QKV projections.
    gemm_qkv_kernel<<<qkv_grid, 256, gemm_smem>>>(APKp, WPKp, bq, bk, bv, Qp, Kp, Vp);

    // Pack K/V to fragment order.
    dim3 pack_grid(NTILES, B * NUM_HEADS);        // (64, 32)
    pack_kv_kernel<<<pack_grid, 512>>>(Kp, Vp, KVPp);

    // Attention: writes O directly in packed-A fragment order.
    dim3 attn_grid(SEQ_LEN / 128, B * NUM_HEADS); // (16, 32)
    attn_mma_kernel<<<attn_grid, 256, 3 * STAGE_WORDS * 4>>>(Qp, KVPp, APKp);

    // Output projection.
    gemm_tf32_bias_kernel<<<gemm_grid, 256, gemm_smem>>>(APKp, WPKp + 3 * WSTRIDE, bo, out);
}

// round 11
// speedup vs baseline: 5.4226x; 1.0081x over previous
#include <cuda_runtime.h>
#include <cstdint>

// ---------------------------------------------------------------------------
// Problem constants: x [B=2, S=2048, d=1024], H=16, Dh=64, causal MHA, fp32.
// ---------------------------------------------------------------------------
#define D_MODEL 1024
#define NUM_HEADS 16
#define D_HEAD 64
#define SEQ_LEN 2048
#define BATCH 2
#define M_ROWS (BATCH * SEQ_LEN)   // 4096
#define NT64 (SEQ_LEN / 64)        // 32 key tiles (64 keys) per (b,h)
#define STAGE_WORDS 8192           // attn: 32KB per tile [Khi 4096][Vhi 4096]
#define GW 8192                    // gemm stage words: [A 4096][B 4096] = 32KB
#define KT_N 32                    // k-tiles per GEMM (K=1024 / 32)
#define WSTRIDE ((size_t)8 * KT_N * 4096)

// Scratch (alloc-free rule: __device__ globals).
__device__ float    g_Q[M_ROWS * D_MODEL];
__device__ float    g_K[M_ROWS * D_MODEL];
__device__ float    g_V[M_ROWS * D_MODEL];
__device__ uint32_t g_APK[(size_t)(M_ROWS / 128) * KT_N * 4096];      // A frag-packed
__device__ uint32_t g_WPK[4 * WSTRIDE];                               // W frag-packed
__device__ uint32_t g_KVP[(size_t)BATCH * NUM_HEADS * NT64 * STAGE_WORDS];

__device__ __forceinline__ uint32_t f2tf32(float x) {
    uint32_t r;
    asm("cvt.rna.tf32.f32 %0, %1;" : "=r"(r) : "f"(x));
    return r;
}

__device__ __forceinline__ void mma_tf32(float c[4], const uint32_t a[4],
                                         uint32_t b0, uint32_t b1) {
    asm volatile(
        "mma.sync.aligned.m16n8k8.row.col.f32.tf32.tf32.f32 "
        "{%0,%1,%2,%3}, {%4,%5,%6,%7}, {%8,%9}, {%0,%1,%2,%3};\n"
        : "+f"(c[0]), "+f"(c[1]), "+f"(c[2]), "+f"(c[3])
        : "r"(a[0]), "r"(a[1]), "r"(a[2]), "r"(a[3]), "r"(b0), "r"(b1));
}

// ---------------------------------------------------------------------------
// pack_a: A [M_ROWS][D_MODEL] fp32 -> frag-order tf32 (x only).
// ---------------------------------------------------------------------------
__global__ __launch_bounds__(256) void pack_a_kernel(
    const float* __restrict__ A, uint32_t* __restrict__ out)
{
    __shared__ float s[128][36];
    const int kt = blockIdx.x;
    const int rb = blockIdx.y;
    const int tid = threadIdx.x;

    #pragma unroll
    for (int i = 0; i < 4; i++) {
        int idx = tid + i * 256;
        int row = idx >> 3;
        int c4  = idx & 7;
        float4 v = *reinterpret_cast<const float4*>(
            A + (size_t)(rb * 128 + row) * D_MODEL + kt * 32 + c4 * 4);
        *reinterpret_cast<float4*>(&s[row][c4 * 4]) = v;
    }
    __syncthreads();

    const int lane = tid & 31;
    const int lrow = lane >> 2, lcol = lane & 3;
    uint32_t* blk = out + ((size_t)rb * KT_N + kt) * 4096;
    #pragma unroll
    for (int i = 0; i < 4; i++) {
        int combo = (tid >> 5) + i * 8;
        int kat = combo >> 3, mt = combo & 7;
        int m0 = mt * 16, kk = kat * 8;
        uint4 w;
        w.x = f2tf32(s[m0 + lrow    ][kk + lcol    ]);
        w.y = f2tf32(s[m0 + 8 + lrow][kk + lcol    ]);
        w.z = f2tf32(s[m0 + lrow    ][kk + lcol + 4]);
        w.w = f2tf32(s[m0 + 8 + lrow][kk + lcol + 4]);
        *reinterpret_cast<uint4*>(blk + (size_t)(combo * 32 + lane) * 4) = w;
    }
}

// ---------------------------------------------------------------------------
// pack_w: W [K][N] fp32 (4 matrices) -> frag-order tf32.
// ---------------------------------------------------------------------------
__global__ __launch_bounds__(256) void pack_w_kernel(
    const float* __restrict__ w0, const float* __restrict__ w1,
    const float* __restrict__ w2, const float* __restrict__ w3,
    uint32_t* __restrict__ out)
{
    __shared__ float s[32][132];
    const float* srcs[4] = {w0, w1, w2, w3};
    const int kt  = blockIdx.x;
    const int cb  = blockIdx.y;
    const int mat = blockIdx.z;
    const int tid = threadIdx.x;
    const float* W = srcs[mat];

    #pragma unroll
    for (int i = 0; i < 4; i++) {
        int idx = tid + i * 256;
        int row = idx >> 5;
        int c4  = idx & 31;
        float4 v = *reinterpret_cast<const float4*>(
            W + (size_t)(kt * 32 + row) * D_MODEL + cb * 128 + c4 * 4);
        *reinterpret_cast<float4*>(&s[row][c4 * 4]) = v;
    }
    __syncthreads();

    const int lane = tid & 31;
    const int lrow = lane >> 2, lcol = lane & 3;
    uint32_t* blk = out + (((size_t)mat * 8 + cb) * KT_N + kt) * 4096;
    #pragma unroll
    for (int i = 0; i < 8; i++) {
        int combo = (tid >> 5) + i * 8;
        int kat = combo >> 4, nt = combo & 15;
        int kk = kat * 8, n0 = nt * 8;
        uint2 w;
        w.x = f2tf32(s[kk + lcol    ][n0 + lrow]);
        w.y = f2tf32(s[kk + lcol + 4][n0 + lrow]);
        *reinterpret_cast<uint2*>(blk + (size_t)(combo * 32 + lane) * 2) = w;
    }
}

// ---------------------------------------------------------------------------
// GEMM body: CTA 128x128, 4 warps, warp tile 64x64 (A frags reused over 8
// n-tiles, B over 4 m-tiles: stage smem reads 64KB vs 96KB at 32x64).
// ---------------------------------------------------------------------------
__device__ __forceinline__ void gemm_body(
    const uint32_t* __restrict__ Asrc, const uint32_t* __restrict__ Bsrc,
    const float* __restrict__ bias, float* __restrict__ C,
    uint32_t* gsm, int cb, int rb)
{
    const int tid  = threadIdx.x;       // 0..127
    const int lane = tid & 31;
    const int warp = tid >> 5;          // 0..3
    const int wmt = (warp & 1) * 4;     // m-tile base (of 8)
    const int wnt = (warp >> 1) * 8;    // n-tile base (of 16)
    const int lrow = lane >> 2;
    const int lcol = lane & 3;

    const uint32_t sm_addr = (uint32_t)__cvta_generic_to_shared(gsm);

    auto issue_stage = [&](int t) {
        if (t < KT_N) {
            uint32_t dst0 = sm_addr + ((t % 3) * GW) * 4;
            const uint32_t* sa = Asrc + (size_t)t * 4096;
            const uint32_t* sb = Bsrc + (size_t)t * 4096;
            #pragma unroll
            for (int c = 0; c < 8; c++) {
                uint32_t off16 = (c * 128 + tid) * 16;
                asm volatile("cp.async.cg.shared.global [%0], [%1], 16;\n"
                             :: "r"(dst0 + off16), "l"((const char*)sa + off16));
                asm volatile("cp.async.cg.shared.global [%0], [%1], 16;\n"
                             :: "r"(dst0 + 16384 + off16), "l"((const char*)sb + off16));
            }
        }
        asm volatile("cp.async.commit_group;\n");
    };

    float c[4][8][4];
    #pragma unroll
    for (int mi = 0; mi < 4; mi++)
        #pragma unroll
        for (int ni = 0; ni < 8; ni++)
            #pragma unroll
            for (int r = 0; r < 4; r++) c[mi][ni][r] = 0.0f;

    issue_stage(0);
    issue_stage(1);

    for (int t = 0; t < KT_N; t++) {
        asm volatile("cp.async.wait_group 1;\n");
        __syncthreads();

        const uint32_t* As = gsm + (t % 3) * GW;
        const uint32_t* Bs = As + 4096;

        #pragma unroll
        for (int kat = 0; kat < 4; kat++) {
            uint32_t a[4][4];
            #pragma unroll
            for (int mi = 0; mi < 4; mi++) {
                uint4 av = *reinterpret_cast<const uint4*>(
                    As + (size_t)(((kat * 8 + wmt + mi) * 32 + lane) * 4));
                a[mi][0] = av.x; a[mi][1] = av.y; a[mi][2] = av.z; a[mi][3] = av.w;
            }
            uint2 b[8];
            #pragma unroll
            for (int ni = 0; ni < 8; ni++)
                b[ni] = *reinterpret_cast<const uint2*>(
                    Bs + (size_t)(((kat * 16 + wnt + ni) * 32 + lane) * 2));
            #pragma unroll
            for (int mi = 0; mi < 4; mi++)
                #pragma unroll
                for (int ni = 0; ni < 8; ni++)
                    mma_tf32(c[mi][ni], a[mi], b[ni].x, b[ni].y);
        }

        issue_stage(t + 2);
    }

    #pragma unroll
    for (int mi = 0; mi < 4; mi++) {
        int r0 = rb * 128 + (wmt + mi) * 16 + lrow;
        #pragma unroll
        for (int ni = 0; ni < 8; ni++) {
            int col = cb * 128 + (wnt + ni) * 8 + lcol * 2;
            float b0 = bias[col];
            float b1 = bias[col + 1];
            float2 v0 = make_float2(c[mi][ni][0] + b0, c[mi][ni][1] + b1);
            float2 v1 = make_float2(c[mi][ni][2] + b0, c[mi][ni][3] + b1);
            *reinterpret_cast<float2*>(C + (size_t)r0 * D_MODEL + col) = v0;
            *reinterpret_cast<float2*>(C + (size_t)(r0 + 8) * D_MODEL + col) = v1;
        }
    }
}

// Fused QKV: gridDim.z = 3 selects weight / bias / output.
__global__ __launch_bounds__(128) void gemm_qkv_kernel(
    const uint32_t* __restrict__ APK, const uint32_t* __restrict__ WPK,
    const float* __restrict__ bq, const float* __restrict__ bk,
    const float* __restrict__ bv,
    float* __restrict__ Q, float* __restrict__ K, float* __restrict__ V)
{
    extern __shared__ __align__(16) uint32_t gsm[];
    const int cb = blockIdx.x, rb = blockIdx.y, z = blockIdx.z;
    const float* bias = (z == 0) ? bq : (z == 1) ? bk : bv;
    float* C = (z == 0) ? Q : (z == 1) ? K : V;
    gemm_body(APK + (size_t)rb * KT_N * 4096,
              WPK + (size_t)z * WSTRIDE + (size_t)cb * KT_N * 4096,
              bias, C, gsm, cb, rb);
}

// Single GEMM (output projection).
__global__ __launch_bounds__(128) void gemm_tf32_bias_kernel(
    const uint32_t* __restrict__ APK, const uint32_t* __restrict__ BPK,
    const float* __restrict__ bias, float* __restrict__ C)
{
    extern __shared__ __align__(16) uint32_t gsm[];
    gemm_body(APK + (size_t)blockIdx.y * KT_N * 4096,
              BPK + (size_t)blockIdx.x * KT_N * 4096,
              bias, C, gsm, blockIdx.x, blockIdx.y);
}

// ---------------------------------------------------------------------------
// pack_kv: K,V -> tf32 fragment-order 64-key stage images.
//   stage: [Khi 4096][Vhi 4096]
//   K word: (kd*8 + key>>3)*64 + (key&7)*8, order over dh&7: [0,4,1,5,2,6,3,7]
//   V word: 4096 + (kv*8 + dh>>3)*64 + (dh&7)*8, order over key&7 likewise
// ---------------------------------------------------------------------------
__global__ __launch_bounds__(512) void pack_kv_kernel(
    const float* __restrict__ K, const float* __restrict__ V,
    uint32_t* __restrict__ P)
{
    const int kt = blockIdx.x;       // 64-key tile
    const int bh = blockIdx.y;
    const int b  = bh >> 4;
    const int h  = bh & 15;
    const size_t base = ((size_t)b * SEQ_LEN) * D_MODEL + h * D_HEAD;
    uint32_t* blk = P + ((size_t)bh * NT64 + kt) * STAGE_WORDS;
    const int tid = threadIdx.x;

    {   // K item: key 0..63 x kd 0..7
        const int key = tid & 63;
        const int kd  = tid >> 6;
        const float* src = K + base + (size_t)(kt * 64 + key) * D_MODEL + kd * 8;
        float4 v0 = *reinterpret_cast<const float4*>(src);
        float4 v1 = *reinterpret_cast<const float4*>(src + 4);
        float e[8] = {v0.x, v0.y, v0.z, v0.w, v1.x, v1.y, v1.z, v1.w};
        uint32_t hi[8];
        #pragma unroll
        for (int i = 0; i < 8; i++) hi[i] = f2tf32(e[i]);
        uint32_t* d = blk + (kd * 8 + (key >> 3)) * 64 + (key & 7) * 8;
        *reinterpret_cast<uint4*>(d)     = make_uint4(hi[0], hi[4], hi[1], hi[5]);
        *reinterpret_cast<uint4*>(d + 4) = make_uint4(hi[2], hi[6], hi[3], hi[7]);
    }
    {   // V item: dh 0..63 x kv 0..7
        const int dh = tid & 63;
        const int kv = tid >> 6;
        float e[8];
        #pragma unroll
        for (int k = 0; k < 8; k++)
            e[k] = V[base + (size_t)(kt * 64 + kv * 8 + k) * D_MODEL + dh];
        uint32_t hi[8];
        #pragma unroll
        for (int i = 0; i < 8; i++) hi[i] = f2tf32(e[i]);
        uint32_t* d = blk + 4096 + (kv * 8 + (dh >> 3)) * 64 + (dh & 7) * 8;
        *reinterpret_cast<uint4*>(d)     = make_uint4(hi[0], hi[4], hi[1], hi[5]);
        *reinterpret_cast<uint4*>(d + 4) = make_uint4(hi[2], hi[6], hi[3], hi[7]);
    }
}

// ---------------------------------------------------------------------------
// Tensor-core flash attention, BC=64, 3-stage cp.async pipeline.
// QK 1xTF32, PV 1xTF32; exp->transpose->PV fused per 8-key group (nt==kv).
// Epilogue writes O directly in packed-A fragment order.
// ---------------------------------------------------------------------------
__global__ __launch_bounds__(256, 2) void attn_mma_kernel(
    const float* __restrict__ Q, const uint32_t* __restrict__ KVP,
    uint32_t* __restrict__ APK)
{
    extern __shared__ __align__(16) uint32_t sm[];

    const int qt   = (int)gridDim.x - 1 - (int)blockIdx.x;
    const int bh   = blockIdx.y;
    const int b    = bh >> 4;
    const int h    = bh & 15;
    const int tid  = threadIdx.x;
    const int lane = tid & 31;
    const int warp = tid >> 5;
    const int g    = lane >> 2;
    const int t    = lane & 3;

    const int wq0 = qt * 128 + warp * 16;
    const size_t base = ((size_t)b * SEQ_LEN) * D_MODEL + h * D_HEAD;
    const uint32_t* tile_base = KVP + (size_t)bh * NT64 * STAGE_WORDS;
    const uint32_t sm_addr = (uint32_t)__cvta_generic_to_shared(sm);
    const int nkt = 2 * qt + 2;      // 64-key tiles

    uint32_t qh[8][4];
    {
        const int row0 = wq0 + g, row1 = row0 + 8;
        #pragma unroll
        for (int kd = 0; kd < 8; kd++) {
            int c0 = kd * 8 + t, c1 = c0 + 4;
            qh[kd][0] = f2tf32(Q[base + (size_t)row0 * D_MODEL + c0] * 0.125f);
            qh[kd][1] = f2tf32(Q[base + (size_t)row1 * D_MODEL + c0] * 0.125f);
            qh[kd][2] = f2tf32(Q[base + (size_t)row0 * D_MODEL + c1] * 0.125f);
            qh[kd][3] = f2tf32(Q[base + (size_t)row1 * D_MODEL + c1] * 0.125f);
        }
    }

    float oc[8][4];
    #pragma unroll
    for (int nv = 0; nv < 8; nv++)
        #pragma unroll
        for (int r = 0; r < 4; r++) oc[nv][r] = 0.0f;

    float m0 = -1.0e30f, m1 = -1.0e30f;
    float l0 = 0.0f, l1 = 0.0f;

    // 32KB linear copy per tile: 8 x (256 threads x 16B).
    auto issue_tile = [&](int kt) {
        if (kt < nkt) {
            const uint32_t* src = tile_base + (size_t)kt * STAGE_WORDS + tid * 4;
            uint32_t dst = sm_addr + ((kt % 3) * STAGE_WORDS + tid * 4) * 4;
            #pragma unroll
            for (int c = 0; c < 8; c++) {
                asm volatile("cp.async.cg.shared.global [%0], [%1], 16;\n"
                             :: "r"(dst + c * 4096), "l"(src + c * 1024));
            }
        }
        asm volatile("cp.async.commit_group;\n");
    };

    issue_tile(0);
    issue_tile(1);

    const int src0 = (lane & ~3) | (t >> 1);
    const int src1 = src0 + 2;
    const bool odd = (t & 1);

    for (int kt = 0; kt < nkt; kt++) {
        asm volatile("cp.async.wait_group 1;\n");
        __syncthreads();

        const uint2* KhiS = reinterpret_cast<const uint2*>(sm + (kt % 3) * STAGE_WORDS);
        const uint2* VhiS = KhiS + 2048;
        const int k0 = kt * 64;

        if (k0 <= wq0 + 15) {
            // ---- S = QK^T (1xtf32), 8 key-groups ----
            float sc[8][4];
            #pragma unroll
            for (int nt = 0; nt < 8; nt++)
                #pragma unroll
                for (int r = 0; r < 4; r++) sc[nt][r] = 0.0f;

            #pragma unroll
            for (int kd = 0; kd < 8; kd++) {
                #pragma unroll
                for (int nt = 0; nt < 8; nt++) {
                    uint2 bh2 = KhiS[(kd * 8 + nt) * 32 + lane];
                    mma_tf32(sc[nt], qh[kd], bh2.x, bh2.y);
                }
            }

            const int row0 = wq0 + g, row1 = row0 + 8;

            if (k0 + 63 > wq0) {   // diagonal tile
                #pragma unroll
                for (int nt = 0; nt < 8; nt++) {
                    int col = k0 + nt * 8 + 2 * t;
                    if (col     > row0) sc[nt][0] = -1.0e30f;
                    if (col + 1 > row0) sc[nt][1] = -1.0e30f;
                    if (col     > row1) sc[nt][2] = -1.0e30f;
                    if (col + 1 > row1) sc[nt][3] = -1.0e30f;
                }
            }

            // ---- online softmax max/rescale ----
            float mt0 = sc[0][0], mt1 = sc[0][2];
            #pragma unroll
            for (int nt = 0; nt < 8; nt++) {
                mt0 = fmaxf(mt0, fmaxf(sc[nt][0], sc[nt][1]));
                mt1 = fmaxf(mt1, fmaxf(sc[nt][2], sc[nt][3]));
            }
            #pragma unroll
            for (int w = 1; w < 4; w <<= 1) {
                mt0 = fmaxf(mt0, __shfl_xor_sync(0xffffffff, mt0, w));
                mt1 = fmaxf(mt1, __shfl_xor_sync(0xffffffff, mt1, w));
            }
            float mn0 = fmaxf(m0, mt0), mn1 = fmaxf(m1, mt1);
            float cr0 = __expf(m0 - mn0), cr1 = __expf(m1 - mn1);
            m0 = mn0; m1 = mn1;
            l0 *= cr0; l1 *= cr1;
            #pragma unroll
            for (int nv = 0; nv < 8; nv++) {
                oc[nv][0] *= cr0; oc[nv][1] *= cr0;
                oc[nv][2] *= cr1; oc[nv][3] *= cr1;
            }

            // ---- per key-group: exp -> transpose -> PV (kv == nt) ----
            #pragma unroll
            for (int nt = 0; nt < 8; nt++) {
                float p0 = __expf(sc[nt][0] - m0);
                float p1 = __expf(sc[nt][1] - m0);
                float p2 = __expf(sc[nt][2] - m1);
                float p3 = __expf(sc[nt][3] - m1);
                l0 += p0 + p1;
                l1 += p2 + p3;

                float t00 = __shfl_sync(0xffffffff, p0, src0);
                float t01 = __shfl_sync(0xffffffff, p1, src0);
                float a0f = odd ? t01 : t00;
                float t10 = __shfl_sync(0xffffffff, p2, src0);
                float t11 = __shfl_sync(0xffffffff, p3, src0);
                float a1f = odd ? t11 : t10;
                float t20 = __shfl_sync(0xffffffff, p0, src1);
                float t21 = __shfl_sync(0xffffffff, p1, src1);
                float a2f = odd ? t21 : t20;
                float t30 = __shfl_sync(0xffffffff, p2, src1);
                float t31 = __shfl_sync(0xffffffff, p3, src1);
                float a3f = odd ? t31 : t30;

                uint32_t ph[4];
                ph[0] = f2tf32(a0f);
                ph[1] = f2tf32(a1f);
                ph[2] = f2tf32(a2f);
                ph[3] = f2tf32(a3f);

                #pragma unroll
                for (int nv = 0; nv < 8; nv++) {
                    uint2 vh2 = VhiS[(nt * 8 + nv) * 32 + lane];
                    mma_tf32(oc[nv], ph, vh2.x, vh2.y);
                }
            }
        }

        issue_tile(kt + 2);
    }

    // ---- finalize: normalize, transpose to A-frag order, store packed ----
    #pragma unroll
    for (int w = 1; w < 4; w <<= 1) {
        l0 += __shfl_xor_sync(0xffffffff, l0, w);
        l1 += __shfl_xor_sync(0xffffffff, l1, w);
    }
    const float inv0 = 1.0f / l0, inv1 = 1.0f / l1;
    const int rb = b * (SEQ_LEN / 128) + qt;
    uint32_t* ablk0 = APK + ((size_t)rb * KT_N + h * 2) * 4096;

    #pragma unroll
    for (int nv = 0; nv < 8; nv++) {
        float p0 = oc[nv][0] * inv0, p1 = oc[nv][1] * inv0;
        float p2 = oc[nv][2] * inv1, p3 = oc[nv][3] * inv1;
        float t00 = __shfl_sync(0xffffffff, p0, src0);
        float t01 = __shfl_sync(0xffffffff, p1, src0);
        float a0 = odd ? t01 : t00;
        float t10 = __shfl_sync(0xffffffff, p2, src0);
        float t11 = __shfl_sync(0xffffffff, p3, src0);
        float a1 = odd ? t11 : t10;
        float t20 = __shfl_sync(0xffffffff, p0, src1);
        float t21 = __shfl_sync(0xffffffff, p1, src1);
        float a2 = odd ? t21 : t20;
        float t30 = __shfl_sync(0xffffffff, p2, src1);
        float t31 = __shfl_sync(0xffffffff, p3, src1);
        float a3 = odd ? t31 : t30;
        uint4 wv = make_uint4(f2tf32(a0), f2tf32(a1), f2tf32(a2), f2tf32(a3));
        uint32_t* dst = ablk0 + (size_t)(nv >> 2) * 4096
                              + (size_t)(((nv & 3) * 8 + warp) * 32 + lane) * 4;
        *reinterpret_cast<uint4*>(dst) = wv;
    }
}

// ---------------------------------------------------------------------------
// Launch: pack prepass -> fused QKV GEMM -> pack KV -> attn (packed O)
//         -> output GEMM.
// ---------------------------------------------------------------------------
extern "C" void kernel_launch(void* const* d_in, const int* in_sizes, int n_in,
                              void* d_out, int out_size)
{
    const float* x  = (const float*)d_in[0];
    const float* Wq = (const float*)d_in[1];
    const float* bq = (const float*)d_in[2];
    const float* Wk = (const float*)d_in[3];
    const float* bk = (const float*)d_in[4];
    const float* Wv = (const float*)d_in[5];
    const float* bv = (const float*)d_in[6];
    const float* Wo = (const float*)d_in[7];
    const float* bo = (const float*)d_in[8];
    float* out = (float*)d_out;

    const int M = in_sizes[0] / D_MODEL;   // 4096
    const int B = M / SEQ_LEN;             // 2

    float *Qp, *Kp, *Vp;
    uint32_t *APKp, *WPKp, *KVPp;
    cudaGetSymbolAddress((void**)&Qp, g_Q);
    cudaGetSymbolAddress((void**)&Kp, g_K);
    cudaGetSymbolAddress((void**)&Vp, g_V);
    cudaGetSymbolAddress((void**)&APKp, g_APK);
    cudaGetSymbolAddress((void**)&WPKp, g_WPK);
    cudaGetSymbolAddress((void**)&KVPp, g_KVP);

    static bool attr_set = false;
    if (!attr_set) {
        cudaFuncSetAttribute(attn_mma_kernel,
                             cudaFuncAttributeMaxDynamicSharedMemorySize,
                             3 * STAGE_WORDS * 4);
        cudaFuncSetAttribute(gemm_qkv_kernel,
                             cudaFuncAttributeMaxDynamicSharedMemorySize,
                             3 * GW * 4);
        cudaFuncSetAttribute(gemm_tf32_bias_kernel,
                             cudaFuncAttributeMaxDynamicSharedMemorySize,
                             3 * GW * 4);
        attr_set = true;
    }

    const int gemm_smem = 3 * GW * 4;             // 98304 B
    dim3 qkv_grid(8, M / 128, 3);                 // (8, 32, 3)
    dim3 gemm_grid(8, M / 128);                   // (8, 32)
    dim3 pa_grid(KT_N, M / 128);                  // (32, 32)
    dim3 pw_grid(KT_N, 8, 4);                     // (32, 8, 4)

    // Pre-pass: fragment-pack A (x) and all 4 weight matrices.
    pack_a_kernel<<<pa_grid, 256>>>(x, APKp);
    pack_w_kernel<<<pw_grid, 256>>>(Wq, Wk, Wv, Wo, WPKp);

    // Fused QKV projections.
    gemm_qkv_kernel<<<qkv_grid, 128, gemm_smem>>>(APKp, WPKp, bq, bk, bv, Qp, Kp, Vp);

    // Pack K/V to 64-key fragment-order stages.
    dim3 pack_grid(NT64, B * NUM_HEADS);          // (32, 32)
    pack_kv_kernel<<<pack_grid, 512>>>(Kp, Vp, KVPp);

    // Attention: writes O directly in packed-A fragment order.
    dim3 attn_grid(SEQ_LEN / 128, B * NUM_HEADS); // (16, 32)
    attn_mma_kernel<<<attn_grid, 256, 3 * STAGE_WORDS * 4>>>(Qp, KVPp, APKp);

    // Output projection.
    gemm_tf32_bias_kernel<<<gemm_grid, 128, gemm_smem>>>(APKp, WPKp + 3 * WSTRIDE, bo, out);
}

// round 13
// speedup vs baseline: 5.5273x; 1.0193x over previous
#include <cuda_runtime.h>
#include <cstdint>

// ---------------------------------------------------------------------------
// Problem constants: x [B=2, S=2048, d=1024], H=16, Dh=64, causal MHA, fp32.
// ---------------------------------------------------------------------------
#define D_MODEL 1024
#define NUM_HEADS 16
#define D_HEAD 64
#define SEQ_LEN 2048
#define BATCH 2
#define M_ROWS (BATCH * SEQ_LEN)   // 4096
#define NT64 (SEQ_LEN / 64)        // 32 key tiles (64 keys) per (b,h)
#define STAGE_WORDS 8192           // attn: 32KB per tile [Khi 4096][Vhi 4096]
#define GW 8192                    // gemm stage words: [A 4096][B 4096] = 32KB
#define KT_N 32                    // k-tiles per GEMM (K=1024 / 32)
#define WSTRIDE ((size_t)8 * KT_N * 4096)

// Scratch (alloc-free rule: __device__ globals).
__device__ float    g_Q[M_ROWS * D_MODEL];
__device__ uint32_t g_APK[(size_t)(M_ROWS / 128) * KT_N * 4096];      // A frag-packed
__device__ uint32_t g_WPK[4 * WSTRIDE];                               // W frag-packed
__device__ uint32_t g_KVP[(size_t)BATCH * NUM_HEADS * NT64 * STAGE_WORDS];

__device__ __forceinline__ uint32_t f2tf32(float x) {
    uint32_t r;
    asm("cvt.rna.tf32.f32 %0, %1;" : "=r"(r) : "f"(x));
    return r;
}

__device__ __forceinline__ void mma_tf32(float c[4], const uint32_t a[4],
                                         uint32_t b0, uint32_t b1) {
    asm volatile(
        "mma.sync.aligned.m16n8k8.row.col.f32.tf32.tf32.f32 "
        "{%0,%1,%2,%3}, {%4,%5,%6,%7}, {%8,%9}, {%0,%1,%2,%3};\n"
        : "+f"(c[0]), "+f"(c[1]), "+f"(c[2]), "+f"(c[3])
        : "r"(a[0]), "r"(a[1]), "r"(a[2]), "r"(a[3]), "r"(b0), "r"(b1));
}

// ---------------------------------------------------------------------------
// pack_a: A [M_ROWS][D_MODEL] fp32 -> frag-order tf32 (x only).
// ---------------------------------------------------------------------------
__global__ __launch_bounds__(256) void pack_a_kernel(
    const float* __restrict__ A, uint32_t* __restrict__ out)
{
    __shared__ float s[128][36];
    const int kt = blockIdx.x;
    const int rb = blockIdx.y;
    const int tid = threadIdx.x;

    #pragma unroll
    for (int i = 0; i < 4; i++) {
        int idx = tid + i * 256;
        int row = idx >> 3;
        int c4  = idx & 7;
        float4 v = *reinterpret_cast<const float4*>(
            A + (size_t)(rb * 128 + row) * D_MODEL + kt * 32 + c4 * 4);
        *reinterpret_cast<float4*>(&s[row][c4 * 4]) = v;
    }
    __syncthreads();

    const int lane = tid & 31;
    const int lrow = lane >> 2, lcol = lane & 3;
    uint32_t* blk = out + ((size_t)rb * KT_N + kt) * 4096;
    #pragma unroll
    for (int i = 0; i < 4; i++) {
        int combo = (tid >> 5) + i * 8;
        int kat = combo >> 3, mt = combo & 7;
        int m0 = mt * 16, kk = kat * 8;
        uint4 w;
        w.x = f2tf32(s[m0 + lrow    ][kk + lcol    ]);
        w.y = f2tf32(s[m0 + 8 + lrow][kk + lcol    ]);
        w.z = f2tf32(s[m0 + lrow    ][kk + lcol + 4]);
        w.w = f2tf32(s[m0 + 8 + lrow][kk + lcol + 4]);
        *reinterpret_cast<uint4*>(blk + (size_t)(combo * 32 + lane) * 4) = w;
    }
}

// ---------------------------------------------------------------------------
// pack_w: W [K][N] fp32 (4 matrices) -> frag-order tf32.
// ---------------------------------------------------------------------------
__global__ __launch_bounds__(256) void pack_w_kernel(
    const float* __restrict__ w0, const float* __restrict__ w1,
    const float* __restrict__ w2, const float* __restrict__ w3,
    uint32_t* __restrict__ out)
{
    __shared__ float s[32][132];
    const float* srcs[4] = {w0, w1, w2, w3};
    const int kt  = blockIdx.x;
    const int cb  = blockIdx.y;
    const int mat = blockIdx.z;
    const int tid = threadIdx.x;
    const float* W = srcs[mat];

    #pragma unroll
    for (int i = 0; i < 4; i++) {
        int idx = tid + i * 256;
        int row = idx >> 5;
        int c4  = idx & 31;
        float4 v = *reinterpret_cast<const float4*>(
            W + (size_t)(kt * 32 + row) * D_MODEL + cb * 128 + c4 * 4);
        *reinterpret_cast<float4*>(&s[row][c4 * 4]) = v;
    }
    __syncthreads();

    const int lane = tid & 31;
    const int lrow = lane >> 2, lcol = lane & 3;
    uint32_t* blk = out + (((size_t)mat * 8 + cb) * KT_N + kt) * 4096;
    #pragma unroll
    for (int i = 0; i < 8; i++) {
        int combo = (tid >> 5) + i * 8;
        int kat = combo >> 4, nt = combo & 15;
        int kk = kat * 8, n0 = nt * 8;
        uint2 w;
        w.x = f2tf32(s[kk + lcol    ][n0 + lrow]);
        w.y = f2tf32(s[kk + lcol + 4][n0 + lrow]);
        *reinterpret_cast<uint2*>(blk + (size_t)(combo * 32 + lane) * 2) = w;
    }
}

// ---------------------------------------------------------------------------
// GEMM body (R9 config: 256 threads, 8 warps, 32x64 warp tile — measured
// 49.7us). mode 0: store C fp32 row-major. mode 1: store K directly into
// packed 64-key fragment layout. mode 2: same for V.
// ---------------------------------------------------------------------------
__device__ __forceinline__ void gemm_body(
    const uint32_t* __restrict__ Asrc, const uint32_t* __restrict__ Bsrc,
    const float* __restrict__ bias, float* __restrict__ C,
    uint32_t* __restrict__ KVpk, int mode,
    uint32_t* gsm, int cb, int rb)
{
    const int tid  = threadIdx.x;
    const int lane = tid & 31;
    const int warp = tid >> 5;
    const int wmt = (warp & 3) * 2;    // m-tile base (of 8)
    const int wnt = (warp >> 2) * 8;   // n-tile base (of 16)
    const int lrow = lane >> 2;
    const int lcol = lane & 3;

    const uint32_t sm_addr = (uint32_t)__cvta_generic_to_shared(gsm);

    auto issue_stage = [&](int t) {
        if (t < KT_N) {
            uint32_t dst0 = sm_addr + ((t % 3) * GW) * 4;
            const uint32_t* sa = Asrc + (size_t)t * 4096;
            const uint32_t* sb = Bsrc + (size_t)t * 4096;
            #pragma unroll
            for (int c = 0; c < 4; c++) {
                uint32_t off16 = (c * 256 + tid) * 16;
                asm volatile("cp.async.cg.shared.global [%0], [%1], 16;\n"
                             :: "r"(dst0 + off16), "l"((const char*)sa + off16));
                asm volatile("cp.async.cg.shared.global [%0], [%1], 16;\n"
                             :: "r"(dst0 + 16384 + off16), "l"((const char*)sb + off16));
            }
        }
        asm volatile("cp.async.commit_group;\n");
    };

    float c[2][8][4];
    #pragma unroll
    for (int mi = 0; mi < 2; mi++)
        #pragma unroll
        for (int ni = 0; ni < 8; ni++)
            #pragma unroll
            for (int r = 0; r < 4; r++) c[mi][ni][r] = 0.0f;

    issue_stage(0);
    issue_stage(1);

    for (int t = 0; t < KT_N; t++) {
        asm volatile("cp.async.wait_group 1;\n");
        __syncthreads();

        const uint32_t* As = gsm + (t % 3) * GW;
        const uint32_t* Bs = As + 4096;

        #pragma unroll
        for (int kat = 0; kat < 4; kat++) {
            uint32_t a[2][4];
            #pragma unroll
            for (int mi = 0; mi < 2; mi++) {
                uint4 av = *reinterpret_cast<const uint4*>(
                    As + (size_t)(((kat * 8 + wmt + mi) * 32 + lane) * 4));
                a[mi][0] = av.x; a[mi][1] = av.y; a[mi][2] = av.z; a[mi][3] = av.w;
            }
            uint2 b[8];
            #pragma unroll
            for (int ni = 0; ni < 8; ni++)
                b[ni] = *reinterpret_cast<const uint2*>(
                    Bs + (size_t)(((kat * 16 + wnt + ni) * 32 + lane) * 2));
            #pragma unroll
            for (int mi = 0; mi < 2; mi++)
                #pragma unroll
                for (int ni = 0; ni < 8; ni++)
                    mma_tf32(c[mi][ni], a[mi], b[ni].x, b[ni].y);
        }

        issue_stage(t + 2);
    }

    if (mode == 0) {
        #pragma unroll
        for (int mi = 0; mi < 2; mi++) {
            int r0 = rb * 128 + (wmt + mi) * 16 + lrow;
            #pragma unroll
            for (int ni = 0; ni < 8; ni++) {
                int col = cb * 128 + (wnt + ni) * 8 + lcol * 2;
                float b0 = bias[col];
                float b1 = bias[col + 1];
                float2 v0 = make_float2(c[mi][ni][0] + b0, c[mi][ni][1] + b1);
                float2 v1 = make_float2(c[mi][ni][2] + b0, c[mi][ni][3] + b1);
                *reinterpret_cast<float2*>(C + (size_t)r0 * D_MODEL + col) = v0;
                *reinterpret_cast<float2*>(C + (size_t)(r0 + 8) * D_MODEL + col) = v1;
            }
        }
    } else {
        // Direct packed K/V store (bit-identical to pack_kv of fp32 C+bias).
        const int j0 = (lcol >> 1) + (lcol & 1) * 4;   // K word slot for e=2*lcol
        #pragma unroll
        for (int mi = 0; mi < 2; mi++) {
            #pragma unroll
            for (int ni = 0; ni < 8; ni++) {
                int colbase = cb * 128 + (wnt + ni) * 8 + lcol * 2;
                int h   = colbase >> 6;
                int dh0 = colbase & 63;
                int kd  = dh0 >> 3;
                float b0 = bias[colbase];
                float b1 = bias[colbase + 1];
                #pragma unroll
                for (int rr = 0; rr < 2; rr++) {
                    int r = rb * 128 + (wmt + mi) * 16 + lrow + rr * 8;
                    float v0 = c[mi][ni][rr * 2 + 0] + b0;
                    float v1 = c[mi][ni][rr * 2 + 1] + b1;
                    int b   = r >> 11;
                    int s   = r & 2047;
                    int key = s & 63;
                    uint32_t* blk = KVpk +
                        ((size_t)(b * 16 + h) * NT64 + (s >> 6)) * STAGE_WORDS;
                    if (mode == 1) {
                        uint32_t* d = blk + ((kd * 8 + (key >> 3)) * 64 + (key & 7) * 8);
                        d[j0]     = f2tf32(v0);
                        d[j0 + 2] = f2tf32(v1);
                    } else {
                        int k7 = key & 7;
                        int jv = (k7 & 3) * 2 + (k7 >> 2);
                        uint32_t* d = blk + 4096 +
                            (((key >> 3) * 8 + kd) * 64 + (dh0 & 7) * 8) + jv;
                        d[0] = f2tf32(v0);
                        d[8] = f2tf32(v1);
                    }
                }
            }
        }
    }
}

// Fused QKV: gridDim.z = 3 selects weight / bias / output mode.
__global__ __launch_bounds__(256) void gemm_qkv_kernel(
    const uint32_t* __restrict__ APK, const uint32_t* __restrict__ WPK,
    const float* __restrict__ bq, const float* __restrict__ bk,
    const float* __restrict__ bv,
    float* __restrict__ Q, uint32_t* __restrict__ KVpk)
{
    extern __shared__ __align__(16) uint32_t gsm[];
    const int cb = blockIdx.x, rb = blockIdx.y, z = blockIdx.z;
    const float* bias = (z == 0) ? bq : (z == 1) ? bk : bv;
    gemm_body(APK + (size_t)rb * KT_N * 4096,
              WPK + (size_t)z * WSTRIDE + (size_t)cb * KT_N * 4096,
              bias, Q, KVpk, z, gsm, cb, rb);
}

// Single GEMM (output projection, mode 0).
__global__ __launch_bounds__(256) void gemm_out_kernel(
    const uint32_t* __restrict__ APK, const uint32_t* __restrict__ BPK,
    const float* __restrict__ bias, float* __restrict__ C)
{
    extern __shared__ __align__(16) uint32_t gsm[];
    gemm_body(APK + (size_t)blockIdx.y * KT_N * 4096,
              BPK + (size_t)blockIdx.x * KT_N * 4096,
              bias, C, nullptr, 0, gsm, blockIdx.x, blockIdx.y);
}

// ---------------------------------------------------------------------------
// Tensor-core flash attention, BC=64 (R10, passing). QK 1xTF32, PV 1xTF32.
// Epilogue writes O directly in packed-A fragment order.
// ---------------------------------------------------------------------------
__global__ __launch_bounds__(256, 2) void attn_mma_kernel(
    const float* __restrict__ Q, const uint32_t* __restrict__ KVP,
    uint32_t* __restrict__ APK)
{
    extern __shared__ __align__(16) uint32_t sm[];

    const int qt   = (int)gridDim.x - 1 - (int)blockIdx.x;
    const int bh   = blockIdx.y;
    const int b    = bh >> 4;
    const int h    = bh & 15;
    const int tid  = threadIdx.x;
    const int lane = tid & 31;
    const int warp = tid >> 5;
    const int g    = lane >> 2;
    const int t    = lane & 3;

    const int wq0 = qt * 128 + warp * 16;
    const size_t base = ((size_t)b * SEQ_LEN) * D_MODEL + h * D_HEAD;
    const uint32_t* tile_base = KVP + (size_t)bh * NT64 * STAGE_WORDS;
    const uint32_t sm_addr = (uint32_t)__cvta_generic_to_shared(sm);
    const int nkt = 2 * qt + 2;

    uint32_t qh[8][4];
    {
        const int row0 = wq0 + g, row1 = row0 + 8;
        #pragma unroll
        for (int kd = 0; kd < 8; kd++) {
            int c0 = kd * 8 + t, c1 = c0 + 4;
            qh[kd][0] = f2tf32(Q[base + (size_t)row0 * D_MODEL + c0] * 0.125f);
            qh[kd][1] = f2tf32(Q[base + (size_t)row1 * D_MODEL + c0] * 0.125f);
            qh[kd][2] = f2tf32(Q[base + (size_t)row0 * D_MODEL + c1] * 0.125f);
            qh[kd][3] = f2tf32(Q[base + (size_t)row1 * D_MODEL + c1] * 0.125f);
        }
    }

    float oc[8][4];
    #pragma unroll
    for (int nv = 0; nv < 8; nv++)
        #pragma unroll
        for (int r = 0; r < 4; r++) oc[nv][r] = 0.0f;

    float m0 = -1.0e30f, m1 = -1.0e30f;
    float l0 = 0.0f, l1 = 0.0f;

    auto issue_tile = [&](int kt) {
        if (kt < nkt) {
            const uint32_t* src = tile_base + (size_t)kt * STAGE_WORDS + tid * 4;
            uint32_t dst = sm_addr + ((kt % 3) * STAGE_WORDS + tid * 4) * 4;
            #pragma unroll
            for (int c = 0; c < 8; c++) {
                asm volatile("cp.async.cg.shared.global [%0], [%1], 16;\n"
                             :: "r"(dst + c * 4096), "l"(src + c * 1024));
            }
        }
        asm volatile("cp.async.commit_group;\n");
    };

    issue_tile(0);
    issue_tile(1);

    const int src0 = (lane & ~3) | (t >> 1);
    const int src1 = src0 + 2;
    const bool odd = (t & 1);

    for (int kt = 0; kt < nkt; kt++) {
        asm volatile("cp.async.wait_group 1;\n");
        __syncthreads();

        const uint2* KhiS = reinterpret_cast<const uint2*>(sm + (kt % 3) * STAGE_WORDS);
        const uint2* VhiS = KhiS + 2048;
        const int k0 = kt * 64;

        if (k0 <= wq0 + 15) {
            float sc[8][4];
            #pragma unroll
            for (int nt = 0; nt < 8; nt++)
                #pragma unroll
                for (int r = 0; r < 4; r++) sc[nt][r] = 0.0f;

            #pragma unroll
            for (int kd = 0; kd < 8; kd++) {
                #pragma unroll
                for (int nt = 0; nt < 8; nt++) {
                    uint2 bh2 = KhiS[(kd * 8 + nt) * 32 + lane];
                    mma_tf32(sc[nt], qh[kd], bh2.x, bh2.y);
                }
            }

            const int row0 = wq0 + g, row1 = row0 + 8;

            if (k0 + 63 > wq0) {
                #pragma unroll
                for (int nt = 0; nt < 8; nt++) {
                    int col = k0 + nt * 8 + 2 * t;
                    if (col     > row0) sc[nt][0] = -1.0e30f;
                    if (col + 1 > row0) sc[nt][1] = -1.0e30f;
                    if (col     > row1) sc[nt][2] = -1.0e30f;
                    if (col + 1 > row1) sc[nt][3] = -1.0e30f;
                }
            }

            float mt0 = sc[0][0], mt1 = sc[0][2];
            #pragma unroll
            for (int nt = 0; nt < 8; nt++) {
                mt0 = fmaxf(mt0, fmaxf(sc[nt][0], sc[nt][1]));
                mt1 = fmaxf(mt1, fmaxf(sc[nt][2], sc[nt][3]));
            }
            #pragma unroll
            for (int w = 1; w < 4; w <<= 1) {
                mt0 = fmaxf(mt0, __shfl_xor_sync(0xffffffff, mt0, w));
                mt1 = fmaxf(mt1, __shfl_xor_sync(0xffffffff, mt1, w));
            }
            float mn0 = fmaxf(m0, mt0), mn1 = fmaxf(m1, mt1);
            float cr0 = __expf(m0 - mn0), cr1 = __expf(m1 - mn1);
            m0 = mn0; m1 = mn1;
            l0 *= cr0; l1 *= cr1;
            #pragma unroll
            for (int nv = 0; nv < 8; nv++) {
                oc[nv][0] *= cr0; oc[nv][1] *= cr0;
                oc[nv][2] *= cr1; oc[nv][3] *= cr1;
            }

            #pragma unroll
            for (int nt = 0; nt < 8; nt++) {
                float p0 = __expf(sc[nt][0] - m0);
                float p1 = __expf(sc[nt][1] - m0);
                float p2 = __expf(sc[nt][2] - m1);
                float p3 = __expf(sc[nt][3] - m1);
                l0 += p0 + p1;
                l1 += p2 + p3;

                float t00 = __shfl_sync(0xffffffff, p0, src0);
                float t01 = __shfl_sync(0xffffffff, p1, src0);
                float a0f = odd ? t01 : t00;
                float t10 = __shfl_sync(0xffffffff, p2, src0);
                float t11 = __shfl_sync(0xffffffff, p3, src0);
                float a1f = odd ? t11 : t10;
                float t20 = __shfl_sync(0xffffffff, p0, src1);
                float t21 = __shfl_sync(0xffffffff, p1, src1);
                float a2f = odd ? t21 : t20;
                float t30 = __shfl_sync(0xffffffff, p2, src1);
                float t31 = __shfl_sync(0xffffffff, p3, src1);
                float a3f = odd ? t31 : t30;

                uint32_t ph[4];
                ph[0] = f2tf32(a0f);
                ph[1] = f2tf32(a1f);
                ph[2] = f2tf32(a2f);
                ph[3] = f2tf32(a3f);

                #pragma unroll
                for (int nv = 0; nv < 8; nv++) {
                    uint2 vh2 = VhiS[(nt * 8 + nv) * 32 + lane];
                    mma_tf32(oc[nv], ph, vh2.x, vh2.y);
                }
            }
        }

        issue_tile(kt + 2);
    }

    // ---- finalize: normalize, transpose to A-frag order, store packed ----
    #pragma unroll
    for (int w = 1; w < 4; w <<= 1) {
        l0 += __shfl_xor_sync(0xffffffff, l0, w);
        l1 += __shfl_xor_sync(0xffffffff, l1, w);
    }
    const float inv0 = 1.0f / l0, inv1 = 1.0f / l1;
    const int rb = b * (SEQ_LEN / 128) + qt;
    uint32_t* ablk0 = APK + ((size_t)rb * KT_N + h * 2) * 4096;

    #pragma unroll
    for (int nv = 0; nv < 8; nv++) {
        float p0 = oc[nv][0] * inv0, p1 = oc[nv][1] * inv0;
        float p2 = oc[nv][2] * inv1, p3 = oc[nv][3] * inv1;
        float t00 = __shfl_sync(0xffffffff, p0, src0);
        float t01 = __shfl_sync(0xffffffff, p1, src0);
        float a0 = odd ? t01 : t00;
        float t10 = __shfl_sync(0xffffffff, p2, src0);
        float t11 = __shfl_sync(0xffffffff, p3, src0);
        float a1 = odd ? t11 : t10;
        float t20 = __shfl_sync(0xffffffff, p0, src1);
        float t21 = __shfl_sync(0xffffffff, p1, src1);
        float a2 = odd ? t21 : t20;
        float t30 = __shfl_sync(0xffffffff, p2, src1);
        float t31 = __shfl_sync(0xffffffff, p3, src1);
        float a3 = odd ? t31 : t30;
        uint4 wv = make_uint4(f2tf32(a0), f2tf32(a1), f2tf32(a2), f2tf32(a3));
        uint32_t* dst = ablk0 + (size_t)(nv >> 2) * 4096
                              + (size_t)(((nv & 3) * 8 + warp) * 32 + lane) * 4;
        *reinterpret_cast<uint4*>(dst) = wv;
    }
}

// ---------------------------------------------------------------------------
// Launch: pack prepass -> fused QKV GEMM (K/V packed directly) -> attn
//         (packed O) -> output GEMM.
// ---------------------------------------------------------------------------
extern "C" void kernel_launch(void* const* d_in, const int* in_sizes, int n_in,
                              void* d_out, int out_size)
{
    const float* x  = (const float*)d_in[0];
    const float* Wq = (const float*)d_in[1];
    const float* bq = (const float*)d_in[2];
    const float* Wk = (const float*)d_in[3];
    const float* bk = (const float*)d_in[4];
    const float* Wv = (const float*)d_in[5];
    const float* bv = (const float*)d_in[6];
    const float* Wo = (const float*)d_in[7];
    const float* bo = (const float*)d_in[8];
    float* out = (float*)d_out;

    const int M = in_sizes[0] / D_MODEL;   // 4096
    const int B = M / SEQ_LEN;             // 2

    float* Qp;
    uint32_t *APKp, *WPKp, *KVPp;
    cudaGetSymbolAddress((void**)&Qp, g_Q);
    cudaGetSymbolAddress((void**)&APKp, g_APK);
    cudaGetSymbolAddress((void**)&WPKp, g_WPK);
    cudaGetSymbolAddress((void**)&KVPp, g_KVP);

    static bool attr_set = false;
    if (!attr_set) {
        cudaFuncSetAttribute(attn_mma_kernel,
                             cudaFuncAttributeMaxDynamicSharedMemorySize,
                             3 * STAGE_WORDS * 4);
        cudaFuncSetAttribute(gemm_qkv_kernel,
                             cudaFuncAttributeMaxDynamicSharedMemorySize,
                             3 * GW * 4);
        cudaFuncSetAttribute(gemm_out_kernel,
                             cudaFuncAttributeMaxDynamicSharedMemorySize,
                             3 * GW * 4);
        attr_set = true;
    }

    const int gemm_smem = 3 * GW * 4;             // 98304 B
    dim3 qkv_grid(8, M / 128, 3);                 // (8, 32, 3)
    dim3 gemm_grid(8, M / 128);                   // (8, 32)
    dim3 pa_grid(KT_N, M / 128);                  // (32, 32)
    dim3 pw_grid(KT_N, 8, 4);                     // (32, 8, 4)

    // Pre-pass: fragment-pack A (x) and all 4 weight matrices.
    pack_a_kernel<<<pa_grid, 256>>>(x, APKp);
    pack_w_kernel<<<pw_grid, 256>>>(Wq, Wk, Wv, Wo, WPKp);

    // Fused QKV projections; K and V written directly in packed KV layout.
    gemm_qkv_kernel<<<qkv_grid, 256, gemm_smem>>>(APKp, WPKp, bq, bk, bv, Qp, KVPp);

    // Attention: writes O directly in packed-A fragment order.
    dim3 attn_grid(SEQ_LEN / 128, B * NUM_HEADS); // (16, 32)
    attn_mma_kernel<<<attn_grid, 256, 3 * STAGE_WORDS * 4>>>(Qp, KVPp, APKp);

    // Output projection.
    gemm_out_kernel<<<gemm_grid, 256, gemm_smem>>>(APKp, WPKp + 3 * WSTRIDE, bo, out);
}

// round 14
// speedup vs baseline: 5.9241x; 1.0718x over previous
#include <cuda_runtime.h>
#include <cstdint>

// ---------------------------------------------------------------------------
// Problem constants: x [B=2, S=2048, d=1024], H=16, Dh=64, causal MHA, fp32.
// ---------------------------------------------------------------------------
#define D_MODEL 1024
#define NUM_HEADS 16
#define D_HEAD 64
#define SEQ_LEN 2048
#define BATCH 2
#define M_ROWS (BATCH * SEQ_LEN)   // 4096
#define NT64 (SEQ_LEN / 64)        // 32 key tiles (64 keys) per (b,h)
#define STAGE_WORDS 8192           // attn: 32KB per tile [Khi 4096][Vhi 4096]
#define GW 8192                    // gemm stage words: [A 4096][B 4096] = 32KB
#define KT_N 32                    // k-tiles per GEMM (K=1024 / 32)
#define WSTRIDE ((size_t)8 * KT_N * 4096)

// Scratch (alloc-free rule: __device__ globals).
__device__ float    g_Q[M_ROWS * D_MODEL];
__device__ uint32_t g_APK[(size_t)(M_ROWS / 128) * KT_N * 4096];      // A frag-packed
__device__ uint32_t g_WPK[4 * WSTRIDE];                               // W frag-packed
__device__ uint32_t g_KVP[(size_t)BATCH * NUM_HEADS * NT64 * STAGE_WORDS];

__device__ __forceinline__ uint32_t f2tf32(float x) {
    uint32_t r;
    asm("cvt.rna.tf32.f32 %0, %1;" : "=r"(r) : "f"(x));
    return r;
}

__device__ __forceinline__ void mma_tf32(float c[4], const uint32_t a[4],
                                         uint32_t b0, uint32_t b1) {
    asm volatile(
        "mma.sync.aligned.m16n8k8.row.col.f32.tf32.tf32.f32 "
        "{%0,%1,%2,%3}, {%4,%5,%6,%7}, {%8,%9}, {%0,%1,%2,%3};\n"
        : "+f"(c[0]), "+f"(c[1]), "+f"(c[2]), "+f"(c[3])
        : "r"(a[0]), "r"(a[1]), "r"(a[2]), "r"(a[3]), "r"(b0), "r"(b1));
}

// ---------------------------------------------------------------------------
// pack_a: A [M_ROWS][D_MODEL] fp32 -> frag-order tf32 (x only).
// ---------------------------------------------------------------------------
__global__ __launch_bounds__(256) void pack_a_kernel(
    const float* __restrict__ A, uint32_t* __restrict__ out)
{
    __shared__ float s[128][36];
    const int kt = blockIdx.x;
    const int rb = blockIdx.y;
    const int tid = threadIdx.x;

    #pragma unroll
    for (int i = 0; i < 4; i++) {
        int idx = tid + i * 256;
        int row = idx >> 3;
        int c4  = idx & 7;
        float4 v = *reinterpret_cast<const float4*>(
            A + (size_t)(rb * 128 + row) * D_MODEL + kt * 32 + c4 * 4);
        *reinterpret_cast<float4*>(&s[row][c4 * 4]) = v;
    }
    __syncthreads();

    const int lane = tid & 31;
    const int lrow = lane >> 2, lcol = lane & 3;
    uint32_t* blk = out + ((size_t)rb * KT_N + kt) * 4096;
    #pragma unroll
    for (int i = 0; i < 4; i++) {
        int combo = (tid >> 5) + i * 8;
        int kat = combo >> 3, mt = combo & 7;
        int m0 = mt * 16, kk = kat * 8;
        uint4 w;
        w.x = f2tf32(s[m0 + lrow    ][kk + lcol    ]);
        w.y = f2tf32(s[m0 + 8 + lrow][kk + lcol    ]);
        w.z = f2tf32(s[m0 + lrow    ][kk + lcol + 4]);
        w.w = f2tf32(s[m0 + 8 + lrow][kk + lcol + 4]);
        *reinterpret_cast<uint4*>(blk + (size_t)(combo * 32 + lane) * 4) = w;
    }
}

// ---------------------------------------------------------------------------
// pack_w: W [K][N] fp32 (4 matrices) -> frag-order tf32.
// ---------------------------------------------------------------------------
__global__ __launch_bounds__(256) void pack_w_kernel(
    const float* __restrict__ w0, const float* __restrict__ w1,
    const float* __restrict__ w2, const float* __restrict__ w3,
    uint32_t* __restrict__ out)
{
    __shared__ float s[32][132];
    const float* srcs[4] = {w0, w1, w2, w3};
    const int kt  = blockIdx.x;
    const int cb  = blockIdx.y;
    const int mat = blockIdx.z;
    const int tid = threadIdx.x;
    const float* W = srcs[mat];

    #pragma unroll
    for (int i = 0; i < 4; i++) {
        int idx = tid + i * 256;
        int row = idx >> 5;
        int c4  = idx & 31;
        float4 v = *reinterpret_cast<const float4*>(
            W + (size_t)(kt * 32 + row) * D_MODEL + cb * 128 + c4 * 4);
        *reinterpret_cast<float4*>(&s[row][c4 * 4]) = v;
    }
    __syncthreads();

    const int lane = tid & 31;
    const int lrow = lane >> 2, lcol = lane & 3;
    uint32_t* blk = out + (((size_t)mat * 8 + cb) * KT_N + kt) * 4096;
    #pragma unroll
    for (int i = 0; i < 8; i++) {
        int combo = (tid >> 5) + i * 8;
        int kat = combo >> 4, nt = combo & 15;
        int kk = kat * 8, n0 = nt * 8;
        uint2 w;
        w.x = f2tf32(s[kk + lcol    ][n0 + lrow]);
        w.y = f2tf32(s[kk + lcol + 4][n0 + lrow]);
        *reinterpret_cast<uint2*>(blk + (size_t)(combo * 32 + lane) * 2) = w;
    }
}

// ---------------------------------------------------------------------------
// GEMM body (R9 config, passing). mode 0: fp32 row-major C. mode 1/2: K/V
// written directly in packed 64-key fragment layout (bit-identical).
// ---------------------------------------------------------------------------
__device__ __forceinline__ void gemm_body(
    const uint32_t* __restrict__ Asrc, const uint32_t* __restrict__ Bsrc,
    const float* __restrict__ bias, float* __restrict__ C,
    uint32_t* __restrict__ KVpk, int mode,
    uint32_t* gsm, int cb, int rb)
{
    const int tid  = threadIdx.x;
    const int lane = tid & 31;
    const int warp = tid >> 5;
    const int wmt = (warp & 3) * 2;
    const int wnt = (warp >> 2) * 8;
    const int lrow = lane >> 2;
    const int lcol = lane & 3;

    const uint32_t sm_addr = (uint32_t)__cvta_generic_to_shared(gsm);

    auto issue_stage = [&](int t) {
        if (t < KT_N) {
            uint32_t dst0 = sm_addr + ((t % 3) * GW) * 4;
            const uint32_t* sa = Asrc + (size_t)t * 4096;
            const uint32_t* sb = Bsrc + (size_t)t * 4096;
            #pragma unroll
            for (int c = 0; c < 4; c++) {
                uint32_t off16 = (c * 256 + tid) * 16;
                asm volatile("cp.async.cg.shared.global [%0], [%1], 16;\n"
                             :: "r"(dst0 + off16), "l"((const char*)sa + off16));
                asm volatile("cp.async.cg.shared.global [%0], [%1], 16;\n"
                             :: "r"(dst0 + 16384 + off16), "l"((const char*)sb + off16));
            }
        }
        asm volatile("cp.async.commit_group;\n");
    };

    float c[2][8][4];
    #pragma unroll
    for (int mi = 0; mi < 2; mi++)
        #pragma unroll
        for (int ni = 0; ni < 8; ni++)
            #pragma unroll
            for (int r = 0; r < 4; r++) c[mi][ni][r] = 0.0f;

    issue_stage(0);
    issue_stage(1);

    for (int t = 0; t < KT_N; t++) {
        asm volatile("cp.async.wait_group 1;\n");
        __syncthreads();

        const uint32_t* As = gsm + (t % 3) * GW;
        const uint32_t* Bs = As + 4096;

        #pragma unroll
        for (int kat = 0; kat < 4; kat++) {
            uint32_t a[2][4];
            #pragma unroll
            for (int mi = 0; mi < 2; mi++) {
                uint4 av = *reinterpret_cast<const uint4*>(
                    As + (size_t)(((kat * 8 + wmt + mi) * 32 + lane) * 4));
                a[mi][0] = av.x; a[mi][1] = av.y; a[mi][2] = av.z; a[mi][3] = av.w;
            }
            uint2 b[8];
            #pragma unroll
            for (int ni = 0; ni < 8; ni++)
                b[ni] = *reinterpret_cast<const uint2*>(
                    Bs + (size_t)(((kat * 16 + wnt + ni) * 32 + lane) * 2));
            #pragma unroll
            for (int mi = 0; mi < 2; mi++)
                #pragma unroll
                for (int ni = 0; ni < 8; ni++)
                    mma_tf32(c[mi][ni], a[mi], b[ni].x, b[ni].y);
        }

        issue_stage(t + 2);
    }

    if (mode == 0) {
        #pragma unroll
        for (int mi = 0; mi < 2; mi++) {
            int r0 = rb * 128 + (wmt + mi) * 16 + lrow;
            #pragma unroll
            for (int ni = 0; ni < 8; ni++) {
                int col = cb * 128 + (wnt + ni) * 8 + lcol * 2;
                float b0 = bias[col];
                float b1 = bias[col + 1];
                float2 v0 = make_float2(c[mi][ni][0] + b0, c[mi][ni][1] + b1);
                float2 v1 = make_float2(c[mi][ni][2] + b0, c[mi][ni][3] + b1);
                *reinterpret_cast<float2*>(C + (size_t)r0 * D_MODEL + col) = v0;
                *reinterpret_cast<float2*>(C + (size_t)(r0 + 8) * D_MODEL + col) = v1;
            }
        }
    } else {
        const int j0 = (lcol >> 1) + (lcol & 1) * 4;
        #pragma unroll
        for (int mi = 0; mi < 2; mi++) {
            #pragma unroll
            for (int ni = 0; ni < 8; ni++) {
                int colbase = cb * 128 + (wnt + ni) * 8 + lcol * 2;
                int h   = colbase >> 6;
                int dh0 = colbase & 63;
                int kd  = dh0 >> 3;
                float b0 = bias[colbase];
                float b1 = bias[colbase + 1];
                #pragma unroll
                for (int rr = 0; rr < 2; rr++) {
                    int r = rb * 128 + (wmt + mi) * 16 + lrow + rr * 8;
                    float v0 = c[mi][ni][rr * 2 + 0] + b0;
                    float v1 = c[mi][ni][rr * 2 + 1] + b1;
                    int b   = r >> 11;
                    int s   = r & 2047;
                    int key = s & 63;
                    uint32_t* blk = KVpk +
                        ((size_t)(b * 16 + h) * NT64 + (s >> 6)) * STAGE_WORDS;
                    if (mode == 1) {
                        uint32_t* d = blk + ((kd * 8 + (key >> 3)) * 64 + (key & 7) * 8);
                        d[j0]     = f2tf32(v0);
                        d[j0 + 2] = f2tf32(v1);
                    } else {
                        int k7 = key & 7;
                        int jv = (k7 & 3) * 2 + (k7 >> 2);
                        uint32_t* d = blk + 4096 +
                            (((key >> 3) * 8 + kd) * 64 + (dh0 & 7) * 8) + jv;
                        d[0] = f2tf32(v0);
                        d[8] = f2tf32(v1);
                    }
                }
            }
        }
    }
}

__global__ __launch_bounds__(256) void gemm_qkv_kernel(
    const uint32_t* __restrict__ APK, const uint32_t* __restrict__ WPK,
    const float* __restrict__ bq, const float* __restrict__ bk,
    const float* __restrict__ bv,
    float* __restrict__ Q, uint32_t* __restrict__ KVpk)
{
    extern __shared__ __align__(16) uint32_t gsm[];
    const int cb = blockIdx.x, rb = blockIdx.y, z = blockIdx.z;
    const float* bias = (z == 0) ? bq : (z == 1) ? bk : bv;
    gemm_body(APK + (size_t)rb * KT_N * 4096,
              WPK + (size_t)z * WSTRIDE + (size_t)cb * KT_N * 4096,
              bias, Q, KVpk, z, gsm, cb, rb);
}

__global__ __launch_bounds__(256) void gemm_out_kernel(
    const uint32_t* __restrict__ APK, const uint32_t* __restrict__ BPK,
    const float* __restrict__ bias, float* __restrict__ C)
{
    extern __shared__ __align__(16) uint32_t gsm[];
    gemm_body(APK + (size_t)blockIdx.y * KT_N * 4096,
              BPK + (size_t)blockIdx.x * KT_N * 4096,
              bias, C, nullptr, 0, gsm, blockIdx.x, blockIdx.y);
}

// ---------------------------------------------------------------------------
// Tensor-core flash attention, BC=64; warp owns 32 queries (2 m-tiles):
// each K/V fragment LDS feeds 2 MMAs -> SMEM traffic halved vs R12.
// CTA = 4 warps x 32 queries = 128 queries; 128 threads.
// ---------------------------------------------------------------------------
__global__ __launch_bounds__(128, 2) void attn_mma_kernel(
    const float* __restrict__ Q, const uint32_t* __restrict__ KVP,
    uint32_t* __restrict__ APK)
{
    extern __shared__ __align__(16) uint32_t sm[];

    const int qt   = (int)gridDim.x - 1 - (int)blockIdx.x;
    const int bh   = blockIdx.y;
    const int b    = bh >> 4;
    const int h    = bh & 15;
    const int tid  = threadIdx.x;
    const int lane = tid & 31;
    const int warp = tid >> 5;       // 0..3
    const int g    = lane >> 2;
    const int t    = lane & 3;

    const int wq0 = qt * 128 + warp * 32;   // warp's first query row
    const size_t base = ((size_t)b * SEQ_LEN) * D_MODEL + h * D_HEAD;
    const uint32_t* tile_base = KVP + (size_t)bh * NT64 * STAGE_WORDS;
    const uint32_t sm_addr = (uint32_t)__cvta_generic_to_shared(sm);
    const int nkt = 2 * qt + 2;

    uint32_t qh[2][8][4];
    #pragma unroll
    for (int mi = 0; mi < 2; mi++) {
        const int row0 = wq0 + mi * 16 + g, row1 = row0 + 8;
        #pragma unroll
        for (int kd = 0; kd < 8; kd++) {
            int c0 = kd * 8 + t, c1 = c0 + 4;
            qh[mi][kd][0] = f2tf32(Q[base + (size_t)row0 * D_MODEL + c0] * 0.125f);
            qh[mi][kd][1] = f2tf32(Q[base + (size_t)row1 * D_MODEL + c0] * 0.125f);
            qh[mi][kd][2] = f2tf32(Q[base + (size_t)row0 * D_MODEL + c1] * 0.125f);
            qh[mi][kd][3] = f2tf32(Q[base + (size_t)row1 * D_MODEL + c1] * 0.125f);
        }
    }

    float oc[2][8][4];
    #pragma unroll
    for (int mi = 0; mi < 2; mi++)
        #pragma unroll
        for (int nv = 0; nv < 8; nv++)
            #pragma unroll
            for (int r = 0; r < 4; r++) oc[mi][nv][r] = 0.0f;

    float mm[2][2], ll[2][2];
    #pragma unroll
    for (int mi = 0; mi < 2; mi++) {
        mm[mi][0] = -1.0e30f; mm[mi][1] = -1.0e30f;
        ll[mi][0] = 0.0f;     ll[mi][1] = 0.0f;
    }

    // 32KB linear copy per tile: 16 x (128 threads x 16B).
    auto issue_tile = [&](int kt) {
        if (kt < nkt) {
            const uint32_t* src = tile_base + (size_t)kt * STAGE_WORDS + tid * 4;
            uint32_t dst = sm_addr + ((kt % 3) * STAGE_WORDS + tid * 4) * 4;
            #pragma unroll
            for (int c = 0; c < 16; c++) {
                asm volatile("cp.async.cg.shared.global [%0], [%1], 16;\n"
                             :: "r"(dst + c * 2048), "l"(src + c * 512));
            }
        }
        asm volatile("cp.async.commit_group;\n");
    };

    issue_tile(0);
    issue_tile(1);

    const int src0 = (lane & ~3) | (t >> 1);
    const int src1 = src0 + 2;
    const bool odd = (t & 1);

    for (int kt = 0; kt < nkt; kt++) {
        asm volatile("cp.async.wait_group 1;\n");
        __syncthreads();

        const uint2* KhiS = reinterpret_cast<const uint2*>(sm + (kt % 3) * STAGE_WORDS);
        const uint2* VhiS = KhiS + 2048;
        const int k0 = kt * 64;

        if (k0 <= wq0 + 31) {
            // ---- S = QK^T: one K LDS feeds both m-tiles ----
            float sc[2][8][4];
            #pragma unroll
            for (int mi = 0; mi < 2; mi++)
                #pragma unroll
                for (int nt = 0; nt < 8; nt++)
                    #pragma unroll
                    for (int r = 0; r < 4; r++) sc[mi][nt][r] = 0.0f;

            #pragma unroll
            for (int kd = 0; kd < 8; kd++) {
                #pragma unroll
                for (int nt = 0; nt < 8; nt++) {
                    uint2 bh2 = KhiS[(kd * 8 + nt) * 32 + lane];
                    mma_tf32(sc[0][nt], qh[0][kd], bh2.x, bh2.y);
                    mma_tf32(sc[1][nt], qh[1][kd], bh2.x, bh2.y);
                }
            }

            // ---- causal mask ----
            if (k0 + 63 > wq0) {
                #pragma unroll
                for (int mi = 0; mi < 2; mi++) {
                    const int row0 = wq0 + mi * 16 + g, row1 = row0 + 8;
                    #pragma unroll
                    for (int nt = 0; nt < 8; nt++) {
                        int col = k0 + nt * 8 + 2 * t;
                        if (col     > row0) sc[mi][nt][0] = -1.0e30f;
                        if (col + 1 > row0) sc[mi][nt][1] = -1.0e30f;
                        if (col     > row1) sc[mi][nt][2] = -1.0e30f;
                        if (col + 1 > row1) sc[mi][nt][3] = -1.0e30f;
                    }
                }
            }

            // ---- online softmax (per m-tile) ----
            #pragma unroll
            for (int mi = 0; mi < 2; mi++) {
                float mt0 = sc[mi][0][0], mt1 = sc[mi][0][2];
                #pragma unroll
                for (int nt = 0; nt < 8; nt++) {
                    mt0 = fmaxf(mt0, fmaxf(sc[mi][nt][0], sc[mi][nt][1]));
                    mt1 = fmaxf(mt1, fmaxf(sc[mi][nt][2], sc[mi][nt][3]));
                }
                #pragma unroll
                for (int w = 1; w < 4; w <<= 1) {
                    mt0 = fmaxf(mt0, __shfl_xor_sync(0xffffffff, mt0, w));
                    mt1 = fmaxf(mt1, __shfl_xor_sync(0xffffffff, mt1, w));
                }
                float mn0 = fmaxf(mm[mi][0], mt0), mn1 = fmaxf(mm[mi][1], mt1);
                float cr0 = __expf(mm[mi][0] - mn0), cr1 = __expf(mm[mi][1] - mn1);
                mm[mi][0] = mn0; mm[mi][1] = mn1;
                ll[mi][0] *= cr0; ll[mi][1] *= cr1;
                #pragma unroll
                for (int nv = 0; nv < 8; nv++) {
                    oc[mi][nv][0] *= cr0; oc[mi][nv][1] *= cr0;
                    oc[mi][nv][2] *= cr1; oc[mi][nv][3] *= cr1;
                }
            }

            // ---- per key-group: exp -> transpose -> PV (shared V LDS) ----
            #pragma unroll
            for (int nt = 0; nt < 8; nt++) {
                uint32_t ph[2][4];
                #pragma unroll
                for (int mi = 0; mi < 2; mi++) {
                    float p0 = __expf(sc[mi][nt][0] - mm[mi][0]);
                    float p1 = __expf(sc[mi][nt][1] - mm[mi][0]);
                    float p2 = __expf(sc[mi][nt][2] - mm[mi][1]);
                    float p3 = __expf(sc[mi][nt][3] - mm[mi][1]);
                    ll[mi][0] += p0 + p1;
                    ll[mi][1] += p2 + p3;

                    float t00 = __shfl_sync(0xffffffff, p0, src0);
                    float t01 = __shfl_sync(0xffffffff, p1, src0);
                    float a0f = odd ? t01 : t00;
                    float t10 = __shfl_sync(0xffffffff, p2, src0);
                    float t11 = __shfl_sync(0xffffffff, p3, src0);
                    float a1f = odd ? t11 : t10;
                    float t20 = __shfl_sync(0xffffffff, p0, src1);
                    float t21 = __shfl_sync(0xffffffff, p1, src1);
                    float a2f = odd ? t21 : t20;
                    float t30 = __shfl_sync(0xffffffff, p2, src1);
                    float t31 = __shfl_sync(0xffffffff, p3, src1);
                    float a3f = odd ? t31 : t30;

                    ph[mi][0] = f2tf32(a0f);
                    ph[mi][1] = f2tf32(a1f);
                    ph[mi][2] = f2tf32(a2f);
                    ph[mi][3] = f2tf32(a3f);
                }

                #pragma unroll
                for (int nv = 0; nv < 8; nv++) {
                    uint2 vh2 = VhiS[(nt * 8 + nv) * 32 + lane];
                    mma_tf32(oc[0][nv], ph[0], vh2.x, vh2.y);
                    mma_tf32(oc[1][nv], ph[1], vh2.x, vh2.y);
                }
            }
        }

        issue_tile(kt + 2);
    }

    // ---- finalize: normalize, transpose to A-frag order, store packed ----
    #pragma unroll
    for (int mi = 0; mi < 2; mi++) {
        #pragma unroll
        for (int w = 1; w < 4; w <<= 1) {
            ll[mi][0] += __shfl_xor_sync(0xffffffff, ll[mi][0], w);
            ll[mi][1] += __shfl_xor_sync(0xffffffff, ll[mi][1], w);
        }
    }
    const int rb = b * (SEQ_LEN / 128) + qt;
    uint32_t* ablk0 = APK + ((size_t)rb * KT_N + h * 2) * 4096;

    #pragma unroll
    for (int mi = 0; mi < 2; mi++) {
        const float inv0 = 1.0f / ll[mi][0], inv1 = 1.0f / ll[mi][1];
        const int mt = warp * 2 + mi;    // m-tile index 0..7
        #pragma unroll
        for (int nv = 0; nv < 8; nv++) {
            float p0 = oc[mi][nv][0] * inv0, p1 = oc[mi][nv][1] * inv0;
            float p2 = oc[mi][nv][2] * inv1, p3 = oc[mi][nv][3] * inv1;
            float t00 = __shfl_sync(0xffffffff, p0, src0);
            float t01 = __shfl_sync(0xffffffff, p1, src0);
            float a0 = odd ? t01 : t00;
            float t10 = __shfl_sync(0xffffffff, p2, src0);
            float t11 = __shfl_sync(0xffffffff, p3, src0);
            float a1 = odd ? t11 : t10;
            float t20 = __shfl_sync(0xffffffff, p0, src1);
            float t21 = __shfl_sync(0xffffffff, p1, src1);
            float a2 = odd ? t21 : t20;
            float t30 = __shfl_sync(0xffffffff, p2, src1);
            float t31 = __shfl_sync(0xffffffff, p3, src1);
            float a3 = odd ? t31 : t30;
            uint4 wv = make_uint4(f2tf32(a0), f2tf32(a1), f2tf32(a2), f2tf32(a3));
            uint32_t* dst = ablk0 + (size_t)(nv >> 2) * 4096
                                  + (size_t)(((nv & 3) * 8 + mt) * 32 + lane) * 4;
            *reinterpret_cast<uint4*>(dst) = wv;
        }
    }
}

// ---------------------------------------------------------------------------
// Launch: pack prepass -> fused QKV GEMM (K/V packed directly) -> attn
//         (packed O) -> output GEMM.
// ---------------------------------------------------------------------------
extern "C" void kernel_launch(void* const* d_in, const int* in_sizes, int n_in,
                              void* d_out, int out_size)
{
    const float* x  = (const float*)d_in[0];
    const float* Wq = (const float*)d_in[1];
    const float* bq = (const float*)d_in[2];
    const float* Wk = (const float*)d_in[3];
    const float* bk = (const float*)d_in[4];
    const float* Wv = (const float*)d_in[5];
    const float* bv = (const float*)d_in[6];
    const float* Wo = (const float*)d_in[7];
    const float* bo = (const float*)d_in[8];
    float* out = (float*)d_out;

    const int M = in_sizes[0] / D_MODEL;   // 4096
    const int B = M / SEQ_LEN;             // 2

    float* Qp;
    uint32_t *APKp, *WPKp, *KVPp;
    cudaGetSymbolAddress((void**)&Qp, g_Q);
    cudaGetSymbolAddress((void**)&APKp, g_APK);
    cudaGetSymbolAddress((void**)&WPKp, g_WPK);
    cudaGetSymbolAddress((void**)&KVPp, g_KVP);

    static bool attr_set = false;
    if (!attr_set) {
        cudaFuncSetAttribute(attn_mma_kernel,
                             cudaFuncAttributeMaxDynamicSharedMemorySize,
                             3 * STAGE_WORDS * 4);
        cudaFuncSetAttribute(gemm_qkv_kernel,
                             cudaFuncAttributeMaxDynamicSharedMemorySize,
                             3 * GW * 4);
        cudaFuncSetAttribute(gemm_out_kernel,
                             cudaFuncAttributeMaxDynamicSharedMemorySize,
                             3 * GW * 4);
        attr_set = true;
    }

    const int gemm_smem = 3 * GW * 4;             // 98304 B
    dim3 qkv_grid(8, M / 128, 3);                 // (8, 32, 3)
    dim3 gemm_grid(8, M / 128);                   // (8, 32)
    dim3 pa_grid(KT_N, M / 128);                  // (32, 32)
    dim3 pw_grid(KT_N, 8, 4);                     // (32, 8, 4)

    // Pre-pass: fragment-pack A (x) and all 4 weight matrices.
    pack_a_kernel<<<pa_grid, 256>>>(x, APKp);
    pack_w_kernel<<<pw_grid, 256>>>(Wq, Wk, Wv, Wo, WPKp);

    // Fused QKV projections; K and V written directly in packed KV layout.
    gemm_qkv_kernel<<<qkv_grid, 256, gemm_smem>>>(APKp, WPKp, bq, bk, bv, Qp, KVPp);

    // Attention: 128 threads, warp = 32 queries (2 m-tiles).
    dim3 attn_grid(SEQ_LEN / 128, B * NUM_HEADS); // (16, 32)
    attn_mma_kernel<<<attn_grid, 128, 3 * STAGE_WORDS * 4>>>(Qp, KVPp, APKp);

    // Output projection.
    gemm_out_kernel<<<gemm_grid, 256, gemm_smem>>>(APKp, WPKp + 3 * WSTRIDE, bo, out);
}